// round 5
// baseline (speedup 1.0000x reference)
#include <cuda_runtime.h>
#include <cuda_bf16.h>
#include <cstdint>
#include <math.h>

// ---------------- problem constants ----------------
#define KBATCH 8
#define KSEQ   2048
#define KDIM   512
#define KROWS  (KBATCH*KSEQ)   // 16384

// ---------------- scratch (device globals; no allocations) ----------------
__device__ __nv_bfloat16  g_inh[3][(size_t)KROWS * KDIM];   // split Q,K,V inputs (hi)
__device__ __nv_bfloat16  g_inl[3][(size_t)KROWS * KDIM];   // (lo)
__device__ __nv_bfloat16  g_wh [3][(size_t)KDIM * KDIM];    // W^T hi  [e][d] = [N,K]
__device__ __nv_bfloat16  g_wl [3][(size_t)KDIM * KDIM];
__device__ __nv_bfloat16  g_qh [(size_t)KROWS * KDIM];      // q_s split [M,K]
__device__ __nv_bfloat16  g_ql [(size_t)KROWS * KDIM];
__device__ __nv_bfloat16  g_ksh[(size_t)KROWS * KDIM];      // k_s split [N,K]
__device__ __nv_bfloat16  g_ksl[(size_t)KROWS * KDIM];
__device__ float          g_v  [(size_t)KROWS * KDIM];      // v_s fp32
__device__ __nv_bfloat16  g_vth[(size_t)KBATCH * KDIM * KSEQ];  // v_s^T split [B][D][S]
__device__ __nv_bfloat16  g_vtl[(size_t)KBATCH * KDIM * KSEQ];
__device__ float          g_s  [(size_t)KBATCH * KSEQ * KSEQ];  // scores f32
__device__ __nv_bfloat16  g_ph [(size_t)KBATCH * KSEQ * KSEQ];  // probs split
__device__ __nv_bfloat16  g_pl [(size_t)KBATCH * KSEQ * KSEQ];

// ---------------- helpers ----------------
__device__ __forceinline__ uint32_t smem_u32(const void* p) {
    uint32_t a;
    asm("{ .reg .u64 t; cvta.to.shared.u64 t, %1; cvt.u32.u64 %0, t; }" : "=r"(a) : "l"(p));
    return a;
}
__device__ __forceinline__ void split_f32(float x, __nv_bfloat16& h, __nv_bfloat16& l) {
    h = __float2bfloat16(x);
    l = __float2bfloat16(x - __bfloat162float(h));
}
__device__ __forceinline__ uint32_t pack2(__nv_bfloat16 a, __nv_bfloat16 b) {
    return (uint32_t)__bfloat16_as_ushort(a) | ((uint32_t)__bfloat16_as_ushort(b) << 16);
}
__device__ __forceinline__ void ldmx4(uint32_t& r0, uint32_t& r1, uint32_t& r2, uint32_t& r3,
                                      uint32_t addr) {
    asm volatile("ldmatrix.sync.aligned.m8n8.x4.shared.b16 {%0,%1,%2,%3}, [%4];"
                 : "=r"(r0), "=r"(r1), "=r"(r2), "=r"(r3) : "r"(addr));
}
__device__ __forceinline__ void mma_bf16(float* c, const uint32_t* a, uint32_t b0, uint32_t b1) {
    asm volatile("mma.sync.aligned.m16n8k16.row.col.f32.bf16.bf16.f32 "
                 "{%0,%1,%2,%3}, {%4,%5,%6,%7}, {%8,%9}, {%0,%1,%2,%3};"
                 : "+f"(c[0]), "+f"(c[1]), "+f"(c[2]), "+f"(c[3])
                 : "r"(a[0]), "r"(a[1]), "r"(a[2]), "r"(a[3]), "r"(b0), "r"(b1));
}
#define CP16(dst, src) \
    asm volatile("cp.async.cg.shared.global [%0], [%1], 16;" :: "r"(dst), "l"(src))
#define CP_COMMIT() asm volatile("cp.async.commit_group;" ::: "memory")
#define CP_WAIT(n)  asm volatile("cp.async.wait_group %0;" :: "n"(n) : "memory")

__device__ __forceinline__ float ssc() { return 0.044194173824159216f; } // 1/sqrt(512)

// ---------------- HMMA GEMM (all-bf16 operands, 4-stage cp.async) ----------------
// C[M,N] = (Ah+Al)[M,K] * (Bh+Bl)^T[N,K]  (3-term split product)
// EPI 0: +bias -> f32    EPI 1: *scale + mask -> f32
// EPI 2: plain -> f32    EPI 3: +bias -> split bf16 (Ch, Cl)
#define TILE_M 128
#define TILE_N 128
#define TILE_K 32
#define GT 256
#define STAGES 4
#define PSTR 40                      // padded smem row stride (bf16)
#define TILE_BYTES (128 * PSTR * 2)  // 10240
#define ST_BYTES (4 * TILE_BYTES)    // per-stage: Ah Al Bh Bl
#define OFF_AH(s) ((s) * ST_BYTES)
#define OFF_AL(s) ((s) * ST_BYTES + TILE_BYTES)
#define OFF_BH(s) ((s) * ST_BYTES + 2 * TILE_BYTES)
#define OFF_BL(s) ((s) * ST_BYTES + 3 * TILE_BYTES)
#define SMEM_BYTES (STAGES * ST_BYTES)  // 163840

template<int EPI>
__global__ __launch_bounds__(GT, 1)
void gemm_hmma(const __nv_bfloat16* __restrict__ Ah,
               const __nv_bfloat16* __restrict__ Al,
               const __nv_bfloat16* __restrict__ Bh,
               const __nv_bfloat16* __restrict__ Bl,
               const float* __restrict__ aux,
               float* __restrict__ C,
               __nv_bfloat16* __restrict__ Ch,
               __nv_bfloat16* __restrict__ Cl,
               int N, int K,
               size_t sA, size_t sB, size_t sC, size_t sAux)
{
    extern __shared__ char sm[];
    const uint32_t sb = smem_u32(sm);

    Ah  += sA   * (size_t)blockIdx.z;
    Al  += sA   * (size_t)blockIdx.z;
    Bh  += sB   * (size_t)blockIdx.z;
    Bl  += sB   * (size_t)blockIdx.z;
    C   += sC   * (size_t)blockIdx.z;
    Ch  += sC   * (size_t)blockIdx.z;
    Cl  += sC   * (size_t)blockIdx.z;
    aux += sAux * (size_t)blockIdx.z;

    const int t    = threadIdx.x;
    const int lane = t & 31;
    const int w    = t >> 5;
    const int wm   = w & 3;         // warp row (4)
    const int wn   = w >> 2;        // warp col (2)
    const int bm   = blockIdx.y * TILE_M;
    const int bn   = blockIdx.x * TILE_N;

    // cp.async mapping: thread -> (row pair, 16B column)
    const int cr = t >> 2;          // 0..63 (rows, 2 passes +64)
    const int cc = t & 3;           // 16B chunk within 64B (32 bf16) row

    // ldmatrix address components
    const int a_r  = wm * 32 + (lane & 15);
    const int a_c8 = (lane >> 4) * 8;
    const int b_r  = wn * 64 + (lane & 7) + ((lane >> 4) & 1) * 8;
    const int b_c8 = ((lane >> 3) & 1) * 8;

    float acc[2][8][4];
    #pragma unroll
    for (int i = 0; i < 2; ++i)
        #pragma unroll
        for (int j = 0; j < 8; ++j)
            #pragma unroll
            for (int e = 0; e < 4; ++e) acc[i][j][e] = 0.0f;

    const int nch = K / TILE_K;

#define ISSUE(j, s) do {                                                        \
        const size_t kco = (size_t)(j) * TILE_K + cc * 8;                       \
        _Pragma("unroll")                                                       \
        for (int p = 0; p < 2; ++p) {                                           \
            const int row = cr + p * 64;                                        \
            const uint32_t doff = (uint32_t)(row * (PSTR * 2) + cc * 16);       \
            const size_t ga = (size_t)(bm + row) * K + kco;                     \
            const size_t gb = (size_t)(bn + row) * K + kco;                     \
            CP16(sb + OFF_AH(s) + doff, Ah + ga);                               \
            CP16(sb + OFF_AL(s) + doff, Al + ga);                               \
            CP16(sb + OFF_BH(s) + doff, Bh + gb);                               \
            CP16(sb + OFF_BL(s) + doff, Bl + gb);                               \
        }                                                                       \
    } while (0)

    // prologue: stages 0..STAGES-2
    #pragma unroll
    for (int j = 0; j < STAGES - 1; ++j) {
        if (j < nch) ISSUE(j, j);
        CP_COMMIT();
    }

    for (int i = 0; i < nch; ++i) {
        const int jn = i + STAGES - 1;
        if (jn < nch) ISSUE(jn, jn % STAGES);
        CP_COMMIT();
        CP_WAIT(STAGES - 2);
        __syncthreads();

        const int s = i % STAGES;
        #pragma unroll
        for (int h = 0; h < 2; ++h) {
            // ---- load ALL fragments for this k16 half first ----
            const uint32_t acol = (uint32_t)((h * 16 + a_c8) * 2);
            uint32_t ahr[2][4], alr[2][4];
            #pragma unroll
            for (int mt = 0; mt < 2; ++mt) {
                const uint32_t aoff = (uint32_t)((a_r + mt * 16) * (PSTR * 2)) + acol;
                ldmx4(ahr[mt][0], ahr[mt][1], ahr[mt][2], ahr[mt][3], sb + OFF_AH(s) + aoff);
                ldmx4(alr[mt][0], alr[mt][1], alr[mt][2], alr[mt][3], sb + OFF_AL(s) + aoff);
            }
            const uint32_t bcol = (uint32_t)((h * 16 + b_c8) * 2);
            uint32_t bh[4][4], bl[4][4];
            #pragma unroll
            for (int np = 0; np < 4; ++np) {
                const uint32_t boff = (uint32_t)((b_r + np * 16) * (PSTR * 2)) + bcol;
                ldmx4(bh[np][0], bh[np][1], bh[np][2], bh[np][3], sb + OFF_BH(s) + boff);
                ldmx4(bl[np][0], bl[np][1], bl[np][2], bl[np][3], sb + OFF_BL(s) + boff);
            }
            // ---- term passes: each acc written once per pass ----
            // pass 1: Ah * Bh
            #pragma unroll
            for (int np = 0; np < 4; ++np)
                #pragma unroll
                for (int mt = 0; mt < 2; ++mt) {
                    mma_bf16(acc[mt][2*np],   ahr[mt], bh[np][0], bh[np][1]);
                    mma_bf16(acc[mt][2*np+1], ahr[mt], bh[np][2], bh[np][3]);
                }
            // pass 2: Ah * Bl
            #pragma unroll
            for (int np = 0; np < 4; ++np)
                #pragma unroll
                for (int mt = 0; mt < 2; ++mt) {
                    mma_bf16(acc[mt][2*np],   ahr[mt], bl[np][0], bl[np][1]);
                    mma_bf16(acc[mt][2*np+1], ahr[mt], bl[np][2], bl[np][3]);
                }
            // pass 3: Al * Bh
            #pragma unroll
            for (int np = 0; np < 4; ++np)
                #pragma unroll
                for (int mt = 0; mt < 2; ++mt) {
                    mma_bf16(acc[mt][2*np],   alr[mt], bh[np][0], bh[np][1]);
                    mma_bf16(acc[mt][2*np+1], alr[mt], bh[np][2], bh[np][3]);
                }
        }
        __syncthreads();
    }
#undef ISSUE

    // ---------------- epilogue ----------------
    const int er = (lane >> 2);
    const int ec = (lane & 3) * 2;
    #pragma unroll
    for (int mt = 0; mt < 2; ++mt) {
        #pragma unroll
        for (int nt = 0; nt < 8; ++nt) {
            const int col = bn + wn * 64 + nt * 8 + ec;
            #pragma unroll
            for (int half = 0; half < 2; ++half) {
                const int row = bm + wm * 32 + mt * 16 + er + half * 8;
                float x0 = acc[mt][nt][2*half + 0];
                float x1 = acc[mt][nt][2*half + 1];
                if (EPI == 0 || EPI == 3) {
                    x0 += aux[col];
                    x1 += aux[col + 1];
                }
                if (EPI == 1) {
                    const float2 m2 = *reinterpret_cast<const float2*>(&aux[(size_t)row * N + col]);
                    x0 = fmaf(x0, ssc(), m2.x);
                    x1 = fmaf(x1, ssc(), m2.y);
                }
                if (EPI == 3) {
                    __nv_bfloat16 h0,h1,l0,l1;
                    split_f32(x0, h0, l0);
                    split_f32(x1, h1, l1);
                    const size_t o = (size_t)row * N + col;
                    *reinterpret_cast<uint32_t*>(&Ch[o]) = pack2(h0, h1);
                    *reinterpret_cast<uint32_t*>(&Cl[o]) = pack2(l0, l1);
                } else {
                    *reinterpret_cast<float2*>(&C[(size_t)row * N + col]) = make_float2(x0, x1);
                }
            }
        }
    }
}

// ---------------- elementwise split: f32 -> bf16 hi/lo ----------------
__global__ __launch_bounds__(256)
void split_pass(const float* __restrict__ src,
                __nv_bfloat16* __restrict__ dh,
                __nv_bfloat16* __restrict__ dl)
{
    const size_t i = ((size_t)blockIdx.x * 256 + threadIdx.x) * 4;
    float4 v = *reinterpret_cast<const float4*>(src + i);
    __nv_bfloat16 h0,h1,h2,h3,l0,l1,l2,l3;
    split_f32(v.x, h0, l0); split_f32(v.y, h1, l1);
    split_f32(v.z, h2, l2); split_f32(v.w, h3, l3);
    *reinterpret_cast<uint2*>(dh + i) = make_uint2(pack2(h0,h1), pack2(h2,h3));
    *reinterpret_cast<uint2*>(dl + i) = make_uint2(pack2(l0,l1), pack2(l2,l3));
}

// ---------------- transpose + split: dst[c][r] = split(src[r][c]) ----------------
__global__ __launch_bounds__(256)
void transpose_split(const float* __restrict__ src,
                     __nv_bfloat16* __restrict__ dh,
                     __nv_bfloat16* __restrict__ dl,
                     int rows, int cols, size_t ss, size_t ds)
{
    __shared__ float tile[32][33];
    src += ss * (size_t)blockIdx.z;
    dh  += ds * (size_t)blockIdx.z;
    dl  += ds * (size_t)blockIdx.z;
    const int bx = blockIdx.x * 32;
    const int by = blockIdx.y * 32;
    const int tx = threadIdx.x & 31;
    const int ty = threadIdx.x >> 5;
    #pragma unroll
    for (int i = 0; i < 32; i += 8)
        tile[ty + i][tx] = src[(size_t)(by + ty + i) * cols + bx + tx];
    __syncthreads();
    #pragma unroll
    for (int i = 0; i < 32; i += 8) {
        float v = tile[tx][ty + i];
        __nv_bfloat16 h, l;
        split_f32(v, h, l);
        size_t o = (size_t)(bx + ty + i) * rows + by + tx;
        dh[o] = h; dl[o] = l;
    }
}

// ---------------- row softmax over 2048, emits split bf16 probs ----------------
__global__ __launch_bounds__(256)
void softmax_kernel(const float* __restrict__ S,
                    __nv_bfloat16* __restrict__ Ph,
                    __nv_bfloat16* __restrict__ Pl)
{
    __shared__ float buf[KSEQ];
    __shared__ float red[8];
    const float* p = S + (size_t)blockIdx.x * KSEQ;
    const int t = threadIdx.x, lane = t & 31, wid = t >> 5;

    float mx = -3.4e38f;
    #pragma unroll
    for (int i = t; i < KSEQ; i += 256) { float v = p[i]; buf[i] = v; mx = fmaxf(mx, v); }
    #pragma unroll
    for (int o = 16; o > 0; o >>= 1) mx = fmaxf(mx, __shfl_xor_sync(0xffffffffu, mx, o));
    if (lane == 0) red[wid] = mx;
    __syncthreads();
    mx = fmaxf(fmaxf(fmaxf(red[0], red[1]), fmaxf(red[2], red[3])),
               fmaxf(fmaxf(red[4], red[5]), fmaxf(red[6], red[7])));
    __syncthreads();

    float sum = 0.0f;
    #pragma unroll
    for (int i = t; i < KSEQ; i += 256) { float e = __expf(buf[i] - mx); buf[i] = e; sum += e; }
    #pragma unroll
    for (int o = 16; o > 0; o >>= 1) sum += __shfl_xor_sync(0xffffffffu, sum, o);
    if (lane == 0) red[wid] = sum;
    __syncthreads();
    sum = ((red[0] + red[1]) + (red[2] + red[3])) + ((red[4] + red[5]) + (red[6] + red[7]));
    const float inv = 1.0f / sum;

    __nv_bfloat16* ph = Ph + (size_t)blockIdx.x * KSEQ;
    __nv_bfloat16* pl = Pl + (size_t)blockIdx.x * KSEQ;
    #pragma unroll
    for (int j = t; j < KSEQ / 2; j += 256) {
        float e0 = buf[2*j]     * inv;
        float e1 = buf[2*j + 1] * inv;
        __nv_bfloat16 h0, h1, l0, l1;
        split_f32(e0, h0, l0);
        split_f32(e1, h1, l1);
        *reinterpret_cast<uint32_t*>(ph + 2*j) = pack2(h0, h1);
        *reinterpret_cast<uint32_t*>(pl + 2*j) = pack2(l0, l1);
    }
}

// ---------------- launch ----------------
extern "C" void kernel_launch(void* const* d_in, const int* in_sizes, int n_in,
                              void* d_out, int out_size)
{
    (void)in_sizes; (void)n_in; (void)out_size;
    const float* Qin  = (const float*)d_in[0];
    const float* Kin  = (const float*)d_in[1];
    const float* Vin  = (const float*)d_in[2];
    const float* mask = (const float*)d_in[3];
    const float* Wq   = (const float*)d_in[4];
    const float* bq   = (const float*)d_in[5];
    const float* Wk   = (const float*)d_in[6];
    const float* bk   = (const float*)d_in[7];
    const float* Wv   = (const float*)d_in[8];
    const float* bv   = (const float*)d_in[9];
    float* out = (float*)d_out;

    float *v, *s;
    __nv_bfloat16 *inh, *inl, *wh, *wl, *qh, *ql, *ksh, *ksl, *vth, *vtl, *ph, *pl;
    cudaGetSymbolAddress((void**)&inh, g_inh);
    cudaGetSymbolAddress((void**)&inl, g_inl);
    cudaGetSymbolAddress((void**)&wh,  g_wh);
    cudaGetSymbolAddress((void**)&wl,  g_wl);
    cudaGetSymbolAddress((void**)&qh,  g_qh);
    cudaGetSymbolAddress((void**)&ql,  g_ql);
    cudaGetSymbolAddress((void**)&ksh, g_ksh);
    cudaGetSymbolAddress((void**)&ksl, g_ksl);
    cudaGetSymbolAddress((void**)&v,   g_v);
    cudaGetSymbolAddress((void**)&vth, g_vth);
    cudaGetSymbolAddress((void**)&vtl, g_vtl);
    cudaGetSymbolAddress((void**)&s,   g_s);
    cudaGetSymbolAddress((void**)&ph,  g_ph);
    cudaGetSymbolAddress((void**)&pl,  g_pl);

    cudaFuncSetAttribute(gemm_hmma<0>, cudaFuncAttributeMaxDynamicSharedMemorySize, SMEM_BYTES);
    cudaFuncSetAttribute(gemm_hmma<1>, cudaFuncAttributeMaxDynamicSharedMemorySize, SMEM_BYTES);
    cudaFuncSetAttribute(gemm_hmma<2>, cudaFuncAttributeMaxDynamicSharedMemorySize, SMEM_BYTES);
    cudaFuncSetAttribute(gemm_hmma<3>, cudaFuncAttributeMaxDynamicSharedMemorySize, SMEM_BYTES);

    const size_t WSZ = (size_t)KDIM * KDIM;
    const size_t ISZ = (size_t)KROWS * KDIM;
    dim3 tb(256);

    // 1) split inputs + transpose/split weights
    const int sgrid = (int)(ISZ / 4 / 256);
    split_pass<<<sgrid, tb>>>(Qin, inh + 0*ISZ, inl + 0*ISZ);
    split_pass<<<sgrid, tb>>>(Kin, inh + 1*ISZ, inl + 1*ISZ);
    split_pass<<<sgrid, tb>>>(Vin, inh + 2*ISZ, inl + 2*ISZ);
    transpose_split<<<dim3(16, 16, 1), tb>>>(Wq, wh + 0*WSZ, wl + 0*WSZ, KDIM, KDIM, 0, 0);
    transpose_split<<<dim3(16, 16, 1), tb>>>(Wk, wh + 1*WSZ, wl + 1*WSZ, KDIM, KDIM, 0, 0);
    transpose_split<<<dim3(16, 16, 1), tb>>>(Wv, wh + 2*WSZ, wl + 2*WSZ, KDIM, KDIM, 0, 0);

    // 2) projections (M=16384, N=512, K=512)
    dim3 gp(KDIM / TILE_N, KROWS / TILE_M, 1);
    gemm_hmma<3><<<gp, GT, SMEM_BYTES>>>(inh + 0*ISZ, inl + 0*ISZ, wh + 0*WSZ, wl + 0*WSZ,
                                         bq, nullptr, qh, ql, KDIM, KDIM, 0, 0, 0, 0);
    gemm_hmma<3><<<gp, GT, SMEM_BYTES>>>(inh + 1*ISZ, inl + 1*ISZ, wh + 1*WSZ, wl + 1*WSZ,
                                         bk, nullptr, ksh, ksl, KDIM, KDIM, 0, 0, 0, 0);
    gemm_hmma<0><<<gp, GT, SMEM_BYTES>>>(inh + 2*ISZ, inl + 2*ISZ, wh + 2*WSZ, wl + 2*WSZ,
                                         bv, v, nullptr, nullptr, KDIM, KDIM, 0, 0, 0, 0);

    // 3) v_s -> v_s^T split  [B][D][S]
    transpose_split<<<dim3(KDIM / 32, KSEQ / 32, KBATCH), tb>>>(
        v, vth, vtl, KSEQ, KDIM, (size_t)KSEQ * KDIM, (size_t)KDIM * KSEQ);

    // 4) scores = q_s k_s^T * scale + mask  (per batch 2048x2048, K=512)
    dim3 gs(KSEQ / TILE_N, KSEQ / TILE_M, KBATCH);
    gemm_hmma<1><<<gs, GT, SMEM_BYTES>>>(qh, ql, ksh, ksl, mask, s, nullptr, nullptr,
                                         KSEQ, KDIM,
                                         (size_t)KSEQ * KDIM, (size_t)KSEQ * KDIM,
                                         (size_t)KSEQ * KSEQ, (size_t)KSEQ * KSEQ);

    // 5) softmax -> split bf16 probs
    softmax_kernel<<<KROWS, 256>>>(s, ph, pl);

    // 6) out = probs @ v_s  (per batch 2048x512, K=2048)
    dim3 ga(KDIM / TILE_N, KSEQ / TILE_M, KBATCH);
    gemm_hmma<2><<<ga, GT, SMEM_BYTES>>>(ph, pl, vth, vtl, nullptr, out, nullptr, nullptr,
                                         KDIM, KSEQ,
                                         (size_t)KSEQ * KSEQ, (size_t)KDIM * KSEQ,
                                         (size_t)KSEQ * KDIM, 0);
}

// round 6
// speedup vs baseline: 1.0928x; 1.0928x over previous
#include <cuda_runtime.h>
#include <cuda_bf16.h>
#include <cstdint>
#include <math.h>

// ---------------- problem constants ----------------
#define KBATCH 8
#define KSEQ   2048
#define KDIM   512
#define KROWS  (KBATCH*KSEQ)   // 16384

// ---------------- scratch (device globals; no allocations) ----------------
__device__ __nv_bfloat16  g_inh[3][(size_t)KROWS * KDIM];   // split Q,K,V inputs (hi)
__device__ __nv_bfloat16  g_inl[3][(size_t)KROWS * KDIM];   // (lo)
__device__ __nv_bfloat16  g_wh [3][(size_t)KDIM * KDIM];    // W^T hi  [e][d] = [N,K]
__device__ __nv_bfloat16  g_wl [3][(size_t)KDIM * KDIM];
__device__ __nv_bfloat16  g_qh [(size_t)KROWS * KDIM];      // q_s split [M,K]
__device__ __nv_bfloat16  g_ql [(size_t)KROWS * KDIM];
__device__ __nv_bfloat16  g_ksh[(size_t)KROWS * KDIM];      // k_s split [N,K]
__device__ __nv_bfloat16  g_ksl[(size_t)KROWS * KDIM];
__device__ float          g_v  [(size_t)KROWS * KDIM];      // v_s fp32
__device__ __nv_bfloat16  g_vth[(size_t)KBATCH * KDIM * KSEQ];  // v_s^T split [B][D][S]
__device__ __nv_bfloat16  g_vtl[(size_t)KBATCH * KDIM * KSEQ];
__device__ float          g_s  [(size_t)KBATCH * KSEQ * KSEQ];  // scores f32
__device__ __nv_bfloat16  g_ph [(size_t)KBATCH * KSEQ * KSEQ];  // probs split
__device__ __nv_bfloat16  g_pl [(size_t)KBATCH * KSEQ * KSEQ];

// ---------------- helpers ----------------
__device__ __forceinline__ uint32_t smem_u32(const void* p) {
    uint32_t a;
    asm("{ .reg .u64 t; cvta.to.shared.u64 t, %1; cvt.u32.u64 %0, t; }" : "=r"(a) : "l"(p));
    return a;
}
__device__ __forceinline__ void split_f32(float x, __nv_bfloat16& h, __nv_bfloat16& l) {
    h = __float2bfloat16(x);
    l = __float2bfloat16(x - __bfloat162float(h));
}
__device__ __forceinline__ uint32_t pack2(__nv_bfloat16 a, __nv_bfloat16 b) {
    return (uint32_t)__bfloat16_as_ushort(a) | ((uint32_t)__bfloat16_as_ushort(b) << 16);
}
__device__ __forceinline__ void ldmx4(uint32_t& r0, uint32_t& r1, uint32_t& r2, uint32_t& r3,
                                      uint32_t addr) {
    asm volatile("ldmatrix.sync.aligned.m8n8.x4.shared.b16 {%0,%1,%2,%3}, [%4];"
                 : "=r"(r0), "=r"(r1), "=r"(r2), "=r"(r3) : "r"(addr));
}
__device__ __forceinline__ void mma_bf16(float* c, const uint32_t* a, uint32_t b0, uint32_t b1) {
    asm volatile("mma.sync.aligned.m16n8k16.row.col.f32.bf16.bf16.f32 "
                 "{%0,%1,%2,%3}, {%4,%5,%6,%7}, {%8,%9}, {%0,%1,%2,%3};"
                 : "+f"(c[0]), "+f"(c[1]), "+f"(c[2]), "+f"(c[3])
                 : "r"(a[0]), "r"(a[1]), "r"(a[2]), "r"(a[3]), "r"(b0), "r"(b1));
}
#define CP16(dst, src) \
    asm volatile("cp.async.cg.shared.global [%0], [%1], 16;" :: "r"(dst), "l"(src))
#define CP_COMMIT() asm volatile("cp.async.commit_group;" ::: "memory")
#define CP_WAIT(n)  asm volatile("cp.async.wait_group %0;" :: "n"(n) : "memory")

__device__ __forceinline__ float ssc() { return 0.044194173824159216f; } // 1/sqrt(512)

// ---------------- HMMA GEMM: 512 threads, CTA 128x256, warp tile 32x32 ----------------
// C[M,N] = (Ah+Al)[M,K] * (Bh+Bl)^T[N,K]  (3-term split)
// EPI 0: +bias -> f32    EPI 1: *scale + mask -> f32
// EPI 2: plain -> f32    EPI 3: +bias -> split bf16 (Ch, Cl)
#define TILE_M 128
#define TILE_N 256
#define TILE_K 32
#define GT 512
#define STAGES 3
#define PSTR 40                        // padded smem row stride (bf16) -> 80 B/row
#define A_TILE_B (128 * PSTR * 2)      // 10240
#define B_TILE_B (256 * PSTR * 2)      // 20480
#define ST_BYTES (2 * A_TILE_B + 2 * B_TILE_B)   // 61440: Ah Al Bh Bl
#define OFF_AH(s) ((s) * ST_BYTES)
#define OFF_AL(s) ((s) * ST_BYTES + A_TILE_B)
#define OFF_BH(s) ((s) * ST_BYTES + 2 * A_TILE_B)
#define OFF_BL(s) ((s) * ST_BYTES + 2 * A_TILE_B + B_TILE_B)
#define SMEM_BYTES (STAGES * ST_BYTES)  // 184320

template<int EPI>
__global__ __launch_bounds__(GT, 1)
void gemm_hmma(const __nv_bfloat16* __restrict__ Ah,
               const __nv_bfloat16* __restrict__ Al,
               const __nv_bfloat16* __restrict__ Bh,
               const __nv_bfloat16* __restrict__ Bl,
               const float* __restrict__ aux,
               float* __restrict__ C,
               __nv_bfloat16* __restrict__ Ch,
               __nv_bfloat16* __restrict__ Cl,
               int N, int K,
               size_t sA, size_t sB, size_t sC, size_t sAux)
{
    extern __shared__ char sm[];
    const uint32_t sb = smem_u32(sm);

    Ah  += sA   * (size_t)blockIdx.z;
    Al  += sA   * (size_t)blockIdx.z;
    Bh  += sB   * (size_t)blockIdx.z;
    Bl  += sB   * (size_t)blockIdx.z;
    C   += sC   * (size_t)blockIdx.z;
    Ch  += sC   * (size_t)blockIdx.z;
    Cl  += sC   * (size_t)blockIdx.z;
    aux += sAux * (size_t)blockIdx.z;

    const int t    = threadIdx.x;
    const int lane = t & 31;
    const int w    = t >> 5;        // 0..15
    const int wm   = w & 3;         // warp row (4)  -> M offset 32*wm
    const int wn   = w >> 2;        // warp col (4)  -> N offset 64... no: 32*wn? (4 warps over 256 -> 64 each)
    // NOTE: 16 warps as 4x4; warp tile 32 (M) x 64 (N)? -> regs too high.
    // We use warp tile 32x64 here? No: 4 warps across N=256 -> 64 cols each.
    // To keep acc small we split the 64 cols into 2 independent 32-col groups
    // handled in the same warp via nt loop of 8 n8-tiles (acc[2][8][4] = 64 regs)
    // would blow regs at 512 thr. Instead: true warp tile 32x64 with acc[2][8][4]
    // = 64 regs is the R5 shape; at 512 threads that's 64+~60 > 128.
    // => warp grid 4(M) x 4(N), warp tile 32x64 is forced by N=256/4.
    // We keep acc[2][8][4] but drop separate A lo/hi register staging to fit.
    const int bm   = blockIdx.y * TILE_M;
    const int bn   = blockIdx.x * TILE_N;

    // cp.async mapping: 512 threads, per stage:
    // A: 128 rows x 4 x 16B (hi,lo)  -> 1 chunk each
    // B: 256 rows x 4 x 16B (hi,lo)  -> 2 chunks each
    const int cr = t >> 2;          // 0..127
    const int cc = t & 3;           // 16B chunk within 64B row

    // ldmatrix address components (warp tile 32 x 64)
    const int a_r  = wm * 32 + (lane & 15);
    const int a_c8 = (lane >> 4) * 8;
    const int b_r  = wn * 64 + (lane & 7) + ((lane >> 4) & 1) * 8;
    const int b_c8 = ((lane >> 3) & 1) * 8;

    float acc[2][8][4];
    #pragma unroll
    for (int i = 0; i < 2; ++i)
        #pragma unroll
        for (int j = 0; j < 8; ++j)
            #pragma unroll
            for (int e = 0; e < 4; ++e) acc[i][j][e] = 0.0f;

    const int nch = K / TILE_K;

#define ISSUE(j, s) do {                                                        \
        const size_t kco = (size_t)(j) * TILE_K + cc * 8;                       \
        {   /* A: one row-chunk (hi, lo) */                                     \
            const uint32_t doff = (uint32_t)(cr * (PSTR * 2) + cc * 16);        \
            const size_t ga = (size_t)(bm + cr) * K + kco;                      \
            CP16(sb + OFF_AH(s) + doff, Ah + ga);                               \
            CP16(sb + OFF_AL(s) + doff, Al + ga);                               \
        }                                                                       \
        _Pragma("unroll")                                                       \
        for (int p = 0; p < 2; ++p) {   /* B: two row-chunks (hi, lo) */        \
            const int row = cr + p * 128;                                       \
            const uint32_t doff = (uint32_t)(row * (PSTR * 2) + cc * 16);       \
            const size_t gb = (size_t)(bn + row) * K + kco;                     \
            CP16(sb + OFF_BH(s) + doff, Bh + gb);                               \
            CP16(sb + OFF_BL(s) + doff, Bl + gb);                               \
        }                                                                       \
    } while (0)

    // prologue: stages 0..STAGES-2
    #pragma unroll
    for (int j = 0; j < STAGES - 1; ++j) {
        if (j < nch) ISSUE(j, j);
        CP_COMMIT();
    }

    for (int i = 0; i < nch; ++i) {
        const int jn = i + STAGES - 1;
        if (jn < nch) ISSUE(jn, jn % STAGES);
        CP_COMMIT();
        CP_WAIT(STAGES - 2);
        __syncthreads();

        const int s = i % STAGES;
        #pragma unroll
        for (int h = 0; h < 2; ++h) {
            const uint32_t acol = (uint32_t)((h * 16 + a_c8) * 2);
            uint32_t ahr[2][4], alr[2][4];
            #pragma unroll
            for (int mt = 0; mt < 2; ++mt) {
                const uint32_t aoff = (uint32_t)((a_r + mt * 16) * (PSTR * 2)) + acol;
                ldmx4(ahr[mt][0], ahr[mt][1], ahr[mt][2], ahr[mt][3], sb + OFF_AH(s) + aoff);
                ldmx4(alr[mt][0], alr[mt][1], alr[mt][2], alr[mt][3], sb + OFF_AL(s) + aoff);
            }
            const uint32_t bcol = (uint32_t)((h * 16 + b_c8) * 2);
            #pragma unroll
            for (int np = 0; np < 4; ++np) {
                const uint32_t boff = (uint32_t)((b_r + np * 16) * (PSTR * 2)) + bcol;
                uint32_t bh0, bh1, bh2, bh3, bl0, bl1, bl2, bl3;
                ldmx4(bh0, bh1, bh2, bh3, sb + OFF_BH(s) + boff);
                ldmx4(bl0, bl1, bl2, bl3, sb + OFF_BL(s) + boff);
                #pragma unroll
                for (int mt = 0; mt < 2; ++mt) {
                    mma_bf16(acc[mt][2*np],   ahr[mt], bh0, bh1);
                    mma_bf16(acc[mt][2*np+1], ahr[mt], bh2, bh3);
                    mma_bf16(acc[mt][2*np],   ahr[mt], bl0, bl1);
                    mma_bf16(acc[mt][2*np+1], ahr[mt], bl2, bl3);
                    mma_bf16(acc[mt][2*np],   alr[mt], bh0, bh1);
                    mma_bf16(acc[mt][2*np+1], alr[mt], bh2, bh3);
                }
            }
        }
        __syncthreads();
    }
#undef ISSUE

    // ---------------- epilogue ----------------
    const int er = (lane >> 2);
    const int ec = (lane & 3) * 2;
    #pragma unroll
    for (int mt = 0; mt < 2; ++mt) {
        #pragma unroll
        for (int nt = 0; nt < 8; ++nt) {
            const int col = bn + wn * 64 + nt * 8 + ec;
            #pragma unroll
            for (int half = 0; half < 2; ++half) {
                const int row = bm + wm * 32 + mt * 16 + er + half * 8;
                float x0 = acc[mt][nt][2*half + 0];
                float x1 = acc[mt][nt][2*half + 1];
                if (EPI == 0 || EPI == 3) {
                    x0 += aux[col];
                    x1 += aux[col + 1];
                }
                if (EPI == 1) {
                    const float2 m2 = *reinterpret_cast<const float2*>(&aux[(size_t)row * N + col]);
                    x0 = fmaf(x0, ssc(), m2.x);
                    x1 = fmaf(x1, ssc(), m2.y);
                }
                if (EPI == 3) {
                    __nv_bfloat16 h0,h1,l0,l1;
                    split_f32(x0, h0, l0);
                    split_f32(x1, h1, l1);
                    const size_t o = (size_t)row * N + col;
                    *reinterpret_cast<uint32_t*>(&Ch[o]) = pack2(h0, h1);
                    *reinterpret_cast<uint32_t*>(&Cl[o]) = pack2(l0, l1);
                } else {
                    *reinterpret_cast<float2*>(&C[(size_t)row * N + col]) = make_float2(x0, x1);
                }
            }
        }
    }
}

// ---------------- elementwise split: f32 -> bf16 hi/lo ----------------
__global__ __launch_bounds__(256)
void split_pass(const float* __restrict__ src,
                __nv_bfloat16* __restrict__ dh,
                __nv_bfloat16* __restrict__ dl)
{
    const size_t i = ((size_t)blockIdx.x * 256 + threadIdx.x) * 4;
    float4 v = *reinterpret_cast<const float4*>(src + i);
    __nv_bfloat16 h0,h1,h2,h3,l0,l1,l2,l3;
    split_f32(v.x, h0, l0); split_f32(v.y, h1, l1);
    split_f32(v.z, h2, l2); split_f32(v.w, h3, l3);
    *reinterpret_cast<uint2*>(dh + i) = make_uint2(pack2(h0,h1), pack2(h2,h3));
    *reinterpret_cast<uint2*>(dl + i) = make_uint2(pack2(l0,l1), pack2(l2,l3));
}

// ---------------- transpose + split: dst[c][r] = split(src[r][c]) ----------------
__global__ __launch_bounds__(256)
void transpose_split(const float* __restrict__ src,
                     __nv_bfloat16* __restrict__ dh,
                     __nv_bfloat16* __restrict__ dl,
                     int rows, int cols, size_t ss, size_t ds)
{
    __shared__ float tile[32][33];
    src += ss * (size_t)blockIdx.z;
    dh  += ds * (size_t)blockIdx.z;
    dl  += ds * (size_t)blockIdx.z;
    const int bx = blockIdx.x * 32;
    const int by = blockIdx.y * 32;
    const int tx = threadIdx.x & 31;
    const int ty = threadIdx.x >> 5;
    #pragma unroll
    for (int i = 0; i < 32; i += 8)
        tile[ty + i][tx] = src[(size_t)(by + ty + i) * cols + bx + tx];
    __syncthreads();
    #pragma unroll
    for (int i = 0; i < 32; i += 8) {
        float v = tile[tx][ty + i];
        __nv_bfloat16 h, l;
        split_f32(v, h, l);
        size_t o = (size_t)(bx + ty + i) * rows + by + tx;
        dh[o] = h; dl[o] = l;
    }
}

// ---------------- row softmax over 2048, emits split bf16 probs ----------------
__global__ __launch_bounds__(256)
void softmax_kernel(const float* __restrict__ S,
                    __nv_bfloat16* __restrict__ Ph,
                    __nv_bfloat16* __restrict__ Pl)
{
    __shared__ float buf[KSEQ];
    __shared__ float red[8];
    const float* p = S + (size_t)blockIdx.x * KSEQ;
    const int t = threadIdx.x, lane = t & 31, wid = t >> 5;

    float mx = -3.4e38f;
    #pragma unroll
    for (int i = t; i < KSEQ; i += 256) { float v = p[i]; buf[i] = v; mx = fmaxf(mx, v); }
    #pragma unroll
    for (int o = 16; o > 0; o >>= 1) mx = fmaxf(mx, __shfl_xor_sync(0xffffffffu, mx, o));
    if (lane == 0) red[wid] = mx;
    __syncthreads();
    mx = fmaxf(fmaxf(fmaxf(red[0], red[1]), fmaxf(red[2], red[3])),
               fmaxf(fmaxf(red[4], red[5]), fmaxf(red[6], red[7])));
    __syncthreads();

    float sum = 0.0f;
    #pragma unroll
    for (int i = t; i < KSEQ; i += 256) { float e = __expf(buf[i] - mx); buf[i] = e; sum += e; }
    #pragma unroll
    for (int o = 16; o > 0; o >>= 1) sum += __shfl_xor_sync(0xffffffffu, sum, o);
    if (lane == 0) red[wid] = sum;
    __syncthreads();
    sum = ((red[0] + red[1]) + (red[2] + red[3])) + ((red[4] + red[5]) + (red[6] + red[7]));
    const float inv = 1.0f / sum;

    __nv_bfloat16* ph = Ph + (size_t)blockIdx.x * KSEQ;
    __nv_bfloat16* pl = Pl + (size_t)blockIdx.x * KSEQ;
    #pragma unroll
    for (int j = t; j < KSEQ / 2; j += 256) {
        float e0 = buf[2*j]     * inv;
        float e1 = buf[2*j + 1] * inv;
        __nv_bfloat16 h0, h1, l0, l1;
        split_f32(e0, h0, l0);
        split_f32(e1, h1, l1);
        *reinterpret_cast<uint32_t*>(ph + 2*j) = pack2(h0, h1);
        *reinterpret_cast<uint32_t*>(pl + 2*j) = pack2(l0, l1);
    }
}

// ---------------- launch ----------------
extern "C" void kernel_launch(void* const* d_in, const int* in_sizes, int n_in,
                              void* d_out, int out_size)
{
    (void)in_sizes; (void)n_in; (void)out_size;
    const float* Qin  = (const float*)d_in[0];
    const float* Kin  = (const float*)d_in[1];
    const float* Vin  = (const float*)d_in[2];
    const float* mask = (const float*)d_in[3];
    const float* Wq   = (const float*)d_in[4];
    const float* bq   = (const float*)d_in[5];
    const float* Wk   = (const float*)d_in[6];
    const float* bk   = (const float*)d_in[7];
    const float* Wv   = (const float*)d_in[8];
    const float* bv   = (const float*)d_in[9];
    float* out = (float*)d_out;

    float *v, *s;
    __nv_bfloat16 *inh, *inl, *wh, *wl, *qh, *ql, *ksh, *ksl, *vth, *vtl, *ph, *pl;
    cudaGetSymbolAddress((void**)&inh, g_inh);
    cudaGetSymbolAddress((void**)&inl, g_inl);
    cudaGetSymbolAddress((void**)&wh,  g_wh);
    cudaGetSymbolAddress((void**)&wl,  g_wl);
    cudaGetSymbolAddress((void**)&qh,  g_qh);
    cudaGetSymbolAddress((void**)&ql,  g_ql);
    cudaGetSymbolAddress((void**)&ksh, g_ksh);
    cudaGetSymbolAddress((void**)&ksl, g_ksl);
    cudaGetSymbolAddress((void**)&v,   g_v);
    cudaGetSymbolAddress((void**)&vth, g_vth);
    cudaGetSymbolAddress((void**)&vtl, g_vtl);
    cudaGetSymbolAddress((void**)&s,   g_s);
    cudaGetSymbolAddress((void**)&ph,  g_ph);
    cudaGetSymbolAddress((void**)&pl,  g_pl);

    cudaFuncSetAttribute(gemm_hmma<0>, cudaFuncAttributeMaxDynamicSharedMemorySize, SMEM_BYTES);
    cudaFuncSetAttribute(gemm_hmma<1>, cudaFuncAttributeMaxDynamicSharedMemorySize, SMEM_BYTES);
    cudaFuncSetAttribute(gemm_hmma<2>, cudaFuncAttributeMaxDynamicSharedMemorySize, SMEM_BYTES);
    cudaFuncSetAttribute(gemm_hmma<3>, cudaFuncAttributeMaxDynamicSharedMemorySize, SMEM_BYTES);

    const size_t WSZ = (size_t)KDIM * KDIM;
    const size_t ISZ = (size_t)KROWS * KDIM;
    dim3 tb(256);

    // 1) split inputs + transpose/split weights
    const int sgrid = (int)(ISZ / 4 / 256);
    split_pass<<<sgrid, tb>>>(Qin, inh + 0*ISZ, inl + 0*ISZ);
    split_pass<<<sgrid, tb>>>(Kin, inh + 1*ISZ, inl + 1*ISZ);
    split_pass<<<sgrid, tb>>>(Vin, inh + 2*ISZ, inl + 2*ISZ);
    transpose_split<<<dim3(16, 16, 1), tb>>>(Wq, wh + 0*WSZ, wl + 0*WSZ, KDIM, KDIM, 0, 0);
    transpose_split<<<dim3(16, 16, 1), tb>>>(Wk, wh + 1*WSZ, wl + 1*WSZ, KDIM, KDIM, 0, 0);
    transpose_split<<<dim3(16, 16, 1), tb>>>(Wv, wh + 2*WSZ, wl + 2*WSZ, KDIM, KDIM, 0, 0);

    // 2) projections (M=16384, N=512, K=512)
    dim3 gp(KDIM / TILE_N, KROWS / TILE_M, 1);
    gemm_hmma<3><<<gp, GT, SMEM_BYTES>>>(inh + 0*ISZ, inl + 0*ISZ, wh + 0*WSZ, wl + 0*WSZ,
                                         bq, nullptr, qh, ql, KDIM, KDIM, 0, 0, 0, 0);
    gemm_hmma<3><<<gp, GT, SMEM_BYTES>>>(inh + 1*ISZ, inl + 1*ISZ, wh + 1*WSZ, wl + 1*WSZ,
                                         bk, nullptr, ksh, ksl, KDIM, KDIM, 0, 0, 0, 0);
    gemm_hmma<0><<<gp, GT, SMEM_BYTES>>>(inh + 2*ISZ, inl + 2*ISZ, wh + 2*WSZ, wl + 2*WSZ,
                                         bv, v, nullptr, nullptr, KDIM, KDIM, 0, 0, 0, 0);

    // 3) v_s -> v_s^T split  [B][D][S]
    transpose_split<<<dim3(KDIM / 32, KSEQ / 32, KBATCH), tb>>>(
        v, vth, vtl, KSEQ, KDIM, (size_t)KSEQ * KDIM, (size_t)KDIM * KSEQ);

    // 4) scores = q_s k_s^T * scale + mask  (per batch 2048x2048, K=512)
    dim3 gs(KSEQ / TILE_N, KSEQ / TILE_M, KBATCH);
    gemm_hmma<1><<<gs, GT, SMEM_BYTES>>>(qh, ql, ksh, ksl, mask, s, nullptr, nullptr,
                                         KSEQ, KDIM,
                                         (size_t)KSEQ * KDIM, (size_t)KSEQ * KDIM,
                                         (size_t)KSEQ * KSEQ, (size_t)KSEQ * KSEQ);

    // 5) softmax -> split bf16 probs
    softmax_kernel<<<KROWS, 256>>>(s, ph, pl);

    // 6) out = probs @ v_s  (per batch 2048x512, K=2048)
    dim3 ga(KDIM / TILE_N, KSEQ / TILE_M, KBATCH);
    gemm_hmma<2><<<ga, GT, SMEM_BYTES>>>(ph, pl, vth, vtl, nullptr, out, nullptr, nullptr,
                                         KDIM, KSEQ,
                                         (size_t)KSEQ * KSEQ, (size_t)KDIM * KSEQ,
                                         (size_t)KSEQ * KDIM, 0);
}

// round 7
// speedup vs baseline: 1.1016x; 1.0081x over previous
#include <cuda_runtime.h>
#include <cuda_bf16.h>
#include <cstdint>
#include <math.h>

// ---------------- problem constants ----------------
#define KBATCH 8
#define KSEQ   2048
#define KDIM   512
#define KROWS  (KBATCH*KSEQ)   // 16384

// ---------------- scratch (device globals; no allocations) ----------------
__device__ __nv_bfloat16  g_inh[3][(size_t)KROWS * KDIM];   // split Q,K,V inputs (hi)
__device__ __nv_bfloat16  g_inl[3][(size_t)KROWS * KDIM];   // (lo)
__device__ __nv_bfloat16  g_wh [3][(size_t)KDIM * KDIM];    // W^T hi  [e][d] = [N,K]
__device__ __nv_bfloat16  g_wl [3][(size_t)KDIM * KDIM];
__device__ __nv_bfloat16  g_qh [(size_t)KROWS * KDIM];      // q_s split [M,K]
__device__ __nv_bfloat16  g_ql [(size_t)KROWS * KDIM];
__device__ __nv_bfloat16  g_ksh[(size_t)KROWS * KDIM];      // k_s split [N,K]
__device__ __nv_bfloat16  g_ksl[(size_t)KROWS * KDIM];
__device__ float          g_v  [(size_t)KROWS * KDIM];      // v_s fp32
__device__ __nv_bfloat16  g_vth[(size_t)KBATCH * KDIM * KSEQ];  // v_s^T split [B][D][S]
__device__ __nv_bfloat16  g_vtl[(size_t)KBATCH * KDIM * KSEQ];
__device__ float          g_s  [(size_t)KBATCH * KSEQ * KSEQ];  // scores f32
__device__ __nv_bfloat16  g_ph [(size_t)KBATCH * KSEQ * KSEQ];  // probs split
__device__ __nv_bfloat16  g_pl [(size_t)KBATCH * KSEQ * KSEQ];

// ---------------- helpers ----------------
__device__ __forceinline__ uint32_t smem_u32(const void* p) {
    uint32_t a;
    asm("{ .reg .u64 t; cvta.to.shared.u64 t, %1; cvt.u32.u64 %0, t; }" : "=r"(a) : "l"(p));
    return a;
}
__device__ __forceinline__ void split_f32(float x, __nv_bfloat16& h, __nv_bfloat16& l) {
    h = __float2bfloat16(x);
    l = __float2bfloat16(x - __bfloat162float(h));
}
__device__ __forceinline__ uint32_t pack2(__nv_bfloat16 a, __nv_bfloat16 b) {
    return (uint32_t)__bfloat16_as_ushort(a) | ((uint32_t)__bfloat16_as_ushort(b) << 16);
}
__device__ __forceinline__ void ldmx4(uint32_t& r0, uint32_t& r1, uint32_t& r2, uint32_t& r3,
                                      uint32_t addr) {
    asm volatile("ldmatrix.sync.aligned.m8n8.x4.shared.b16 {%0,%1,%2,%3}, [%4];"
                 : "=r"(r0), "=r"(r1), "=r"(r2), "=r"(r3) : "r"(addr));
}
__device__ __forceinline__ void mma_bf16(float* c, const uint32_t* a, uint32_t b0, uint32_t b1) {
    asm volatile("mma.sync.aligned.m16n8k16.row.col.f32.bf16.bf16.f32 "
                 "{%0,%1,%2,%3}, {%4,%5,%6,%7}, {%8,%9}, {%0,%1,%2,%3};"
                 : "+f"(c[0]), "+f"(c[1]), "+f"(c[2]), "+f"(c[3])
                 : "r"(a[0]), "r"(a[1]), "r"(a[2]), "r"(a[3]), "r"(b0), "r"(b1));
}
#define CP16(dst, src) \
    asm volatile("cp.async.cg.shared.global [%0], [%1], 16;" :: "r"(dst), "l"(src))
#define CP_COMMIT() asm volatile("cp.async.commit_group;" ::: "memory")
#define CP_WAIT(n)  asm volatile("cp.async.wait_group %0;" :: "n"(n) : "memory")

__device__ __forceinline__ float ssc() { return 0.044194173824159216f; } // 1/sqrt(512)

// ---------------- HMMA GEMM: 256 threads, CTA 128x256, warp tile 64x64 ----------------
// C[M,N] = (Ah+Al)[M,K] * (Bh+Bl)^T[N,K]  (3-term split)
// EPI 0: +bias -> f32    EPI 1: *scale + mask -> f32
// EPI 2: plain -> f32    EPI 3: +bias -> split bf16 (Ch, Cl)
#define TILE_M 128
#define TILE_N 256
#define TILE_K 32
#define GT 256
#define STAGES 3
#define PSTR 40                        // padded smem row stride (bf16) -> 80 B/row
#define A_TILE_B (128 * PSTR * 2)      // 10240
#define B_TILE_B (256 * PSTR * 2)      // 20480
#define ST_BYTES (2 * A_TILE_B + 2 * B_TILE_B)   // 61440
#define OFF_AH(s) ((s) * ST_BYTES)
#define OFF_AL(s) ((s) * ST_BYTES + A_TILE_B)
#define OFF_BH(s) ((s) * ST_BYTES + 2 * A_TILE_B)
#define OFF_BL(s) ((s) * ST_BYTES + 2 * A_TILE_B + B_TILE_B)
#define SMEM_BYTES (STAGES * ST_BYTES)  // 184320

template<int EPI>
__global__ __launch_bounds__(GT, 1)
void gemm_hmma(const __nv_bfloat16* __restrict__ Ah,
               const __nv_bfloat16* __restrict__ Al,
               const __nv_bfloat16* __restrict__ Bh,
               const __nv_bfloat16* __restrict__ Bl,
               const float* __restrict__ aux,
               float* __restrict__ C,
               __nv_bfloat16* __restrict__ Ch,
               __nv_bfloat16* __restrict__ Cl,
               int N, int K,
               size_t sA, size_t sB, size_t sC, size_t sAux)
{
    extern __shared__ char sm[];
    const uint32_t sb = smem_u32(sm);

    Ah  += sA   * (size_t)blockIdx.z;
    Al  += sA   * (size_t)blockIdx.z;
    Bh  += sB   * (size_t)blockIdx.z;
    Bl  += sB   * (size_t)blockIdx.z;
    C   += sC   * (size_t)blockIdx.z;
    Ch  += sC   * (size_t)blockIdx.z;
    Cl  += sC   * (size_t)blockIdx.z;
    aux += sAux * (size_t)blockIdx.z;

    const int t    = threadIdx.x;
    const int lane = t & 31;
    const int w    = t >> 5;        // 0..7
    const int wm   = w & 1;         // warp row (2) -> M offset 64*wm
    const int wn   = w >> 1;        // warp col (4) -> N offset 64*wn
    const int bm   = blockIdx.y * TILE_M;
    const int bn   = blockIdx.x * TILE_N;

    // cp.async mapping: 256 threads; per stage A:128 rows, B:256 rows, 4x16B per row
    const int cr = t >> 2;          // 0..63
    const int cc = t & 3;           // 16B chunk within 64B row

    // ldmatrix address components (warp tile 64 x 64)
    const int a_r  = wm * 64 + (lane & 15);
    const int a_c8 = (lane >> 4) * 8;
    const int b_r  = wn * 64 + (lane & 7) + ((lane >> 4) & 1) * 8;
    const int b_c8 = ((lane >> 3) & 1) * 8;

    float acc[4][8][4];
    #pragma unroll
    for (int i = 0; i < 4; ++i)
        #pragma unroll
        for (int j = 0; j < 8; ++j)
            #pragma unroll
            for (int e = 0; e < 4; ++e) acc[i][j][e] = 0.0f;

    const int nch = K / TILE_K;

#define ISSUE(j, s) do {                                                        \
        const size_t kco = (size_t)(j) * TILE_K + cc * 8;                       \
        _Pragma("unroll")                                                       \
        for (int p = 0; p < 2; ++p) {   /* A: 128 rows (hi, lo) */              \
            const int row = cr + p * 64;                                        \
            const uint32_t doff = (uint32_t)(row * (PSTR * 2) + cc * 16);       \
            const size_t ga = (size_t)(bm + row) * K + kco;                     \
            CP16(sb + OFF_AH(s) + doff, Ah + ga);                               \
            CP16(sb + OFF_AL(s) + doff, Al + ga);                               \
        }                                                                       \
        _Pragma("unroll")                                                       \
        for (int p = 0; p < 4; ++p) {   /* B: 256 rows (hi, lo) */              \
            const int row = cr + p * 64;                                        \
            const uint32_t doff = (uint32_t)(row * (PSTR * 2) + cc * 16);       \
            const size_t gb = (size_t)(bn + row) * K + kco;                     \
            CP16(sb + OFF_BH(s) + doff, Bh + gb);                               \
            CP16(sb + OFF_BL(s) + doff, Bl + gb);                               \
        }                                                                       \
    } while (0)

    // prologue
    #pragma unroll
    for (int j = 0; j < STAGES - 1; ++j) {
        if (j < nch) ISSUE(j, j);
        CP_COMMIT();
    }

    for (int i = 0; i < nch; ++i) {
        const int jn = i + STAGES - 1;
        if (jn < nch) ISSUE(jn, jn % STAGES);
        CP_COMMIT();
        CP_WAIT(STAGES - 2);
        __syncthreads();

        const int s = i % STAGES;
        #pragma unroll
        for (int h = 0; h < 2; ++h) {
            // B fragments for all 4 n-tiles (hi + lo)
            const uint32_t bcol = (uint32_t)((h * 16 + b_c8) * 2);
            uint32_t bh[4][4], bl[4][4];
            #pragma unroll
            for (int np = 0; np < 4; ++np) {
                const uint32_t boff = (uint32_t)((b_r + np * 16) * (PSTR * 2)) + bcol;
                ldmx4(bh[np][0], bh[np][1], bh[np][2], bh[np][3], sb + OFF_BH(s) + boff);
                ldmx4(bl[np][0], bl[np][1], bl[np][2], bl[np][3], sb + OFF_BL(s) + boff);
            }
            const uint32_t acol = (uint32_t)((h * 16 + a_c8) * 2);
            // process M in pairs of 16-row tiles: mt = 2*mp, 2*mp+1
            #pragma unroll
            for (int mp = 0; mp < 2; ++mp) {
                uint32_t ahr[2][4], alr[2][4];
                #pragma unroll
                for (int m2 = 0; m2 < 2; ++m2) {
                    const uint32_t aoff =
                        (uint32_t)((a_r + (mp * 2 + m2) * 16) * (PSTR * 2)) + acol;
                    ldmx4(ahr[m2][0], ahr[m2][1], ahr[m2][2], ahr[m2][3], sb + OFF_AH(s) + aoff);
                    ldmx4(alr[m2][0], alr[m2][1], alr[m2][2], alr[m2][3], sb + OFF_AL(s) + aoff);
                }
                // term pass 1: Ah * Bh  (each acc written once; reuse distance 16)
                #pragma unroll
                for (int np = 0; np < 4; ++np)
                    #pragma unroll
                    for (int m2 = 0; m2 < 2; ++m2) {
                        mma_bf16(acc[mp*2+m2][2*np],   ahr[m2], bh[np][0], bh[np][1]);
                        mma_bf16(acc[mp*2+m2][2*np+1], ahr[m2], bh[np][2], bh[np][3]);
                    }
                // term pass 2: Ah * Bl
                #pragma unroll
                for (int np = 0; np < 4; ++np)
                    #pragma unroll
                    for (int m2 = 0; m2 < 2; ++m2) {
                        mma_bf16(acc[mp*2+m2][2*np],   ahr[m2], bl[np][0], bl[np][1]);
                        mma_bf16(acc[mp*2+m2][2*np+1], ahr[m2], bl[np][2], bl[np][3]);
                    }
                // term pass 3: Al * Bh
                #pragma unroll
                for (int np = 0; np < 4; ++np)
                    #pragma unroll
                    for (int m2 = 0; m2 < 2; ++m2) {
                        mma_bf16(acc[mp*2+m2][2*np],   alr[m2], bh[np][0], bh[np][1]);
                        mma_bf16(acc[mp*2+m2][2*np+1], alr[m2], bh[np][2], bh[np][3]);
                    }
            }
        }
        __syncthreads();
    }
#undef ISSUE

    // ---------------- epilogue ----------------
    const int er = (lane >> 2);
    const int ec = (lane & 3) * 2;
    #pragma unroll
    for (int mt = 0; mt < 4; ++mt) {
        #pragma unroll
        for (int nt = 0; nt < 8; ++nt) {
            const int col = bn + wn * 64 + nt * 8 + ec;
            #pragma unroll
            for (int half = 0; half < 2; ++half) {
                const int row = bm + wm * 64 + mt * 16 + er + half * 8;
                float x0 = acc[mt][nt][2*half + 0];
                float x1 = acc[mt][nt][2*half + 1];
                if (EPI == 0 || EPI == 3) {
                    x0 += aux[col];
                    x1 += aux[col + 1];
                }
                if (EPI == 1) {
                    const float2 m2 = *reinterpret_cast<const float2*>(&aux[(size_t)row * N + col]);
                    x0 = fmaf(x0, ssc(), m2.x);
                    x1 = fmaf(x1, ssc(), m2.y);
                }
                if (EPI == 3) {
                    __nv_bfloat16 h0,h1,l0,l1;
                    split_f32(x0, h0, l0);
                    split_f32(x1, h1, l1);
                    const size_t o = (size_t)row * N + col;
                    *reinterpret_cast<uint32_t*>(&Ch[o]) = pack2(h0, h1);
                    *reinterpret_cast<uint32_t*>(&Cl[o]) = pack2(l0, l1);
                } else {
                    *reinterpret_cast<float2*>(&C[(size_t)row * N + col]) = make_float2(x0, x1);
                }
            }
        }
    }
}

// ---------------- elementwise split: f32 -> bf16 hi/lo ----------------
__global__ __launch_bounds__(256)
void split_pass(const float* __restrict__ src,
                __nv_bfloat16* __restrict__ dh,
                __nv_bfloat16* __restrict__ dl)
{
    const size_t i = ((size_t)blockIdx.x * 256 + threadIdx.x) * 4;
    float4 v = *reinterpret_cast<const float4*>(src + i);
    __nv_bfloat16 h0,h1,h2,h3,l0,l1,l2,l3;
    split_f32(v.x, h0, l0); split_f32(v.y, h1, l1);
    split_f32(v.z, h2, l2); split_f32(v.w, h3, l3);
    *reinterpret_cast<uint2*>(dh + i) = make_uint2(pack2(h0,h1), pack2(h2,h3));
    *reinterpret_cast<uint2*>(dl + i) = make_uint2(pack2(l0,l1), pack2(l2,l3));
}

// ---------------- transpose + split: dst[c][r] = split(src[r][c]) ----------------
__global__ __launch_bounds__(256)
void transpose_split(const float* __restrict__ src,
                     __nv_bfloat16* __restrict__ dh,
                     __nv_bfloat16* __restrict__ dl,
                     int rows, int cols, size_t ss, size_t ds)
{
    __shared__ float tile[32][33];
    src += ss * (size_t)blockIdx.z;
    dh  += ds * (size_t)blockIdx.z;
    dl  += ds * (size_t)blockIdx.z;
    const int bx = blockIdx.x * 32;
    const int by = blockIdx.y * 32;
    const int tx = threadIdx.x & 31;
    const int ty = threadIdx.x >> 5;
    #pragma unroll
    for (int i = 0; i < 32; i += 8)
        tile[ty + i][tx] = src[(size_t)(by + ty + i) * cols + bx + tx];
    __syncthreads();
    #pragma unroll
    for (int i = 0; i < 32; i += 8) {
        float v = tile[tx][ty + i];
        __nv_bfloat16 h, l;
        split_f32(v, h, l);
        size_t o = (size_t)(bx + ty + i) * rows + by + tx;
        dh[o] = h; dl[o] = l;
    }
}

// ---------------- row softmax over 2048, emits split bf16 probs ----------------
__global__ __launch_bounds__(256)
void softmax_kernel(const float* __restrict__ S,
                    __nv_bfloat16* __restrict__ Ph,
                    __nv_bfloat16* __restrict__ Pl)
{
    __shared__ float buf[KSEQ];
    __shared__ float red[8];
    const float* p = S + (size_t)blockIdx.x * KSEQ;
    const int t = threadIdx.x, lane = t & 31, wid = t >> 5;

    float mx = -3.4e38f;
    #pragma unroll
    for (int i = t; i < KSEQ; i += 256) { float v = p[i]; buf[i] = v; mx = fmaxf(mx, v); }
    #pragma unroll
    for (int o = 16; o > 0; o >>= 1) mx = fmaxf(mx, __shfl_xor_sync(0xffffffffu, mx, o));
    if (lane == 0) red[wid] = mx;
    __syncthreads();
    mx = fmaxf(fmaxf(fmaxf(red[0], red[1]), fmaxf(red[2], red[3])),
               fmaxf(fmaxf(red[4], red[5]), fmaxf(red[6], red[7])));
    __syncthreads();

    float sum = 0.0f;
    #pragma unroll
    for (int i = t; i < KSEQ; i += 256) { float e = __expf(buf[i] - mx); buf[i] = e; sum += e; }
    #pragma unroll
    for (int o = 16; o > 0; o >>= 1) sum += __shfl_xor_sync(0xffffffffu, sum, o);
    if (lane == 0) red[wid] = sum;
    __syncthreads();
    sum = ((red[0] + red[1]) + (red[2] + red[3])) + ((red[4] + red[5]) + (red[6] + red[7]));
    const float inv = 1.0f / sum;

    __nv_bfloat16* ph = Ph + (size_t)blockIdx.x * KSEQ;
    __nv_bfloat16* pl = Pl + (size_t)blockIdx.x * KSEQ;
    #pragma unroll
    for (int j = t; j < KSEQ / 2; j += 256) {
        float e0 = buf[2*j]     * inv;
        float e1 = buf[2*j + 1] * inv;
        __nv_bfloat16 h0, h1, l0, l1;
        split_f32(e0, h0, l0);
        split_f32(e1, h1, l1);
        *reinterpret_cast<uint32_t*>(ph + 2*j) = pack2(h0, h1);
        *reinterpret_cast<uint32_t*>(pl + 2*j) = pack2(l0, l1);
    }
}

// ---------------- launch ----------------
extern "C" void kernel_launch(void* const* d_in, const int* in_sizes, int n_in,
                              void* d_out, int out_size)
{
    (void)in_sizes; (void)n_in; (void)out_size;
    const float* Qin  = (const float*)d_in[0];
    const float* Kin  = (const float*)d_in[1];
    const float* Vin  = (const float*)d_in[2];
    const float* mask = (const float*)d_in[3];
    const float* Wq   = (const float*)d_in[4];
    const float* bq   = (const float*)d_in[5];
    const float* Wk   = (const float*)d_in[6];
    const float* bk   = (const float*)d_in[7];
    const float* Wv   = (const float*)d_in[8];
    const float* bv   = (const float*)d_in[9];
    float* out = (float*)d_out;

    float *v, *s;
    __nv_bfloat16 *inh, *inl, *wh, *wl, *qh, *ql, *ksh, *ksl, *vth, *vtl, *ph, *pl;
    cudaGetSymbolAddress((void**)&inh, g_inh);
    cudaGetSymbolAddress((void**)&inl, g_inl);
    cudaGetSymbolAddress((void**)&wh,  g_wh);
    cudaGetSymbolAddress((void**)&wl,  g_wl);
    cudaGetSymbolAddress((void**)&qh,  g_qh);
    cudaGetSymbolAddress((void**)&ql,  g_ql);
    cudaGetSymbolAddress((void**)&ksh, g_ksh);
    cudaGetSymbolAddress((void**)&ksl, g_ksl);
    cudaGetSymbolAddress((void**)&v,   g_v);
    cudaGetSymbolAddress((void**)&vth, g_vth);
    cudaGetSymbolAddress((void**)&vtl, g_vtl);
    cudaGetSymbolAddress((void**)&s,   g_s);
    cudaGetSymbolAddress((void**)&ph,  g_ph);
    cudaGetSymbolAddress((void**)&pl,  g_pl);

    cudaFuncSetAttribute(gemm_hmma<0>, cudaFuncAttributeMaxDynamicSharedMemorySize, SMEM_BYTES);
    cudaFuncSetAttribute(gemm_hmma<1>, cudaFuncAttributeMaxDynamicSharedMemorySize, SMEM_BYTES);
    cudaFuncSetAttribute(gemm_hmma<2>, cudaFuncAttributeMaxDynamicSharedMemorySize, SMEM_BYTES);
    cudaFuncSetAttribute(gemm_hmma<3>, cudaFuncAttributeMaxDynamicSharedMemorySize, SMEM_BYTES);

    const size_t WSZ = (size_t)KDIM * KDIM;
    const size_t ISZ = (size_t)KROWS * KDIM;
    dim3 tb(256);

    // 1) split inputs + transpose/split weights
    const int sgrid = (int)(ISZ / 4 / 256);
    split_pass<<<sgrid, tb>>>(Qin, inh + 0*ISZ, inl + 0*ISZ);
    split_pass<<<sgrid, tb>>>(Kin, inh + 1*ISZ, inl + 1*ISZ);
    split_pass<<<sgrid, tb>>>(Vin, inh + 2*ISZ, inl + 2*ISZ);
    transpose_split<<<dim3(16, 16, 1), tb>>>(Wq, wh + 0*WSZ, wl + 0*WSZ, KDIM, KDIM, 0, 0);
    transpose_split<<<dim3(16, 16, 1), tb>>>(Wk, wh + 1*WSZ, wl + 1*WSZ, KDIM, KDIM, 0, 0);
    transpose_split<<<dim3(16, 16, 1), tb>>>(Wv, wh + 2*WSZ, wl + 2*WSZ, KDIM, KDIM, 0, 0);

    // 2) projections (M=16384, N=512, K=512)
    dim3 gp(KDIM / TILE_N, KROWS / TILE_M, 1);
    gemm_hmma<3><<<gp, GT, SMEM_BYTES>>>(inh + 0*ISZ, inl + 0*ISZ, wh + 0*WSZ, wl + 0*WSZ,
                                         bq, nullptr, qh, ql, KDIM, KDIM, 0, 0, 0, 0);
    gemm_hmma<3><<<gp, GT, SMEM_BYTES>>>(inh + 1*ISZ, inl + 1*ISZ, wh + 1*WSZ, wl + 1*WSZ,
                                         bk, nullptr, ksh, ksl, KDIM, KDIM, 0, 0, 0, 0);
    gemm_hmma<0><<<gp, GT, SMEM_BYTES>>>(inh + 2*ISZ, inl + 2*ISZ, wh + 2*WSZ, wl + 2*WSZ,
                                         bv, v, nullptr, nullptr, KDIM, KDIM, 0, 0, 0, 0);

    // 3) v_s -> v_s^T split  [B][D][S]
    transpose_split<<<dim3(KDIM / 32, KSEQ / 32, KBATCH), tb>>>(
        v, vth, vtl, KSEQ, KDIM, (size_t)KSEQ * KDIM, (size_t)KDIM * KSEQ);

    // 4) scores = q_s k_s^T * scale + mask  (per batch 2048x2048, K=512)
    dim3 gs(KSEQ / TILE_N, KSEQ / TILE_M, KBATCH);
    gemm_hmma<1><<<gs, GT, SMEM_BYTES>>>(qh, ql, ksh, ksl, mask, s, nullptr, nullptr,
                                         KSEQ, KDIM,
                                         (size_t)KSEQ * KDIM, (size_t)KSEQ * KDIM,
                                         (size_t)KSEQ * KSEQ, (size_t)KSEQ * KSEQ);

    // 5) softmax -> split bf16 probs
    softmax_kernel<<<KROWS, 256>>>(s, ph, pl);

    // 6) out = probs @ v_s  (per batch 2048x512, K=2048)
    dim3 ga(KDIM / TILE_N, KSEQ / TILE_M, KBATCH);
    gemm_hmma<2><<<ga, GT, SMEM_BYTES>>>(ph, pl, vth, vtl, nullptr, out, nullptr, nullptr,
                                         KDIM, KSEQ,
                                         (size_t)KSEQ * KSEQ, (size_t)KDIM * KSEQ,
                                         (size_t)KSEQ * KDIM, 0);
}

// round 8
// speedup vs baseline: 1.3837x; 1.2561x over previous
#include <cuda_runtime.h>
#include <cuda_fp16.h>
#include <cstdint>
#include <math.h>

// ---------------- problem constants ----------------
#define KBATCH 8
#define KSEQ   2048
#define KDIM   512
#define KROWS  (KBATCH*KSEQ)   // 16384

// ---------------- scratch (device globals; no allocations) ----------------
__device__ __half  g_inh[3][(size_t)KROWS * KDIM];   // split Q,K,V inputs (hi)
__device__ __half  g_inl[3][(size_t)KROWS * KDIM];   // (lo)
__device__ __half  g_wh [3][(size_t)KDIM * KDIM];    // W^T hi [e][d] = [N,K]
__device__ __half  g_wl [3][(size_t)KDIM * KDIM];
__device__ __half  g_qh [(size_t)KROWS * KDIM];      // q_s split [M,K]
__device__ __half  g_ql [(size_t)KROWS * KDIM];
__device__ __half  g_kh [(size_t)KROWS * KDIM];      // k_s single fp16 [N,K]
__device__ float   g_v  [(size_t)KROWS * KDIM];      // v_s fp32
__device__ __half  g_vt [(size_t)KBATCH * KDIM * KSEQ]; // v_s^T single fp16 [B][D][S]
__device__ float   g_s  [(size_t)KBATCH * KSEQ * KSEQ]; // scores f32
__device__ __half  g_ph [(size_t)KBATCH * KSEQ * KSEQ]; // probs split
__device__ __half  g_pl [(size_t)KBATCH * KSEQ * KSEQ];

// ---------------- helpers ----------------
__device__ __forceinline__ uint32_t smem_u32(const void* p) {
    uint32_t a;
    asm("{ .reg .u64 t; cvta.to.shared.u64 t, %1; cvt.u32.u64 %0, t; }" : "=r"(a) : "l"(p));
    return a;
}
__device__ __forceinline__ void split_h(float x, __half& h, __half& l) {
    h = __float2half(x);
    l = __float2half(x - __half2float(h));
}
__device__ __forceinline__ uint32_t pack2h(__half a, __half b) {
    return (uint32_t)__half_as_ushort(a) | ((uint32_t)__half_as_ushort(b) << 16);
}
__device__ __forceinline__ void ldmx4(uint32_t& r0, uint32_t& r1, uint32_t& r2, uint32_t& r3,
                                      uint32_t addr) {
    asm volatile("ldmatrix.sync.aligned.m8n8.x4.shared.b16 {%0,%1,%2,%3}, [%4];"
                 : "=r"(r0), "=r"(r1), "=r"(r2), "=r"(r3) : "r"(addr));
}
__device__ __forceinline__ void mma_f16(float* c, const uint32_t* a, uint32_t b0, uint32_t b1) {
    asm volatile("mma.sync.aligned.m16n8k16.row.col.f32.f16.f16.f32 "
                 "{%0,%1,%2,%3}, {%4,%5,%6,%7}, {%8,%9}, {%0,%1,%2,%3};"
                 : "+f"(c[0]), "+f"(c[1]), "+f"(c[2]), "+f"(c[3])
                 : "r"(a[0]), "r"(a[1]), "r"(a[2]), "r"(a[3]), "r"(b0), "r"(b1));
}
#define CP16(dst, src) \
    asm volatile("cp.async.cg.shared.global [%0], [%1], 16;" :: "r"(dst), "l"(src))
#define CP_COMMIT() asm volatile("cp.async.commit_group;" ::: "memory")
#define CP_WAIT(n)  asm volatile("cp.async.wait_group %0;" :: "n"(n) : "memory")

__device__ __forceinline__ float ssc() { return 0.044194173824159216f; } // 1/sqrt(512)

// ---------------- HMMA GEMM: 256 threads, CTA 128x256, warp tile 64x64 ----------------
// BSPL=1: C = (Ah+Al)(Bh+Bl)^T   3 terms (AhBh + AhBl + AlBh)
// BSPL=0: C = (Ah+Al)(Bh)^T      2 terms (AhBh + AlBh), no Bl tile at all
// EPI 0: +bias -> f32    EPI 1: *scale + mask -> f32    EPI 2: plain -> f32
// EPI 3: +bias -> split fp16 (Ch, Cl)    EPI 4: +bias -> single fp16 (Ch)
#define TILE_M 128
#define TILE_N 256
#define TILE_K 32
#define GT 256
#define STAGES 3
#define PSTR 40                        // padded smem row stride (halves) -> 80 B/row
#define A_TILE_B (128 * PSTR * 2)      // 10240
#define B_TILE_B (256 * PSTR * 2)      // 20480

template<int EPI, int BSPL>
__global__ __launch_bounds__(GT, 1)
void gemm_hmma(const __half* __restrict__ Ah,
               const __half* __restrict__ Al,
               const __half* __restrict__ Bh,
               const __half* __restrict__ Bl,
               const float* __restrict__ aux,
               float* __restrict__ C,
               __half* __restrict__ Ch,
               __half* __restrict__ Cl,
               int N, int K,
               size_t sA, size_t sB, size_t sC, size_t sAux)
{
    constexpr int STB = 2 * A_TILE_B + (BSPL ? 2 : 1) * B_TILE_B;

    extern __shared__ char sm[];
    const uint32_t sb = smem_u32(sm);

    Ah  += sA   * (size_t)blockIdx.z;
    Al  += sA   * (size_t)blockIdx.z;
    Bh  += sB   * (size_t)blockIdx.z;
    if (BSPL) Bl += sB * (size_t)blockIdx.z;
    C   += sC   * (size_t)blockIdx.z;
    Ch  += sC   * (size_t)blockIdx.z;
    Cl  += sC   * (size_t)blockIdx.z;
    aux += sAux * (size_t)blockIdx.z;

    const int t    = threadIdx.x;
    const int lane = t & 31;
    const int w    = t >> 5;        // 0..7
    const int wm   = w & 1;         // warp row (2) -> M offset 64*wm
    const int wn   = w >> 1;        // warp col (4) -> N offset 64*wn
    const int bm   = blockIdx.y * TILE_M;
    const int bn   = blockIdx.x * TILE_N;

    const int cr = t >> 2;          // 0..63
    const int cc = t & 3;           // 16B chunk within 64B row

    const int a_r  = wm * 64 + (lane & 15);
    const int a_c8 = (lane >> 4) * 8;
    const int b_r  = wn * 64 + (lane & 7) + ((lane >> 4) & 1) * 8;
    const int b_c8 = ((lane >> 3) & 1) * 8;

    float acc[4][8][4];
    #pragma unroll
    for (int i = 0; i < 4; ++i)
        #pragma unroll
        for (int j = 0; j < 8; ++j)
            #pragma unroll
            for (int e = 0; e < 4; ++e) acc[i][j][e] = 0.0f;

    const int nch = K / TILE_K;

    auto issue = [&](int j, int s) {
        const size_t kco = (size_t)j * TILE_K + cc * 8;
        const uint32_t base = sb + (uint32_t)(s * STB);
        #pragma unroll
        for (int p = 0; p < 2; ++p) {   // A: 128 rows (hi, lo)
            const int row = cr + p * 64;
            const uint32_t doff = (uint32_t)(row * (PSTR * 2) + cc * 16);
            const size_t ga = (size_t)(bm + row) * K + kco;
            CP16(base + doff, Ah + ga);
            CP16(base + A_TILE_B + doff, Al + ga);
        }
        #pragma unroll
        for (int p = 0; p < 4; ++p) {   // B: 256 rows
            const int row = cr + p * 64;
            const uint32_t doff = (uint32_t)(row * (PSTR * 2) + cc * 16);
            const size_t gb = (size_t)(bn + row) * K + kco;
            CP16(base + 2 * A_TILE_B + doff, Bh + gb);
            if (BSPL) CP16(base + 2 * A_TILE_B + B_TILE_B + doff, Bl + gb);
        }
    };

    // prologue
    #pragma unroll
    for (int j = 0; j < STAGES - 1; ++j) {
        if (j < nch) issue(j, j);
        CP_COMMIT();
    }

    for (int i = 0; i < nch; ++i) {
        const int jn = i + STAGES - 1;
        if (jn < nch) issue(jn, jn % STAGES);
        CP_COMMIT();
        CP_WAIT(STAGES - 2);
        __syncthreads();

        const int s = i % STAGES;
        const uint32_t sAH = sb + (uint32_t)(s * STB);
        const uint32_t sAL = sAH + A_TILE_B;
        const uint32_t sBH = sAL + A_TILE_B;
        const uint32_t sBL = sBH + B_TILE_B;

        #pragma unroll
        for (int h = 0; h < 2; ++h) {
            // B fragments for all 4 n-tiles
            const uint32_t bcol = (uint32_t)((h * 16 + b_c8) * 2);
            uint32_t bh[4][4], bl[4][4];
            #pragma unroll
            for (int np = 0; np < 4; ++np) {
                const uint32_t boff = (uint32_t)((b_r + np * 16) * (PSTR * 2)) + bcol;
                ldmx4(bh[np][0], bh[np][1], bh[np][2], bh[np][3], sBH + boff);
                if (BSPL)
                    ldmx4(bl[np][0], bl[np][1], bl[np][2], bl[np][3], sBL + boff);
            }
            const uint32_t acol = (uint32_t)((h * 16 + a_c8) * 2);
            #pragma unroll
            for (int mp = 0; mp < 2; ++mp) {
                uint32_t ahr[2][4], alr[2][4];
                #pragma unroll
                for (int m2 = 0; m2 < 2; ++m2) {
                    const uint32_t aoff =
                        (uint32_t)((a_r + (mp * 2 + m2) * 16) * (PSTR * 2)) + acol;
                    ldmx4(ahr[m2][0], ahr[m2][1], ahr[m2][2], ahr[m2][3], sAH + aoff);
                    ldmx4(alr[m2][0], alr[m2][1], alr[m2][2], alr[m2][3], sAL + aoff);
                }
                // term pass 1: Ah * Bh
                #pragma unroll
                for (int np = 0; np < 4; ++np)
                    #pragma unroll
                    for (int m2 = 0; m2 < 2; ++m2) {
                        mma_f16(acc[mp*2+m2][2*np],   ahr[m2], bh[np][0], bh[np][1]);
                        mma_f16(acc[mp*2+m2][2*np+1], ahr[m2], bh[np][2], bh[np][3]);
                    }
                // term pass 2: Al * Bh
                #pragma unroll
                for (int np = 0; np < 4; ++np)
                    #pragma unroll
                    for (int m2 = 0; m2 < 2; ++m2) {
                        mma_f16(acc[mp*2+m2][2*np],   alr[m2], bh[np][0], bh[np][1]);
                        mma_f16(acc[mp*2+m2][2*np+1], alr[m2], bh[np][2], bh[np][3]);
                    }
                // term pass 3 (BSPL only): Ah * Bl
                if (BSPL) {
                    #pragma unroll
                    for (int np = 0; np < 4; ++np)
                        #pragma unroll
                        for (int m2 = 0; m2 < 2; ++m2) {
                            mma_f16(acc[mp*2+m2][2*np],   ahr[m2], bl[np][0], bl[np][1]);
                            mma_f16(acc[mp*2+m2][2*np+1], ahr[m2], bl[np][2], bl[np][3]);
                        }
                }
            }
        }
        __syncthreads();
    }

    // ---------------- epilogue ----------------
    const int er = (lane >> 2);
    const int ec = (lane & 3) * 2;
    #pragma unroll
    for (int mt = 0; mt < 4; ++mt) {
        #pragma unroll
        for (int nt = 0; nt < 8; ++nt) {
            const int col = bn + wn * 64 + nt * 8 + ec;
            #pragma unroll
            for (int half = 0; half < 2; ++half) {
                const int row = bm + wm * 64 + mt * 16 + er + half * 8;
                float x0 = acc[mt][nt][2*half + 0];
                float x1 = acc[mt][nt][2*half + 1];
                if (EPI == 0 || EPI == 3 || EPI == 4) {
                    x0 += aux[col];
                    x1 += aux[col + 1];
                }
                if (EPI == 1) {
                    const float2 m2 = *reinterpret_cast<const float2*>(&aux[(size_t)row * N + col]);
                    x0 = fmaf(x0, ssc(), m2.x);
                    x1 = fmaf(x1, ssc(), m2.y);
                }
                const size_t o = (size_t)row * N + col;
                if (EPI == 3) {
                    __half h0,h1,l0,l1;
                    split_h(x0, h0, l0);
                    split_h(x1, h1, l1);
                    *reinterpret_cast<uint32_t*>(&Ch[o]) = pack2h(h0, h1);
                    *reinterpret_cast<uint32_t*>(&Cl[o]) = pack2h(l0, l1);
                } else if (EPI == 4) {
                    *reinterpret_cast<uint32_t*>(&Ch[o]) =
                        pack2h(__float2half(x0), __float2half(x1));
                } else {
                    *reinterpret_cast<float2*>(&C[o]) = make_float2(x0, x1);
                }
            }
        }
    }
}

// ---------------- fused input split: 3 tensors -> fp16 hi/lo ----------------
__global__ __launch_bounds__(256)
void split_inputs(const float* __restrict__ q, const float* __restrict__ k,
                  const float* __restrict__ v,
                  __half* __restrict__ dh, __half* __restrict__ dl)
{
    const size_t ISZ = (size_t)KROWS * KDIM;
    const float* src = (blockIdx.z == 0) ? q : (blockIdx.z == 1) ? k : v;
    __half* oh = dh + blockIdx.z * ISZ;
    __half* ol = dl + blockIdx.z * ISZ;
    const size_t i = ((size_t)blockIdx.x * 256 + threadIdx.x) * 4;
    float4 x = *reinterpret_cast<const float4*>(src + i);
    __half h0,h1,h2,h3,l0,l1,l2,l3;
    split_h(x.x, h0, l0); split_h(x.y, h1, l1);
    split_h(x.z, h2, l2); split_h(x.w, h3, l3);
    *reinterpret_cast<uint2*>(oh + i) = make_uint2(pack2h(h0,h1), pack2h(h2,h3));
    *reinterpret_cast<uint2*>(ol + i) = make_uint2(pack2h(l0,l1), pack2h(l2,l3));
}

// ---------------- fused weight transpose+split: 3 weights -> [e][d] hi/lo ----------------
__global__ __launch_bounds__(256)
void wtrans(const float* __restrict__ wq, const float* __restrict__ wk,
            const float* __restrict__ wv,
            __half* __restrict__ dh, __half* __restrict__ dl)
{
    __shared__ float tile[32][33];
    const size_t WSZ = (size_t)KDIM * KDIM;
    const float* src = (blockIdx.z == 0) ? wq : (blockIdx.z == 1) ? wk : wv;
    __half* oh = dh + blockIdx.z * WSZ;
    __half* ol = dl + blockIdx.z * WSZ;
    const int bx = blockIdx.x * 32;
    const int by = blockIdx.y * 32;
    const int tx = threadIdx.x & 31;
    const int ty = threadIdx.x >> 5;
    #pragma unroll
    for (int i = 0; i < 32; i += 8)
        tile[ty + i][tx] = src[(size_t)(by + ty + i) * KDIM + bx + tx];
    __syncthreads();
    #pragma unroll
    for (int i = 0; i < 32; i += 8) {
        float x = tile[tx][ty + i];
        __half h, l;
        split_h(x, h, l);
        size_t o = (size_t)(bx + ty + i) * KDIM + by + tx;
        oh[o] = h; ol[o] = l;
    }
}

// ---------------- v transpose: f32 [B][S][D] -> single fp16 [B][D][S] ----------------
__global__ __launch_bounds__(256)
void vtrans(const float* __restrict__ src, __half* __restrict__ dst)
{
    __shared__ float tile[32][33];
    src += (size_t)KSEQ * KDIM * blockIdx.z;
    dst += (size_t)KDIM * KSEQ * blockIdx.z;
    const int bx = blockIdx.x * 32;   // D
    const int by = blockIdx.y * 32;   // S
    const int tx = threadIdx.x & 31;
    const int ty = threadIdx.x >> 5;
    #pragma unroll
    for (int i = 0; i < 32; i += 8)
        tile[ty + i][tx] = src[(size_t)(by + ty + i) * KDIM + bx + tx];
    __syncthreads();
    #pragma unroll
    for (int i = 0; i < 32; i += 8)
        dst[(size_t)(bx + ty + i) * KSEQ + by + tx] = __float2half(tile[tx][ty + i]);
}

// ---------------- row softmax over 2048, emits split fp16 probs ----------------
__global__ __launch_bounds__(256)
void softmax_kernel(const float* __restrict__ S,
                    __half* __restrict__ Ph,
                    __half* __restrict__ Pl)
{
    __shared__ float buf[KSEQ];
    __shared__ float red[8];
    const float* p = S + (size_t)blockIdx.x * KSEQ;
    const int t = threadIdx.x, lane = t & 31, wid = t >> 5;

    float mx = -3.4e38f;
    #pragma unroll
    for (int i = t; i < KSEQ; i += 256) { float v = p[i]; buf[i] = v; mx = fmaxf(mx, v); }
    #pragma unroll
    for (int o = 16; o > 0; o >>= 1) mx = fmaxf(mx, __shfl_xor_sync(0xffffffffu, mx, o));
    if (lane == 0) red[wid] = mx;
    __syncthreads();
    mx = fmaxf(fmaxf(fmaxf(red[0], red[1]), fmaxf(red[2], red[3])),
               fmaxf(fmaxf(red[4], red[5]), fmaxf(red[6], red[7])));
    __syncthreads();

    float sum = 0.0f;
    #pragma unroll
    for (int i = t; i < KSEQ; i += 256) { float e = __expf(buf[i] - mx); buf[i] = e; sum += e; }
    #pragma unroll
    for (int o = 16; o > 0; o >>= 1) sum += __shfl_xor_sync(0xffffffffu, sum, o);
    if (lane == 0) red[wid] = sum;
    __syncthreads();
    sum = ((red[0] + red[1]) + (red[2] + red[3])) + ((red[4] + red[5]) + (red[6] + red[7]));
    const float inv = 1.0f / sum;

    __half* ph = Ph + (size_t)blockIdx.x * KSEQ;
    __half* pl = Pl + (size_t)blockIdx.x * KSEQ;
    #pragma unroll
    for (int j = t; j < KSEQ / 2; j += 256) {
        float e0 = buf[2*j]     * inv;
        float e1 = buf[2*j + 1] * inv;
        __half h0, h1, l0, l1;
        split_h(e0, h0, l0);
        split_h(e1, h1, l1);
        *reinterpret_cast<uint32_t*>(ph + 2*j) = pack2h(h0, h1);
        *reinterpret_cast<uint32_t*>(pl + 2*j) = pack2h(l0, l1);
    }
}

// ---------------- launch ----------------
extern "C" void kernel_launch(void* const* d_in, const int* in_sizes, int n_in,
                              void* d_out, int out_size)
{
    (void)in_sizes; (void)n_in; (void)out_size;
    const float* Qin  = (const float*)d_in[0];
    const float* Kin  = (const float*)d_in[1];
    const float* Vin  = (const float*)d_in[2];
    const float* mask = (const float*)d_in[3];
    const float* Wq   = (const float*)d_in[4];
    const float* bq   = (const float*)d_in[5];
    const float* Wk   = (const float*)d_in[6];
    const float* bk   = (const float*)d_in[7];
    const float* Wv   = (const float*)d_in[8];
    const float* bv   = (const float*)d_in[9];
    float* out = (float*)d_out;

    float *v, *s;
    __half *inh, *inl, *wh, *wl, *qh, *ql, *kh, *vt, *ph, *pl;
    cudaGetSymbolAddress((void**)&inh, g_inh);
    cudaGetSymbolAddress((void**)&inl, g_inl);
    cudaGetSymbolAddress((void**)&wh,  g_wh);
    cudaGetSymbolAddress((void**)&wl,  g_wl);
    cudaGetSymbolAddress((void**)&qh,  g_qh);
    cudaGetSymbolAddress((void**)&ql,  g_ql);
    cudaGetSymbolAddress((void**)&kh,  g_kh);
    cudaGetSymbolAddress((void**)&v,   g_v);
    cudaGetSymbolAddress((void**)&vt,  g_vt);
    cudaGetSymbolAddress((void**)&s,   g_s);
    cudaGetSymbolAddress((void**)&ph,  g_ph);
    cudaGetSymbolAddress((void**)&pl,  g_pl);

    constexpr int SM_BSPL1 = STAGES * (2 * A_TILE_B + 2 * B_TILE_B);  // 184320
    constexpr int SM_BSPL0 = STAGES * (2 * A_TILE_B + 1 * B_TILE_B);  // 122880
    cudaFuncSetAttribute(gemm_hmma<3,1>, cudaFuncAttributeMaxDynamicSharedMemorySize, SM_BSPL1);
    cudaFuncSetAttribute(gemm_hmma<4,1>, cudaFuncAttributeMaxDynamicSharedMemorySize, SM_BSPL1);
    cudaFuncSetAttribute(gemm_hmma<0,1>, cudaFuncAttributeMaxDynamicSharedMemorySize, SM_BSPL1);
    cudaFuncSetAttribute(gemm_hmma<1,0>, cudaFuncAttributeMaxDynamicSharedMemorySize, SM_BSPL0);
    cudaFuncSetAttribute(gemm_hmma<2,0>, cudaFuncAttributeMaxDynamicSharedMemorySize, SM_BSPL0);

    const size_t ISZ = (size_t)KROWS * KDIM;
    const size_t WSZ = (size_t)KDIM * KDIM;
    dim3 tb(256);

    // 1) fused input split (launch 1)
    split_inputs<<<dim3((int)(ISZ / 4 / 256), 1, 3), tb>>>(Qin, Kin, Vin, inh, inl);
    // 2) fused weight transpose+split (launch 2)
    wtrans<<<dim3(16, 16, 3), tb>>>(Wq, Wk, Wv, wh, wl);

    // 3-5) projections (launches 3,4,5): 3-term fp16, M=16384, N=512, K=512
    dim3 gp(KDIM / TILE_N, KROWS / TILE_M, 1);
    gemm_hmma<3,1><<<gp, GT, SM_BSPL1>>>(inh + 0*ISZ, inl + 0*ISZ, wh + 0*WSZ, wl + 0*WSZ,
                                         bq, nullptr, qh, ql, KDIM, KDIM, 0, 0, 0, 0);
    gemm_hmma<4,1><<<gp, GT, SM_BSPL1>>>(inh + 1*ISZ, inl + 1*ISZ, wh + 1*WSZ, wl + 1*WSZ,
                                         bk, nullptr, kh, nullptr, KDIM, KDIM, 0, 0, 0, 0);
    gemm_hmma<0,1><<<gp, GT, SM_BSPL1>>>(inh + 2*ISZ, inl + 2*ISZ, wh + 2*WSZ, wl + 2*WSZ,
                                         bv, v, nullptr, nullptr, KDIM, KDIM, 0, 0, 0, 0);

    // 6) scores = q_s k_s^T * scale + mask (launch 6 — ncu capture target)
    //    2-term: A = q split, B = k single
    dim3 gs(KSEQ / TILE_N, KSEQ / TILE_M, KBATCH);
    gemm_hmma<1,0><<<gs, GT, SM_BSPL0>>>(qh, ql, kh, nullptr, mask, s, nullptr, nullptr,
                                         KSEQ, KDIM,
                                         (size_t)KSEQ * KDIM, (size_t)KSEQ * KDIM,
                                         (size_t)KSEQ * KSEQ, (size_t)KSEQ * KSEQ);

    // 7) v_s -> v_s^T single fp16
    vtrans<<<dim3(KDIM / 32, KSEQ / 32, KBATCH), tb>>>(v, vt);

    // 8) softmax -> split fp16 probs
    softmax_kernel<<<KROWS, 256>>>(s, ph, pl);

    // 9) out = probs @ v_s : 2-term, A = probs split, B = v^T single
    dim3 ga(KDIM / TILE_N, KSEQ / TILE_M, KBATCH);
    gemm_hmma<2,0><<<ga, GT, SM_BSPL0>>>(ph, pl, vt, nullptr, nullptr, out, nullptr, nullptr,
                                         KDIM, KSEQ,
                                         (size_t)KSEQ * KSEQ, (size_t)KDIM * KSEQ,
                                         (size_t)KSEQ * KDIM, 0);
}

// round 9
// speedup vs baseline: 1.4859x; 1.0738x over previous
#include <cuda_runtime.h>
#include <cuda_fp16.h>
#include <cstdint>
#include <math.h>

// ---------------- problem constants ----------------
#define KBATCH 8
#define KSEQ   2048
#define KDIM   512
#define KROWS  (KBATCH*KSEQ)   // 16384

// ---------------- scratch (device globals; no allocations) ----------------
__device__ __half  g_inh[3][(size_t)KROWS * KDIM];   // split Q,K,V inputs (hi)
__device__ __half  g_inl[3][(size_t)KROWS * KDIM];   // (lo)
__device__ __half  g_wh [3][(size_t)KDIM * KDIM];    // W^T hi [e][d] = [N,K]
__device__ __half  g_wl [3][(size_t)KDIM * KDIM];
__device__ __half  g_qh [(size_t)KROWS * KDIM];      // q_s split [M,K]
__device__ __half  g_ql [(size_t)KROWS * KDIM];
__device__ __half  g_kh [(size_t)KROWS * KDIM];      // k_s single fp16 [N,K]
__device__ float   g_v  [(size_t)KROWS * KDIM];      // v_s fp32
__device__ __half  g_vt [(size_t)KBATCH * KDIM * KSEQ]; // v_s^T single fp16 [B][D][S]
__device__ float   g_s  [(size_t)KBATCH * KSEQ * KSEQ]; // scores f32
__device__ __half  g_ph [(size_t)KBATCH * KSEQ * KSEQ]; // probs split
__device__ __half  g_pl [(size_t)KBATCH * KSEQ * KSEQ];

// ---------------- helpers ----------------
__device__ __forceinline__ uint32_t smem_u32(const void* p) {
    uint32_t a;
    asm("{ .reg .u64 t; cvta.to.shared.u64 t, %1; cvt.u32.u64 %0, t; }" : "=r"(a) : "l"(p));
    return a;
}
__device__ __forceinline__ void split_h(float x, __half& h, __half& l) {
    h = __float2half(x);
    l = __float2half(x - __half2float(h));
}
__device__ __forceinline__ uint32_t pack2h(__half a, __half b) {
    return (uint32_t)__half_as_ushort(a) | ((uint32_t)__half_as_ushort(b) << 16);
}
__device__ __forceinline__ void ldmx4(uint32_t& r0, uint32_t& r1, uint32_t& r2, uint32_t& r3,
                                      uint32_t addr) {
    asm volatile("ldmatrix.sync.aligned.m8n8.x4.shared.b16 {%0,%1,%2,%3}, [%4];"
                 : "=r"(r0), "=r"(r1), "=r"(r2), "=r"(r3) : "r"(addr));
}
__device__ __forceinline__ void mma_f16(float* c, const uint32_t* a, uint32_t b0, uint32_t b1) {
    asm volatile("mma.sync.aligned.m16n8k16.row.col.f32.f16.f16.f32 "
                 "{%0,%1,%2,%3}, {%4,%5,%6,%7}, {%8,%9}, {%0,%1,%2,%3};"
                 : "+f"(c[0]), "+f"(c[1]), "+f"(c[2]), "+f"(c[3])
                 : "r"(a[0]), "r"(a[1]), "r"(a[2]), "r"(a[3]), "r"(b0), "r"(b1));
}
#define CP16(dst, src) \
    asm volatile("cp.async.cg.shared.global [%0], [%1], 16;" :: "r"(dst), "l"(src))
#define CP_COMMIT() asm volatile("cp.async.commit_group;" ::: "memory")

__device__ __forceinline__ float ssc() { return 0.044194173824159216f; } // 1/sqrt(512)

// ---------------- HMMA GEMM: 128 threads, CTA 128x128, warp tile 64x64 ----------------
// 2 CTAs per SM (decorrelated barriers).
// BSPL=1: 3 terms (AhBh + AlBh + AhBl).  BSPL=0: 2 terms (AhBh + AlBh), no Bl.
// EPI 0: +bias -> f32    EPI 1: *scale + mask -> f32    EPI 2: plain -> f32
// EPI 3: +bias -> split fp16 (Ch, Cl)    EPI 4: +bias -> single fp16 (Ch)
#define TILE_M 128
#define TILE_N 128
#define TILE_K 32
#define GT 128
#define PSTR 40                     // padded smem row stride (halves) -> 80 B/row
#define T_B (128 * PSTR * 2)        // 10240 bytes per 128x32 fp16 tile

template<int EPI, int BSPL, int NST>
__global__ __launch_bounds__(GT, 2)
void gemm_hmma(const __half* __restrict__ Ah,
               const __half* __restrict__ Al,
               const __half* __restrict__ Bh,
               const __half* __restrict__ Bl,
               const float* __restrict__ aux,
               float* __restrict__ C,
               __half* __restrict__ Ch,
               __half* __restrict__ Cl,
               int N, int K,
               size_t sA, size_t sB, size_t sC, size_t sAux)
{
    constexpr int NTILE = 2 + (BSPL ? 2 : 1);      // Ah, Al, Bh[, Bl]
    constexpr int STB = NTILE * T_B;

    extern __shared__ char sm[];
    const uint32_t sb = smem_u32(sm);

    Ah  += sA   * (size_t)blockIdx.z;
    Al  += sA   * (size_t)blockIdx.z;
    Bh  += sB   * (size_t)blockIdx.z;
    if (BSPL) Bl += sB * (size_t)blockIdx.z;
    C   += sC   * (size_t)blockIdx.z;
    Ch  += sC   * (size_t)blockIdx.z;
    Cl  += sC   * (size_t)blockIdx.z;
    aux += sAux * (size_t)blockIdx.z;

    const int t    = threadIdx.x;
    const int lane = t & 31;
    const int w    = t >> 5;        // 0..3
    const int wm   = w & 1;         // warp row (2) -> M offset 64*wm
    const int wn   = w >> 1;        // warp col (2) -> N offset 64*wn
    const int bm   = blockIdx.y * TILE_M;
    const int bn   = blockIdx.x * TILE_N;

    const int cr = t >> 2;          // 0..31
    const int cc = t & 3;           // 16B chunk within 64B row

    const int a_r  = wm * 64 + (lane & 15);
    const int a_c8 = (lane >> 4) * 8;
    const int b_r  = wn * 64 + (lane & 7) + ((lane >> 4) & 1) * 8;
    const int b_c8 = ((lane >> 3) & 1) * 8;

    float acc[4][8][4];
    #pragma unroll
    for (int i = 0; i < 4; ++i)
        #pragma unroll
        for (int j = 0; j < 8; ++j)
            #pragma unroll
            for (int e = 0; e < 4; ++e) acc[i][j][e] = 0.0f;

    const int nch = K / TILE_K;

    auto issue = [&](int j, int s) {
        const size_t kco = (size_t)j * TILE_K + cc * 8;
        const uint32_t base = sb + (uint32_t)(s * STB);
        #pragma unroll
        for (int p = 0; p < 4; ++p) {
            const int row = cr + p * 32;
            const uint32_t doff = (uint32_t)(row * (PSTR * 2) + cc * 16);
            const size_t ga = (size_t)(bm + row) * K + kco;
            const size_t gb = (size_t)(bn + row) * K + kco;
            CP16(base + doff,           Ah + ga);
            CP16(base + T_B + doff,     Al + ga);
            CP16(base + 2 * T_B + doff, Bh + gb);
            if (BSPL) CP16(base + 3 * T_B + doff, Bl + gb);
        }
    };

    // prologue
    #pragma unroll
    for (int j = 0; j < NST - 1; ++j) {
        if (j < nch) issue(j, j);
        CP_COMMIT();
    }

    for (int i = 0; i < nch; ++i) {
        const int jn = i + NST - 1;
        if (jn < nch) issue(jn, jn % NST);
        CP_COMMIT();
        asm volatile("cp.async.wait_group %0;" :: "n"(NST - 1) : "memory");
        __syncthreads();

        const int s = i % NST;
        const uint32_t sAH = sb + (uint32_t)(s * STB);
        const uint32_t sAL = sAH + T_B;
        const uint32_t sBH = sAL + T_B;
        const uint32_t sBL = sBH + T_B;

        #pragma unroll
        for (int h = 0; h < 2; ++h) {
            const uint32_t bcol = (uint32_t)((h * 16 + b_c8) * 2);
            uint32_t bh[4][4], bl[4][4];
            #pragma unroll
            for (int np = 0; np < 4; ++np) {
                const uint32_t boff = (uint32_t)((b_r + np * 16) * (PSTR * 2)) + bcol;
                ldmx4(bh[np][0], bh[np][1], bh[np][2], bh[np][3], sBH + boff);
                if (BSPL)
                    ldmx4(bl[np][0], bl[np][1], bl[np][2], bl[np][3], sBL + boff);
            }
            const uint32_t acol = (uint32_t)((h * 16 + a_c8) * 2);
            #pragma unroll
            for (int mp = 0; mp < 2; ++mp) {
                uint32_t ahr[2][4], alr[2][4];
                #pragma unroll
                for (int m2 = 0; m2 < 2; ++m2) {
                    const uint32_t aoff =
                        (uint32_t)((a_r + (mp * 2 + m2) * 16) * (PSTR * 2)) + acol;
                    ldmx4(ahr[m2][0], ahr[m2][1], ahr[m2][2], ahr[m2][3], sAH + aoff);
                    ldmx4(alr[m2][0], alr[m2][1], alr[m2][2], alr[m2][3], sAL + aoff);
                }
                // term pass 1: Ah * Bh
                #pragma unroll
                for (int np = 0; np < 4; ++np)
                    #pragma unroll
                    for (int m2 = 0; m2 < 2; ++m2) {
                        mma_f16(acc[mp*2+m2][2*np],   ahr[m2], bh[np][0], bh[np][1]);
                        mma_f16(acc[mp*2+m2][2*np+1], ahr[m2], bh[np][2], bh[np][3]);
                    }
                // term pass 2: Al * Bh
                #pragma unroll
                for (int np = 0; np < 4; ++np)
                    #pragma unroll
                    for (int m2 = 0; m2 < 2; ++m2) {
                        mma_f16(acc[mp*2+m2][2*np],   alr[m2], bh[np][0], bh[np][1]);
                        mma_f16(acc[mp*2+m2][2*np+1], alr[m2], bh[np][2], bh[np][3]);
                    }
                // term pass 3 (BSPL only): Ah * Bl
                if (BSPL) {
                    #pragma unroll
                    for (int np = 0; np < 4; ++np)
                        #pragma unroll
                        for (int m2 = 0; m2 < 2; ++m2) {
                            mma_f16(acc[mp*2+m2][2*np],   ahr[m2], bl[np][0], bl[np][1]);
                            mma_f16(acc[mp*2+m2][2*np+1], ahr[m2], bl[np][2], bl[np][3]);
                        }
                }
            }
        }
        __syncthreads();
    }

    // ---------------- epilogue ----------------
    const int er = (lane >> 2);
    const int ec = (lane & 3) * 2;
    #pragma unroll
    for (int mt = 0; mt < 4; ++mt) {
        #pragma unroll
        for (int nt = 0; nt < 8; ++nt) {
            const int col = bn + wn * 64 + nt * 8 + ec;
            #pragma unroll
            for (int half = 0; half < 2; ++half) {
                const int row = bm + wm * 64 + mt * 16 + er + half * 8;
                float x0 = acc[mt][nt][2*half + 0];
                float x1 = acc[mt][nt][2*half + 1];
                if (EPI == 0 || EPI == 3 || EPI == 4) {
                    x0 += aux[col];
                    x1 += aux[col + 1];
                }
                if (EPI == 1) {
                    const float2 m2 = *reinterpret_cast<const float2*>(&aux[(size_t)row * N + col]);
                    x0 = fmaf(x0, ssc(), m2.x);
                    x1 = fmaf(x1, ssc(), m2.y);
                }
                const size_t o = (size_t)row * N + col;
                if (EPI == 3) {
                    __half h0,h1,l0,l1;
                    split_h(x0, h0, l0);
                    split_h(x1, h1, l1);
                    *reinterpret_cast<uint32_t*>(&Ch[o]) = pack2h(h0, h1);
                    *reinterpret_cast<uint32_t*>(&Cl[o]) = pack2h(l0, l1);
                } else if (EPI == 4) {
                    *reinterpret_cast<uint32_t*>(&Ch[o]) =
                        pack2h(__float2half(x0), __float2half(x1));
                } else {
                    *reinterpret_cast<float2*>(&C[o]) = make_float2(x0, x1);
                }
            }
        }
    }
}

// ---------------- fused input split: 3 tensors -> fp16 hi/lo ----------------
__global__ __launch_bounds__(256)
void split_inputs(const float* __restrict__ q, const float* __restrict__ k,
                  const float* __restrict__ v,
                  __half* __restrict__ dh, __half* __restrict__ dl)
{
    const size_t ISZ = (size_t)KROWS * KDIM;
    const float* src = (blockIdx.z == 0) ? q : (blockIdx.z == 1) ? k : v;
    __half* oh = dh + blockIdx.z * ISZ;
    __half* ol = dl + blockIdx.z * ISZ;
    const size_t i = ((size_t)blockIdx.x * 256 + threadIdx.x) * 4;
    float4 x = *reinterpret_cast<const float4*>(src + i);
    __half h0,h1,h2,h3,l0,l1,l2,l3;
    split_h(x.x, h0, l0); split_h(x.y, h1, l1);
    split_h(x.z, h2, l2); split_h(x.w, h3, l3);
    *reinterpret_cast<uint2*>(oh + i) = make_uint2(pack2h(h0,h1), pack2h(h2,h3));
    *reinterpret_cast<uint2*>(ol + i) = make_uint2(pack2h(l0,l1), pack2h(l2,l3));
}

// ---------------- fused weight transpose+split ----------------
__global__ __launch_bounds__(256)
void wtrans(const float* __restrict__ wq, const float* __restrict__ wk,
            const float* __restrict__ wv,
            __half* __restrict__ dh, __half* __restrict__ dl)
{
    __shared__ float tile[32][33];
    const size_t WSZ = (size_t)KDIM * KDIM;
    const float* src = (blockIdx.z == 0) ? wq : (blockIdx.z == 1) ? wk : wv;
    __half* oh = dh + blockIdx.z * WSZ;
    __half* ol = dl + blockIdx.z * WSZ;
    const int bx = blockIdx.x * 32;
    const int by = blockIdx.y * 32;
    const int tx = threadIdx.x & 31;
    const int ty = threadIdx.x >> 5;
    #pragma unroll
    for (int i = 0; i < 32; i += 8)
        tile[ty + i][tx] = src[(size_t)(by + ty + i) * KDIM + bx + tx];
    __syncthreads();
    #pragma unroll
    for (int i = 0; i < 32; i += 8) {
        float x = tile[tx][ty + i];
        __half h, l;
        split_h(x, h, l);
        size_t o = (size_t)(bx + ty + i) * KDIM + by + tx;
        oh[o] = h; ol[o] = l;
    }
}

// ---------------- v transpose: f32 [B][S][D] -> single fp16 [B][D][S] ----------------
__global__ __launch_bounds__(256)
void vtrans(const float* __restrict__ src, __half* __restrict__ dst)
{
    __shared__ float tile[32][33];
    src += (size_t)KSEQ * KDIM * blockIdx.z;
    dst += (size_t)KDIM * KSEQ * blockIdx.z;
    const int bx = blockIdx.x * 32;   // D
    const int by = blockIdx.y * 32;   // S
    const int tx = threadIdx.x & 31;
    const int ty = threadIdx.x >> 5;
    #pragma unroll
    for (int i = 0; i < 32; i += 8)
        tile[ty + i][tx] = src[(size_t)(by + ty + i) * KDIM + bx + tx];
    __syncthreads();
    #pragma unroll
    for (int i = 0; i < 32; i += 8)
        dst[(size_t)(bx + ty + i) * KSEQ + by + tx] = __float2half(tile[tx][ty + i]);
}

// ---------------- row softmax over 2048, emits split fp16 probs ----------------
__global__ __launch_bounds__(256)
void softmax_kernel(const float* __restrict__ S,
                    __half* __restrict__ Ph,
                    __half* __restrict__ Pl)
{
    __shared__ float buf[KSEQ];
    __shared__ float red[8];
    const float* p = S + (size_t)blockIdx.x * KSEQ;
    const int t = threadIdx.x, lane = t & 31, wid = t >> 5;

    float mx = -3.4e38f;
    #pragma unroll
    for (int i = t; i < KSEQ; i += 256) { float v = p[i]; buf[i] = v; mx = fmaxf(mx, v); }
    #pragma unroll
    for (int o = 16; o > 0; o >>= 1) mx = fmaxf(mx, __shfl_xor_sync(0xffffffffu, mx, o));
    if (lane == 0) red[wid] = mx;
    __syncthreads();
    mx = fmaxf(fmaxf(fmaxf(red[0], red[1]), fmaxf(red[2], red[3])),
               fmaxf(fmaxf(red[4], red[5]), fmaxf(red[6], red[7])));
    __syncthreads();

    float sum = 0.0f;
    #pragma unroll
    for (int i = t; i < KSEQ; i += 256) { float e = __expf(buf[i] - mx); buf[i] = e; sum += e; }
    #pragma unroll
    for (int o = 16; o > 0; o >>= 1) sum += __shfl_xor_sync(0xffffffffu, sum, o);
    if (lane == 0) red[wid] = sum;
    __syncthreads();
    sum = ((red[0] + red[1]) + (red[2] + red[3])) + ((red[4] + red[5]) + (red[6] + red[7]));
    const float inv = 1.0f / sum;

    __half* ph = Ph + (size_t)blockIdx.x * KSEQ;
    __half* pl = Pl + (size_t)blockIdx.x * KSEQ;
    #pragma unroll
    for (int j = t; j < KSEQ / 2; j += 256) {
        float e0 = buf[2*j]     * inv;
        float e1 = buf[2*j + 1] * inv;
        __half h0, h1, l0, l1;
        split_h(e0, h0, l0);
        split_h(e1, h1, l1);
        *reinterpret_cast<uint32_t*>(ph + 2*j) = pack2h(h0, h1);
        *reinterpret_cast<uint32_t*>(pl + 2*j) = pack2h(l0, l1);
    }
}

// ---------------- launch ----------------
extern "C" void kernel_launch(void* const* d_in, const int* in_sizes, int n_in,
                              void* d_out, int out_size)
{
    (void)in_sizes; (void)n_in; (void)out_size;
    const float* Qin  = (const float*)d_in[0];
    const float* Kin  = (const float*)d_in[1];
    const float* Vin  = (const float*)d_in[2];
    const float* mask = (const float*)d_in[3];
    const float* Wq   = (const float*)d_in[4];
    const float* bq   = (const float*)d_in[5];
    const float* Wk   = (const float*)d_in[6];
    const float* bk   = (const float*)d_in[7];
    const float* Wv   = (const float*)d_in[8];
    const float* bv   = (const float*)d_in[9];
    float* out = (float*)d_out;

    float *v, *s;
    __half *inh, *inl, *wh, *wl, *qh, *ql, *kh, *vt, *ph, *pl;
    cudaGetSymbolAddress((void**)&inh, g_inh);
    cudaGetSymbolAddress((void**)&inl, g_inl);
    cudaGetSymbolAddress((void**)&wh,  g_wh);
    cudaGetSymbolAddress((void**)&wl,  g_wl);
    cudaGetSymbolAddress((void**)&qh,  g_qh);
    cudaGetSymbolAddress((void**)&ql,  g_ql);
    cudaGetSymbolAddress((void**)&kh,  g_kh);
    cudaGetSymbolAddress((void**)&v,   g_v);
    cudaGetSymbolAddress((void**)&vt,  g_vt);
    cudaGetSymbolAddress((void**)&s,   g_s);
    cudaGetSymbolAddress((void**)&ph,  g_ph);
    cudaGetSymbolAddress((void**)&pl,  g_pl);

    constexpr int SM3T = 2 * 4 * T_B;   // 3-term, 2 stages: 81920
    constexpr int SM2T = 3 * 3 * T_B;   // 2-term, 3 stages: 92160
    cudaFuncSetAttribute(gemm_hmma<3,1,2>, cudaFuncAttributeMaxDynamicSharedMemorySize, SM3T);
    cudaFuncSetAttribute(gemm_hmma<4,1,2>, cudaFuncAttributeMaxDynamicSharedMemorySize, SM3T);
    cudaFuncSetAttribute(gemm_hmma<0,1,2>, cudaFuncAttributeMaxDynamicSharedMemorySize, SM3T);
    cudaFuncSetAttribute(gemm_hmma<1,0,3>, cudaFuncAttributeMaxDynamicSharedMemorySize, SM2T);
    cudaFuncSetAttribute(gemm_hmma<2,0,3>, cudaFuncAttributeMaxDynamicSharedMemorySize, SM2T);

    const size_t ISZ = (size_t)KROWS * KDIM;
    const size_t WSZ = (size_t)KDIM * KDIM;
    dim3 tb(256);

    // 1-2) preprocessing
    split_inputs<<<dim3((int)(ISZ / 4 / 256), 1, 3), tb>>>(Qin, Kin, Vin, inh, inl);
    wtrans<<<dim3(16, 16, 3), tb>>>(Wq, Wk, Wv, wh, wl);

    // 3-5) projections: 3-term fp16, M=16384, N=512, K=512
    dim3 gp(KDIM / TILE_N, KROWS / TILE_M, 1);
    gemm_hmma<3,1,2><<<gp, GT, SM3T>>>(inh + 0*ISZ, inl + 0*ISZ, wh + 0*WSZ, wl + 0*WSZ,
                                       bq, nullptr, qh, ql, KDIM, KDIM, 0, 0, 0, 0);
    gemm_hmma<4,1,2><<<gp, GT, SM3T>>>(inh + 1*ISZ, inl + 1*ISZ, wh + 1*WSZ, wl + 1*WSZ,
                                       bk, nullptr, kh, nullptr, KDIM, KDIM, 0, 0, 0, 0);
    gemm_hmma<0,1,2><<<gp, GT, SM3T>>>(inh + 2*ISZ, inl + 2*ISZ, wh + 2*WSZ, wl + 2*WSZ,
                                       bv, v, nullptr, nullptr, KDIM, KDIM, 0, 0, 0, 0);

    // 6) scores = q_s k_s^T * scale + mask  (2-term; ncu capture target)
    dim3 gs(KSEQ / TILE_N, KSEQ / TILE_M, KBATCH);
    gemm_hmma<1,0,3><<<gs, GT, SM2T>>>(qh, ql, kh, nullptr, mask, s, nullptr, nullptr,
                                       KSEQ, KDIM,
                                       (size_t)KSEQ * KDIM, (size_t)KSEQ * KDIM,
                                       (size_t)KSEQ * KSEQ, (size_t)KSEQ * KSEQ);

    // 7) v_s -> v_s^T single fp16
    vtrans<<<dim3(KDIM / 32, KSEQ / 32, KBATCH), tb>>>(v, vt);

    // 8) softmax -> split fp16 probs
    softmax_kernel<<<KROWS, 256>>>(s, ph, pl);

    // 9) out = probs @ v_s : 2-term
    dim3 ga(KDIM / TILE_N, KSEQ / TILE_M, KBATCH);
    gemm_hmma<2,0,3><<<ga, GT, SM2T>>>(ph, pl, vt, nullptr, nullptr, out, nullptr, nullptr,
                                       KDIM, KSEQ,
                                       (size_t)KSEQ * KSEQ, (size_t)KDIM * KSEQ,
                                       (size_t)KSEQ * KDIM, 0);
}

// round 10
// speedup vs baseline: 1.7684x; 1.1901x over previous
#include <cuda_runtime.h>
#include <cuda_fp16.h>
#include <cstdint>
#include <math.h>

// ---------------- problem constants ----------------
#define KBATCH 8
#define KSEQ   2048
#define KDIM   512
#define KROWS  (KBATCH*KSEQ)   // 16384

// ---------------- scratch (device globals; no allocations) ----------------
__device__ __half  g_inh[3][(size_t)KROWS * KDIM];   // split Q,K,V inputs (hi)
__device__ __half  g_inl[3][(size_t)KROWS * KDIM];   // (lo)
__device__ __half  g_wh [3][(size_t)KDIM * KDIM];    // W^T hi [e][d] = [N,K]
__device__ __half  g_wl [3][(size_t)KDIM * KDIM];
__device__ __half  g_qh [(size_t)KROWS * KDIM];      // q_s split [M,K]
__device__ __half  g_ql [(size_t)KROWS * KDIM];
__device__ __half  g_kh [(size_t)KROWS * KDIM];      // k_s single fp16 [N,K]
__device__ float   g_v  [(size_t)KROWS * KDIM];      // v_s fp32
__device__ __half  g_vt [(size_t)KBATCH * KDIM * KSEQ]; // v_s^T single fp16 [B][D][S]
__device__ float   g_s  [(size_t)KBATCH * KSEQ * KSEQ]; // scores f32
__device__ __half  g_ph [(size_t)KBATCH * KSEQ * KSEQ]; // probs single fp16

// ---------------- helpers ----------------
__device__ __forceinline__ uint32_t smem_u32(const void* p) {
    uint32_t a;
    asm("{ .reg .u64 t; cvta.to.shared.u64 t, %1; cvt.u32.u64 %0, t; }" : "=r"(a) : "l"(p));
    return a;
}
__device__ __forceinline__ void split_h(float x, __half& h, __half& l) {
    h = __float2half(x);
    l = __float2half(x - __half2float(h));
}
__device__ __forceinline__ uint32_t pack2h(__half a, __half b) {
    return (uint32_t)__half_as_ushort(a) | ((uint32_t)__half_as_ushort(b) << 16);
}
__device__ __forceinline__ void ldmx4(uint32_t& r0, uint32_t& r1, uint32_t& r2, uint32_t& r3,
                                      uint32_t addr) {
    asm volatile("ldmatrix.sync.aligned.m8n8.x4.shared.b16 {%0,%1,%2,%3}, [%4];"
                 : "=r"(r0), "=r"(r1), "=r"(r2), "=r"(r3) : "r"(addr));
}
__device__ __forceinline__ void mma_f16(float* c, const uint32_t* a, uint32_t b0, uint32_t b1) {
    asm volatile("mma.sync.aligned.m16n8k16.row.col.f32.f16.f16.f32 "
                 "{%0,%1,%2,%3}, {%4,%5,%6,%7}, {%8,%9}, {%0,%1,%2,%3};"
                 : "+f"(c[0]), "+f"(c[1]), "+f"(c[2]), "+f"(c[3])
                 : "r"(a[0]), "r"(a[1]), "r"(a[2]), "r"(a[3]), "r"(b0), "r"(b1));
}
#define CP16(dst, src) \
    asm volatile("cp.async.cg.shared.global [%0], [%1], 16;" :: "r"(dst), "l"(src))
#define CP_COMMIT() asm volatile("cp.async.commit_group;" ::: "memory")

__device__ __forceinline__ float ssc() { return 0.044194173824159216f; } // 1/sqrt(512)

// ---------------- HMMA GEMM: 128 threads, CTA 128x128, warp tile 64x64 ----------------
// 2 CTAs per SM.  TERMS=3: AhBh+AlBh+AhBl.  TERMS=2: AhBh+AlBh.  TERMS=1: AhBh only.
// EPI 0: +bias -> f32    EPI 1: *scale + mask -> f32    EPI 2: plain -> f32
// EPI 3: +bias -> split fp16 (Ch, Cl)    EPI 4: +bias -> single fp16 (Ch)
#define TILE_M 128
#define TILE_N 128
#define TILE_K 32
#define GT 128
#define PSTR 40                     // padded smem row stride (halves) -> 80 B/row
#define T_B (128 * PSTR * 2)        // 10240 bytes per 128x32 fp16 tile

template<int EPI, int TERMS, int NST>
__global__ __launch_bounds__(GT, 2)
void gemm_hmma(const __half* __restrict__ Ah,
               const __half* __restrict__ Al,
               const __half* __restrict__ Bh,
               const __half* __restrict__ Bl,
               const float* __restrict__ aux,
               float* __restrict__ C,
               __half* __restrict__ Ch,
               __half* __restrict__ Cl,
               int N, int K,
               size_t sA, size_t sB, size_t sC, size_t sAux)
{
    constexpr bool HAS_AL = (TERMS >= 2);
    constexpr bool HAS_BL = (TERMS == 3);
    constexpr int  NTILE  = 1 + (HAS_AL ? 1 : 0) + 1 + (HAS_BL ? 1 : 0);
    constexpr int  STB    = NTILE * T_B;

    extern __shared__ char sm[];
    const uint32_t sb = smem_u32(sm);

    Ah  += sA   * (size_t)blockIdx.z;
    if (HAS_AL) Al += sA * (size_t)blockIdx.z;
    Bh  += sB   * (size_t)blockIdx.z;
    if (HAS_BL) Bl += sB * (size_t)blockIdx.z;
    C   += sC   * (size_t)blockIdx.z;
    Ch  += sC   * (size_t)blockIdx.z;
    Cl  += sC   * (size_t)blockIdx.z;
    aux += sAux * (size_t)blockIdx.z;

    const int t    = threadIdx.x;
    const int lane = t & 31;
    const int w    = t >> 5;        // 0..3
    const int wm   = w & 1;         // warp row (2) -> M offset 64*wm
    const int wn   = w >> 1;        // warp col (2) -> N offset 64*wn
    const int bm   = blockIdx.y * TILE_M;
    const int bn   = blockIdx.x * TILE_N;

    const int cr = t >> 2;          // 0..31
    const int cc = t & 3;           // 16B chunk within 64B row

    const int a_r  = wm * 64 + (lane & 15);
    const int a_c8 = (lane >> 4) * 8;
    const int b_r  = wn * 64 + (lane & 7) + ((lane >> 4) & 1) * 8;
    const int b_c8 = ((lane >> 3) & 1) * 8;

    float acc[4][8][4];
    #pragma unroll
    for (int i = 0; i < 4; ++i)
        #pragma unroll
        for (int j = 0; j < 8; ++j)
            #pragma unroll
            for (int e = 0; e < 4; ++e) acc[i][j][e] = 0.0f;

    const int nch = K / TILE_K;

    // smem tile offsets within a stage
    constexpr int OAH = 0;
    constexpr int OAL = T_B;                                 // valid if HAS_AL
    constexpr int OBH = (HAS_AL ? 2 : 1) * T_B;
    constexpr int OBL = OBH + T_B;                           // valid if HAS_BL

    auto issue = [&](int j, int s) {
        const size_t kco = (size_t)j * TILE_K + cc * 8;
        const uint32_t base = sb + (uint32_t)(s * STB);
        #pragma unroll
        for (int p = 0; p < 4; ++p) {
            const int row = cr + p * 32;
            const uint32_t doff = (uint32_t)(row * (PSTR * 2) + cc * 16);
            const size_t ga = (size_t)(bm + row) * K + kco;
            const size_t gb = (size_t)(bn + row) * K + kco;
            CP16(base + OAH + doff, Ah + ga);
            if (HAS_AL) CP16(base + OAL + doff, Al + ga);
            CP16(base + OBH + doff, Bh + gb);
            if (HAS_BL) CP16(base + OBL + doff, Bl + gb);
        }
    };

    // prologue
    #pragma unroll
    for (int j = 0; j < NST - 1; ++j) {
        if (j < nch) issue(j, j);
        CP_COMMIT();
    }

    for (int i = 0; i < nch; ++i) {
        const int jn = i + NST - 1;
        if (jn < nch) issue(jn, jn % NST);
        CP_COMMIT();
        asm volatile("cp.async.wait_group %0;" :: "n"(NST - 1) : "memory");
        __syncthreads();

        const int s = i % NST;
        const uint32_t sAH = sb + (uint32_t)(s * STB) + OAH;
        const uint32_t sAL = sb + (uint32_t)(s * STB) + OAL;
        const uint32_t sBH = sb + (uint32_t)(s * STB) + OBH;
        const uint32_t sBL = sb + (uint32_t)(s * STB) + OBL;

        #pragma unroll
        for (int h = 0; h < 2; ++h) {
            const uint32_t bcol = (uint32_t)((h * 16 + b_c8) * 2);
            uint32_t bh[4][4], bl[4][4];
            #pragma unroll
            for (int np = 0; np < 4; ++np) {
                const uint32_t boff = (uint32_t)((b_r + np * 16) * (PSTR * 2)) + bcol;
                ldmx4(bh[np][0], bh[np][1], bh[np][2], bh[np][3], sBH + boff);
                if (HAS_BL)
                    ldmx4(bl[np][0], bl[np][1], bl[np][2], bl[np][3], sBL + boff);
            }
            const uint32_t acol = (uint32_t)((h * 16 + a_c8) * 2);
            #pragma unroll
            for (int mp = 0; mp < 2; ++mp) {
                uint32_t ahr[2][4], alr[2][4];
                #pragma unroll
                for (int m2 = 0; m2 < 2; ++m2) {
                    const uint32_t aoff =
                        (uint32_t)((a_r + (mp * 2 + m2) * 16) * (PSTR * 2)) + acol;
                    ldmx4(ahr[m2][0], ahr[m2][1], ahr[m2][2], ahr[m2][3], sAH + aoff);
                    if (HAS_AL)
                        ldmx4(alr[m2][0], alr[m2][1], alr[m2][2], alr[m2][3], sAL + aoff);
                }
                // term 1: Ah * Bh
                #pragma unroll
                for (int np = 0; np < 4; ++np)
                    #pragma unroll
                    for (int m2 = 0; m2 < 2; ++m2) {
                        mma_f16(acc[mp*2+m2][2*np],   ahr[m2], bh[np][0], bh[np][1]);
                        mma_f16(acc[mp*2+m2][2*np+1], ahr[m2], bh[np][2], bh[np][3]);
                    }
                // term 2: Al * Bh
                if (HAS_AL) {
                    #pragma unroll
                    for (int np = 0; np < 4; ++np)
                        #pragma unroll
                        for (int m2 = 0; m2 < 2; ++m2) {
                            mma_f16(acc[mp*2+m2][2*np],   alr[m2], bh[np][0], bh[np][1]);
                            mma_f16(acc[mp*2+m2][2*np+1], alr[m2], bh[np][2], bh[np][3]);
                        }
                }
                // term 3: Ah * Bl
                if (HAS_BL) {
                    #pragma unroll
                    for (int np = 0; np < 4; ++np)
                        #pragma unroll
                        for (int m2 = 0; m2 < 2; ++m2) {
                            mma_f16(acc[mp*2+m2][2*np],   ahr[m2], bl[np][0], bl[np][1]);
                            mma_f16(acc[mp*2+m2][2*np+1], ahr[m2], bl[np][2], bl[np][3]);
                        }
                }
            }
        }
        __syncthreads();
    }

    // ---------------- epilogue ----------------
    const int er = (lane >> 2);
    const int ec = (lane & 3) * 2;
    #pragma unroll
    for (int mt = 0; mt < 4; ++mt) {
        #pragma unroll
        for (int nt = 0; nt < 8; ++nt) {
            const int col = bn + wn * 64 + nt * 8 + ec;
            #pragma unroll
            for (int half = 0; half < 2; ++half) {
                const int row = bm + wm * 64 + mt * 16 + er + half * 8;
                float x0 = acc[mt][nt][2*half + 0];
                float x1 = acc[mt][nt][2*half + 1];
                if (EPI == 0 || EPI == 3 || EPI == 4) {
                    x0 += aux[col];
                    x1 += aux[col + 1];
                }
                if (EPI == 1) {
                    const float2 m2 = *reinterpret_cast<const float2*>(&aux[(size_t)row * N + col]);
                    x0 = fmaf(x0, ssc(), m2.x);
                    x1 = fmaf(x1, ssc(), m2.y);
                }
                const size_t o = (size_t)row * N + col;
                if (EPI == 3) {
                    __half h0,h1,l0,l1;
                    split_h(x0, h0, l0);
                    split_h(x1, h1, l1);
                    *reinterpret_cast<uint32_t*>(&Ch[o]) = pack2h(h0, h1);
                    *reinterpret_cast<uint32_t*>(&Cl[o]) = pack2h(l0, l1);
                } else if (EPI == 4) {
                    *reinterpret_cast<uint32_t*>(&Ch[o]) =
                        pack2h(__float2half(x0), __float2half(x1));
                } else {
                    *reinterpret_cast<float2*>(&C[o]) = make_float2(x0, x1);
                }
            }
        }
    }
}

// ---------------- fused input split: 3 tensors -> fp16 hi/lo ----------------
__global__ __launch_bounds__(256)
void split_inputs(const float* __restrict__ q, const float* __restrict__ k,
                  const float* __restrict__ v,
                  __half* __restrict__ dh, __half* __restrict__ dl)
{
    const size_t ISZ = (size_t)KROWS * KDIM;
    const float* src = (blockIdx.z == 0) ? q : (blockIdx.z == 1) ? k : v;
    __half* oh = dh + blockIdx.z * ISZ;
    __half* ol = dl + blockIdx.z * ISZ;
    const size_t i = ((size_t)blockIdx.x * 256 + threadIdx.x) * 4;
    float4 x = *reinterpret_cast<const float4*>(src + i);
    __half h0,h1,h2,h3,l0,l1,l2,l3;
    split_h(x.x, h0, l0); split_h(x.y, h1, l1);
    split_h(x.z, h2, l2); split_h(x.w, h3, l3);
    *reinterpret_cast<uint2*>(oh + i) = make_uint2(pack2h(h0,h1), pack2h(h2,h3));
    *reinterpret_cast<uint2*>(ol + i) = make_uint2(pack2h(l0,l1), pack2h(l2,l3));
}

// ---------------- fused weight transpose+split ----------------
__global__ __launch_bounds__(256)
void wtrans(const float* __restrict__ wq, const float* __restrict__ wk,
            const float* __restrict__ wv,
            __half* __restrict__ dh, __half* __restrict__ dl)
{
    __shared__ float tile[32][33];
    const size_t WSZ = (size_t)KDIM * KDIM;
    const float* src = (blockIdx.z == 0) ? wq : (blockIdx.z == 1) ? wk : wv;
    __half* oh = dh + blockIdx.z * WSZ;
    __half* ol = dl + blockIdx.z * WSZ;
    const int bx = blockIdx.x * 32;
    const int by = blockIdx.y * 32;
    const int tx = threadIdx.x & 31;
    const int ty = threadIdx.x >> 5;
    #pragma unroll
    for (int i = 0; i < 32; i += 8)
        tile[ty + i][tx] = src[(size_t)(by + ty + i) * KDIM + bx + tx];
    __syncthreads();
    #pragma unroll
    for (int i = 0; i < 32; i += 8) {
        float x = tile[tx][ty + i];
        __half h, l;
        split_h(x, h, l);
        size_t o = (size_t)(bx + ty + i) * KDIM + by + tx;
        oh[o] = h; ol[o] = l;
    }
}

// ---------------- v transpose: f32 [B][S][D] -> single fp16 [B][D][S] ----------------
__global__ __launch_bounds__(256)
void vtrans(const float* __restrict__ src, __half* __restrict__ dst)
{
    __shared__ float tile[32][33];
    src += (size_t)KSEQ * KDIM * blockIdx.z;
    dst += (size_t)KDIM * KSEQ * blockIdx.z;
    const int bx = blockIdx.x * 32;   // D
    const int by = blockIdx.y * 32;   // S
    const int tx = threadIdx.x & 31;
    const int ty = threadIdx.x >> 5;
    #pragma unroll
    for (int i = 0; i < 32; i += 8)
        tile[ty + i][tx] = src[(size_t)(by + ty + i) * KDIM + bx + tx];
    __syncthreads();
    #pragma unroll
    for (int i = 0; i < 32; i += 8)
        dst[(size_t)(bx + ty + i) * KSEQ + by + tx] = __float2half(tile[tx][ty + i]);
}

// ---------------- row softmax over 2048, emits single fp16 probs ----------------
__global__ __launch_bounds__(256)
void softmax_kernel(const float* __restrict__ S, __half* __restrict__ Ph)
{
    __shared__ float buf[KSEQ];
    __shared__ float red[8];
    const float* p = S + (size_t)blockIdx.x * KSEQ;
    const int t = threadIdx.x, lane = t & 31, wid = t >> 5;

    float mx = -3.4e38f;
    #pragma unroll
    for (int i = t; i < KSEQ; i += 256) { float v = p[i]; buf[i] = v; mx = fmaxf(mx, v); }
    #pragma unroll
    for (int o = 16; o > 0; o >>= 1) mx = fmaxf(mx, __shfl_xor_sync(0xffffffffu, mx, o));
    if (lane == 0) red[wid] = mx;
    __syncthreads();
    mx = fmaxf(fmaxf(fmaxf(red[0], red[1]), fmaxf(red[2], red[3])),
               fmaxf(fmaxf(red[4], red[5]), fmaxf(red[6], red[7])));
    __syncthreads();

    float sum = 0.0f;
    #pragma unroll
    for (int i = t; i < KSEQ; i += 256) { float e = __expf(buf[i] - mx); buf[i] = e; sum += e; }
    #pragma unroll
    for (int o = 16; o > 0; o >>= 1) sum += __shfl_xor_sync(0xffffffffu, sum, o);
    if (lane == 0) red[wid] = sum;
    __syncthreads();
    sum = ((red[0] + red[1]) + (red[2] + red[3])) + ((red[4] + red[5]) + (red[6] + red[7]));
    const float inv = 1.0f / sum;

    __half* ph = Ph + (size_t)blockIdx.x * KSEQ;
    #pragma unroll
    for (int j = t; j < KSEQ / 2; j += 256) {
        float e0 = buf[2*j]     * inv;
        float e1 = buf[2*j + 1] * inv;
        *reinterpret_cast<uint32_t*>(ph + 2*j) =
            pack2h(__float2half(e0), __float2half(e1));
    }
}

// ---------------- launch ----------------
extern "C" void kernel_launch(void* const* d_in, const int* in_sizes, int n_in,
                              void* d_out, int out_size)
{
    (void)in_sizes; (void)n_in; (void)out_size;
    const float* Qin  = (const float*)d_in[0];
    const float* Kin  = (const float*)d_in[1];
    const float* Vin  = (const float*)d_in[2];
    const float* mask = (const float*)d_in[3];
    const float* Wq   = (const float*)d_in[4];
    const float* bq   = (const float*)d_in[5];
    const float* Wk   = (const float*)d_in[6];
    const float* bk   = (const float*)d_in[7];
    const float* Wv   = (const float*)d_in[8];
    const float* bv   = (const float*)d_in[9];
    float* out = (float*)d_out;

    float *v, *s;
    __half *inh, *inl, *wh, *wl, *qh, *ql, *kh, *vt, *ph;
    cudaGetSymbolAddress((void**)&inh, g_inh);
    cudaGetSymbolAddress((void**)&inl, g_inl);
    cudaGetSymbolAddress((void**)&wh,  g_wh);
    cudaGetSymbolAddress((void**)&wl,  g_wl);
    cudaGetSymbolAddress((void**)&qh,  g_qh);
    cudaGetSymbolAddress((void**)&ql,  g_ql);
    cudaGetSymbolAddress((void**)&kh,  g_kh);
    cudaGetSymbolAddress((void**)&v,   g_v);
    cudaGetSymbolAddress((void**)&vt,  g_vt);
    cudaGetSymbolAddress((void**)&s,   g_s);
    cudaGetSymbolAddress((void**)&ph,  g_ph);

    constexpr int SM3T = 2 * 4 * T_B;   // TERMS=3, 2 stages: 81920
    constexpr int SM2T = 3 * 3 * T_B;   // TERMS=2, 3 stages: 92160
    constexpr int SM1T = 4 * 2 * T_B;   // TERMS=1, 4 stages: 81920
    cudaFuncSetAttribute(gemm_hmma<3,3,2>, cudaFuncAttributeMaxDynamicSharedMemorySize, SM3T);
    cudaFuncSetAttribute(gemm_hmma<4,3,2>, cudaFuncAttributeMaxDynamicSharedMemorySize, SM3T);
    cudaFuncSetAttribute(gemm_hmma<0,3,2>, cudaFuncAttributeMaxDynamicSharedMemorySize, SM3T);
    cudaFuncSetAttribute(gemm_hmma<1,2,3>, cudaFuncAttributeMaxDynamicSharedMemorySize, SM2T);
    cudaFuncSetAttribute(gemm_hmma<2,1,4>, cudaFuncAttributeMaxDynamicSharedMemorySize, SM1T);

    const size_t ISZ = (size_t)KROWS * KDIM;
    const size_t WSZ = (size_t)KDIM * KDIM;
    dim3 tb(256);

    // 1-2) preprocessing
    split_inputs<<<dim3((int)(ISZ / 4 / 256), 1, 3), tb>>>(Qin, Kin, Vin, inh, inl);
    wtrans<<<dim3(16, 16, 3), tb>>>(Wq, Wk, Wv, wh, wl);

    // 3-5) projections: TERMS=3, M=16384, N=512, K=512
    dim3 gp(KDIM / TILE_N, KROWS / TILE_M, 1);
    gemm_hmma<3,3,2><<<gp, GT, SM3T>>>(inh + 0*ISZ, inl + 0*ISZ, wh + 0*WSZ, wl + 0*WSZ,
                                       bq, nullptr, qh, ql, KDIM, KDIM, 0, 0, 0, 0);
    gemm_hmma<4,3,2><<<gp, GT, SM3T>>>(inh + 1*ISZ, inl + 1*ISZ, wh + 1*WSZ, wl + 1*WSZ,
                                       bk, nullptr, kh, nullptr, KDIM, KDIM, 0, 0, 0, 0);
    gemm_hmma<0,3,2><<<gp, GT, SM3T>>>(inh + 2*ISZ, inl + 2*ISZ, wh + 2*WSZ, wl + 2*WSZ,
                                       bv, v, nullptr, nullptr, KDIM, KDIM, 0, 0, 0, 0);

    // 6) scores = q_s k_s^T * scale + mask  (TERMS=2; ncu capture target)
    dim3 gs(KSEQ / TILE_N, KSEQ / TILE_M, KBATCH);
    gemm_hmma<1,2,3><<<gs, GT, SM2T>>>(qh, ql, kh, nullptr, mask, s, nullptr, nullptr,
                                       KSEQ, KDIM,
                                       (size_t)KSEQ * KDIM, (size_t)KSEQ * KDIM,
                                       (size_t)KSEQ * KSEQ, (size_t)KSEQ * KSEQ);

    // 7) v_s -> v_s^T single fp16
    vtrans<<<dim3(KDIM / 32, KSEQ / 32, KBATCH), tb>>>(v, vt);

    // 8) softmax -> single fp16 probs
    softmax_kernel<<<KROWS, 256>>>(s, ph);

    // 9) out = probs @ v_s : TERMS=1 (single fp16 probs)
    dim3 ga(KDIM / TILE_N, KSEQ / TILE_M, KBATCH);
    gemm_hmma<2,1,4><<<ga, GT, SM1T>>>(ph, nullptr, vt, nullptr, nullptr, out, nullptr, nullptr,
                                       KDIM, KSEQ,
                                       (size_t)KSEQ * KSEQ, (size_t)KDIM * KSEQ,
                                       (size_t)KSEQ * KDIM, 0);
}

// round 11
// speedup vs baseline: 1.8904x; 1.0690x over previous
#include <cuda_runtime.h>
#include <cuda_fp16.h>
#include <cstdint>
#include <math.h>

// ---------------- problem constants ----------------
#define KBATCH 8
#define KSEQ   2048
#define KDIM   512
#define KROWS  (KBATCH*KSEQ)   // 16384

// ---------------- scratch (device globals; no allocations) ----------------
__device__ __half  g_inh[3][(size_t)KROWS * KDIM];   // split Q,K,V inputs (hi)
__device__ __half  g_inl[3][(size_t)KROWS * KDIM];   // (lo)
__device__ __half  g_wh [3][(size_t)KDIM * KDIM];    // W^T hi [e][d] = [N,K]
__device__ __half  g_wl [3][(size_t)KDIM * KDIM];
__device__ __half  g_qh [(size_t)KROWS * KDIM];      // q_s split [M,K]
__device__ __half  g_ql [(size_t)KROWS * KDIM];
__device__ __half  g_kh [(size_t)KROWS * KDIM];      // k_s single fp16 [N,K]
__device__ float   g_v  [(size_t)KROWS * KDIM];      // v_s fp32
__device__ __half  g_vt [(size_t)KBATCH * KDIM * KSEQ]; // v_s^T single fp16 [B][D][S]
__device__ float   g_s  [(size_t)KBATCH * KSEQ * KSEQ]; // scores f32
__device__ __half  g_ph [(size_t)KBATCH * KSEQ * KSEQ]; // probs single fp16

// ---------------- helpers ----------------
__device__ __forceinline__ uint32_t smem_u32(const void* p) {
    uint32_t a;
    asm("{ .reg .u64 t; cvta.to.shared.u64 t, %1; cvt.u32.u64 %0, t; }" : "=r"(a) : "l"(p));
    return a;
}
__device__ __forceinline__ void split_h(float x, __half& h, __half& l) {
    h = __float2half(x);
    l = __float2half(x - __half2float(h));
}
__device__ __forceinline__ uint32_t pack2h(__half a, __half b) {
    return (uint32_t)__half_as_ushort(a) | ((uint32_t)__half_as_ushort(b) << 16);
}
__device__ __forceinline__ void ldmx4(uint32_t& r0, uint32_t& r1, uint32_t& r2, uint32_t& r3,
                                      uint32_t addr) {
    asm volatile("ldmatrix.sync.aligned.m8n8.x4.shared.b16 {%0,%1,%2,%3}, [%4];"
                 : "=r"(r0), "=r"(r1), "=r"(r2), "=r"(r3) : "r"(addr));
}
__device__ __forceinline__ void mma_f16(float* c, const uint32_t* a, uint32_t b0, uint32_t b1) {
    asm volatile("mma.sync.aligned.m16n8k16.row.col.f32.f16.f16.f32 "
                 "{%0,%1,%2,%3}, {%4,%5,%6,%7}, {%8,%9}, {%0,%1,%2,%3};"
                 : "+f"(c[0]), "+f"(c[1]), "+f"(c[2]), "+f"(c[3])
                 : "r"(a[0]), "r"(a[1]), "r"(a[2]), "r"(a[3]), "r"(b0), "r"(b1));
}
#define CP16(dst, src) \
    asm volatile("cp.async.cg.shared.global [%0], [%1], 16;" :: "r"(dst), "l"(src))
#define CP_COMMIT() asm volatile("cp.async.commit_group;" ::: "memory")

__device__ __forceinline__ float ssc() { return 0.044194173824159216f; } // 1/sqrt(512)

// ---------------- HMMA GEMM: 128 threads, CTA 128x128, warp tile 64x64 ----------------
// 2 CTAs per SM.  TERMS=3: AhBh+AlBh+AhBl.  TERMS=2: AhBh+AlBh.  TERMS=1: AhBh only.
// EPI 0: +bias -> f32    EPI 1: *scale + mask -> f32    EPI 2: plain -> f32
// EPI 3: +bias -> split fp16 (Ch, Cl)    EPI 4: +bias -> single fp16 (Ch)
#define TILE_M 128
#define TILE_N 128
#define TILE_K 32
#define GT 128
#define PSTR 40                     // padded smem row stride (halves) -> 80 B/row
#define T_B (128 * PSTR * 2)        // 10240 bytes per 128x32 fp16 tile

template<int EPI, int TERMS, int NST>
__global__ __launch_bounds__(GT, 2)
void gemm_hmma(const __half* __restrict__ Ah,
               const __half* __restrict__ Al,
               const __half* __restrict__ Bh,
               const __half* __restrict__ Bl,
               const float* __restrict__ aux,
               float* __restrict__ C,
               __half* __restrict__ Ch,
               __half* __restrict__ Cl,
               int N, int K,
               size_t sA, size_t sB, size_t sC, size_t sAux)
{
    constexpr bool HAS_AL = (TERMS >= 2);
    constexpr bool HAS_BL = (TERMS == 3);
    constexpr int  NTILE  = 1 + (HAS_AL ? 1 : 0) + 1 + (HAS_BL ? 1 : 0);
    constexpr int  STB    = NTILE * T_B;

    extern __shared__ char sm[];
    const uint32_t sb = smem_u32(sm);

    Ah  += sA   * (size_t)blockIdx.z;
    if (HAS_AL) Al += sA * (size_t)blockIdx.z;
    Bh  += sB   * (size_t)blockIdx.z;
    if (HAS_BL) Bl += sB * (size_t)blockIdx.z;
    C   += sC   * (size_t)blockIdx.z;
    Ch  += sC   * (size_t)blockIdx.z;
    Cl  += sC   * (size_t)blockIdx.z;
    aux += sAux * (size_t)blockIdx.z;

    const int t    = threadIdx.x;
    const int lane = t & 31;
    const int w    = t >> 5;        // 0..3
    const int wm   = w & 1;         // warp row (2) -> M offset 64*wm
    const int wn   = w >> 1;        // warp col (2) -> N offset 64*wn
    const int bm   = blockIdx.y * TILE_M;
    const int bn   = blockIdx.x * TILE_N;

    const int cr = t >> 2;          // 0..31
    const int cc = t & 3;           // 16B chunk within 64B row

    const int a_r  = wm * 64 + (lane & 15);
    const int a_c8 = (lane >> 4) * 8;
    const int b_r  = wn * 64 + (lane & 7) + ((lane >> 4) & 1) * 8;
    const int b_c8 = ((lane >> 3) & 1) * 8;

    float acc[4][8][4];
    #pragma unroll
    for (int i = 0; i < 4; ++i)
        #pragma unroll
        for (int j = 0; j < 8; ++j)
            #pragma unroll
            for (int e = 0; e < 4; ++e) acc[i][j][e] = 0.0f;

    const int nch = K / TILE_K;

    // smem tile offsets within a stage
    constexpr int OAH = 0;
    constexpr int OAL = T_B;                                 // valid if HAS_AL
    constexpr int OBH = (HAS_AL ? 2 : 1) * T_B;
    constexpr int OBL = OBH + T_B;                           // valid if HAS_BL

    auto issue = [&](int j, int s) {
        const size_t kco = (size_t)j * TILE_K + cc * 8;
        const uint32_t base = sb + (uint32_t)(s * STB);
        #pragma unroll
        for (int p = 0; p < 4; ++p) {
            const int row = cr + p * 32;
            const uint32_t doff = (uint32_t)(row * (PSTR * 2) + cc * 16);
            const size_t ga = (size_t)(bm + row) * K + kco;
            const size_t gb = (size_t)(bn + row) * K + kco;
            CP16(base + OAH + doff, Ah + ga);
            if (HAS_AL) CP16(base + OAL + doff, Al + ga);
            CP16(base + OBH + doff, Bh + gb);
            if (HAS_BL) CP16(base + OBL + doff, Bl + gb);
        }
    };

    // prologue: stages 0..NST-2 in flight
    #pragma unroll
    for (int j = 0; j < NST - 1; ++j) {
        if (j < nch) issue(j, j);
        CP_COMMIT();
    }

    // canonical multistage: ONE sync per chunk.
    // wait(stage i ready) -> sync (all reads of slot (i-1) done) ->
    // issue slot (i+NST-1)%NST == (i-1)%NST -> compute slot i
    for (int i = 0; i < nch; ++i) {
        asm volatile("cp.async.wait_group %0;" :: "n"(NST - 2 >= 0 ? NST - 2 : 0) : "memory");
        __syncthreads();

        const int jn = i + NST - 1;
        if (jn < nch) { issue(jn, jn % NST); }
        CP_COMMIT();

        const int s = i % NST;
        const uint32_t sAH = sb + (uint32_t)(s * STB) + OAH;
        const uint32_t sAL = sb + (uint32_t)(s * STB) + OAL;
        const uint32_t sBH = sb + (uint32_t)(s * STB) + OBH;
        const uint32_t sBL = sb + (uint32_t)(s * STB) + OBL;

        #pragma unroll
        for (int h = 0; h < 2; ++h) {
            const uint32_t bcol = (uint32_t)((h * 16 + b_c8) * 2);
            uint32_t bh[4][4], bl[4][4];
            #pragma unroll
            for (int np = 0; np < 4; ++np) {
                const uint32_t boff = (uint32_t)((b_r + np * 16) * (PSTR * 2)) + bcol;
                ldmx4(bh[np][0], bh[np][1], bh[np][2], bh[np][3], sBH + boff);
                if (HAS_BL)
                    ldmx4(bl[np][0], bl[np][1], bl[np][2], bl[np][3], sBL + boff);
            }
            const uint32_t acol = (uint32_t)((h * 16 + a_c8) * 2);
            #pragma unroll
            for (int mp = 0; mp < 2; ++mp) {
                uint32_t ahr[2][4], alr[2][4];
                #pragma unroll
                for (int m2 = 0; m2 < 2; ++m2) {
                    const uint32_t aoff =
                        (uint32_t)((a_r + (mp * 2 + m2) * 16) * (PSTR * 2)) + acol;
                    ldmx4(ahr[m2][0], ahr[m2][1], ahr[m2][2], ahr[m2][3], sAH + aoff);
                    if (HAS_AL)
                        ldmx4(alr[m2][0], alr[m2][1], alr[m2][2], alr[m2][3], sAL + aoff);
                }
                // term 1: Ah * Bh
                #pragma unroll
                for (int np = 0; np < 4; ++np)
                    #pragma unroll
                    for (int m2 = 0; m2 < 2; ++m2) {
                        mma_f16(acc[mp*2+m2][2*np],   ahr[m2], bh[np][0], bh[np][1]);
                        mma_f16(acc[mp*2+m2][2*np+1], ahr[m2], bh[np][2], bh[np][3]);
                    }
                // term 2: Al * Bh
                if (HAS_AL) {
                    #pragma unroll
                    for (int np = 0; np < 4; ++np)
                        #pragma unroll
                        for (int m2 = 0; m2 < 2; ++m2) {
                            mma_f16(acc[mp*2+m2][2*np],   alr[m2], bh[np][0], bh[np][1]);
                            mma_f16(acc[mp*2+m2][2*np+1], alr[m2], bh[np][2], bh[np][3]);
                        }
                }
                // term 3: Ah * Bl
                if (HAS_BL) {
                    #pragma unroll
                    for (int np = 0; np < 4; ++np)
                        #pragma unroll
                        for (int m2 = 0; m2 < 2; ++m2) {
                            mma_f16(acc[mp*2+m2][2*np],   ahr[m2], bl[np][0], bl[np][1]);
                            mma_f16(acc[mp*2+m2][2*np+1], ahr[m2], bl[np][2], bl[np][3]);
                        }
                }
            }
        }
    }

    // ---------------- epilogue ----------------
    const int er = (lane >> 2);
    const int ec = (lane & 3) * 2;
    #pragma unroll
    for (int mt = 0; mt < 4; ++mt) {
        #pragma unroll
        for (int nt = 0; nt < 8; ++nt) {
            const int col = bn + wn * 64 + nt * 8 + ec;
            #pragma unroll
            for (int half = 0; half < 2; ++half) {
                const int row = bm + wm * 64 + mt * 16 + er + half * 8;
                float x0 = acc[mt][nt][2*half + 0];
                float x1 = acc[mt][nt][2*half + 1];
                if (EPI == 0 || EPI == 3 || EPI == 4) {
                    x0 += aux[col];
                    x1 += aux[col + 1];
                }
                if (EPI == 1) {
                    const float2 m2 = *reinterpret_cast<const float2*>(&aux[(size_t)row * N + col]);
                    x0 = fmaf(x0, ssc(), m2.x);
                    x1 = fmaf(x1, ssc(), m2.y);
                }
                const size_t o = (size_t)row * N + col;
                if (EPI == 3) {
                    __half h0,h1,l0,l1;
                    split_h(x0, h0, l0);
                    split_h(x1, h1, l1);
                    *reinterpret_cast<uint32_t*>(&Ch[o]) = pack2h(h0, h1);
                    *reinterpret_cast<uint32_t*>(&Cl[o]) = pack2h(l0, l1);
                } else if (EPI == 4) {
                    *reinterpret_cast<uint32_t*>(&Ch[o]) =
                        pack2h(__float2half(x0), __float2half(x1));
                } else {
                    *reinterpret_cast<float2*>(&C[o]) = make_float2(x0, x1);
                }
            }
        }
    }
}

// ---------------- fused input split: 3 tensors -> fp16 hi/lo ----------------
__global__ __launch_bounds__(256)
void split_inputs(const float* __restrict__ q, const float* __restrict__ k,
                  const float* __restrict__ v,
                  __half* __restrict__ dh, __half* __restrict__ dl)
{
    const size_t ISZ = (size_t)KROWS * KDIM;
    const float* src = (blockIdx.z == 0) ? q : (blockIdx.z == 1) ? k : v;
    __half* oh = dh + blockIdx.z * ISZ;
    __half* ol = dl + blockIdx.z * ISZ;
    const size_t i = ((size_t)blockIdx.x * 256 + threadIdx.x) * 4;
    float4 x = *reinterpret_cast<const float4*>(src + i);
    __half h0,h1,h2,h3,l0,l1,l2,l3;
    split_h(x.x, h0, l0); split_h(x.y, h1, l1);
    split_h(x.z, h2, l2); split_h(x.w, h3, l3);
    *reinterpret_cast<uint2*>(oh + i) = make_uint2(pack2h(h0,h1), pack2h(h2,h3));
    *reinterpret_cast<uint2*>(ol + i) = make_uint2(pack2h(l0,l1), pack2h(l2,l3));
}

// ---------------- fused weight transpose+split ----------------
__global__ __launch_bounds__(256)
void wtrans(const float* __restrict__ wq, const float* __restrict__ wk,
            const float* __restrict__ wv,
            __half* __restrict__ dh, __half* __restrict__ dl)
{
    __shared__ float tile[32][33];
    const size_t WSZ = (size_t)KDIM * KDIM;
    const float* src = (blockIdx.z == 0) ? wq : (blockIdx.z == 1) ? wk : wv;
    __half* oh = dh + blockIdx.z * WSZ;
    __half* ol = dl + blockIdx.z * WSZ;
    const int bx = blockIdx.x * 32;
    const int by = blockIdx.y * 32;
    const int tx = threadIdx.x & 31;
    const int ty = threadIdx.x >> 5;
    #pragma unroll
    for (int i = 0; i < 32; i += 8)
        tile[ty + i][tx] = src[(size_t)(by + ty + i) * KDIM + bx + tx];
    __syncthreads();
    #pragma unroll
    for (int i = 0; i < 32; i += 8) {
        float x = tile[tx][ty + i];
        __half h, l;
        split_h(x, h, l);
        size_t o = (size_t)(bx + ty + i) * KDIM + by + tx;
        oh[o] = h; ol[o] = l;
    }
}

// ---------------- v transpose: f32 [B][S][D] -> single fp16 [B][D][S] ----------------
__global__ __launch_bounds__(256)
void vtrans(const float* __restrict__ src, __half* __restrict__ dst)
{
    __shared__ float tile[32][33];
    src += (size_t)KSEQ * KDIM * blockIdx.z;
    dst += (size_t)KDIM * KSEQ * blockIdx.z;
    const int bx = blockIdx.x * 32;   // D
    const int by = blockIdx.y * 32;   // S
    const int tx = threadIdx.x & 31;
    const int ty = threadIdx.x >> 5;
    #pragma unroll
    for (int i = 0; i < 32; i += 8)
        tile[ty + i][tx] = src[(size_t)(by + ty + i) * KDIM + bx + tx];
    __syncthreads();
    #pragma unroll
    for (int i = 0; i < 32; i += 8)
        dst[(size_t)(bx + ty + i) * KSEQ + by + tx] = __float2half(tile[tx][ty + i]);
}

// ---------------- row softmax over 2048, emits single fp16 probs ----------------
__global__ __launch_bounds__(256)
void softmax_kernel(const float* __restrict__ S, __half* __restrict__ Ph)
{
    __shared__ float buf[KSEQ];
    __shared__ float red[8];
    const float* p = S + (size_t)blockIdx.x * KSEQ;
    const int t = threadIdx.x, lane = t & 31, wid = t >> 5;

    float mx = -3.4e38f;
    #pragma unroll
    for (int i = t; i < KSEQ; i += 256) { float v = p[i]; buf[i] = v; mx = fmaxf(mx, v); }
    #pragma unroll
    for (int o = 16; o > 0; o >>= 1) mx = fmaxf(mx, __shfl_xor_sync(0xffffffffu, mx, o));
    if (lane == 0) red[wid] = mx;
    __syncthreads();
    mx = fmaxf(fmaxf(fmaxf(red[0], red[1]), fmaxf(red[2], red[3])),
               fmaxf(fmaxf(red[4], red[5]), fmaxf(red[6], red[7])));
    __syncthreads();

    float sum = 0.0f;
    #pragma unroll
    for (int i = t; i < KSEQ; i += 256) { float e = __expf(buf[i] - mx); buf[i] = e; sum += e; }
    #pragma unroll
    for (int o = 16; o > 0; o >>= 1) sum += __shfl_xor_sync(0xffffffffu, sum, o);
    if (lane == 0) red[wid] = sum;
    __syncthreads();
    sum = ((red[0] + red[1]) + (red[2] + red[3])) + ((red[4] + red[5]) + (red[6] + red[7]));
    const float inv = 1.0f / sum;

    __half* ph = Ph + (size_t)blockIdx.x * KSEQ;
    #pragma unroll
    for (int j = t; j < KSEQ / 2; j += 256) {
        float e0 = buf[2*j]     * inv;
        float e1 = buf[2*j + 1] * inv;
        *reinterpret_cast<uint32_t*>(ph + 2*j) =
            pack2h(__float2half(e0), __float2half(e1));
    }
}

// ---------------- launch ----------------
extern "C" void kernel_launch(void* const* d_in, const int* in_sizes, int n_in,
                              void* d_out, int out_size)
{
    (void)in_sizes; (void)n_in; (void)out_size;
    const float* Qin  = (const float*)d_in[0];
    const float* Kin  = (const float*)d_in[1];
    const float* Vin  = (const float*)d_in[2];
    const float* mask = (const float*)d_in[3];
    const float* Wq   = (const float*)d_in[4];
    const float* bq   = (const float*)d_in[5];
    const float* Wk   = (const float*)d_in[6];
    const float* bk   = (const float*)d_in[7];
    const float* Wv   = (const float*)d_in[8];
    const float* bv   = (const float*)d_in[9];
    float* out = (float*)d_out;

    float *v, *s;
    __half *inh, *inl, *wh, *wl, *qh, *ql, *kh, *vt, *ph;
    cudaGetSymbolAddress((void**)&inh, g_inh);
    cudaGetSymbolAddress((void**)&inl, g_inl);
    cudaGetSymbolAddress((void**)&wh,  g_wh);
    cudaGetSymbolAddress((void**)&wl,  g_wl);
    cudaGetSymbolAddress((void**)&qh,  g_qh);
    cudaGetSymbolAddress((void**)&ql,  g_ql);
    cudaGetSymbolAddress((void**)&kh,  g_kh);
    cudaGetSymbolAddress((void**)&v,   g_v);
    cudaGetSymbolAddress((void**)&vt,  g_vt);
    cudaGetSymbolAddress((void**)&s,   g_s);
    cudaGetSymbolAddress((void**)&ph,  g_ph);

    constexpr int SM3T = 2 * 4 * T_B;   // TERMS=3, 2 stages: 81920
    constexpr int SM2T = 3 * 3 * T_B;   // TERMS=2, 3 stages: 92160
    constexpr int SM1T = 4 * 2 * T_B;   // TERMS=1, 4 stages: 81920
    cudaFuncSetAttribute(gemm_hmma<3,3,2>, cudaFuncAttributeMaxDynamicSharedMemorySize, SM3T);
    cudaFuncSetAttribute(gemm_hmma<4,2,3>, cudaFuncAttributeMaxDynamicSharedMemorySize, SM2T);
    cudaFuncSetAttribute(gemm_hmma<0,2,3>, cudaFuncAttributeMaxDynamicSharedMemorySize, SM2T);
    cudaFuncSetAttribute(gemm_hmma<1,2,3>, cudaFuncAttributeMaxDynamicSharedMemorySize, SM2T);
    cudaFuncSetAttribute(gemm_hmma<2,1,4>, cudaFuncAttributeMaxDynamicSharedMemorySize, SM1T);

    const size_t ISZ = (size_t)KROWS * KDIM;
    const size_t WSZ = (size_t)KDIM * KDIM;
    dim3 tb(256);

    // 1-2) preprocessing
    split_inputs<<<dim3((int)(ISZ / 4 / 256), 1, 3), tb>>>(Qin, Kin, Vin, inh, inl);
    wtrans<<<dim3(16, 16, 3), tb>>>(Wq, Wk, Wv, wh, wl);

    // 3) Q projection: TERMS=3 (split fp16 output, consumed at full precision)
    dim3 gp(KDIM / TILE_N, KROWS / TILE_M, 1);
    gemm_hmma<3,3,2><<<gp, GT, SM3T>>>(inh + 0*ISZ, inl + 0*ISZ, wh + 0*WSZ, wl + 0*WSZ,
                                       bq, nullptr, qh, ql, KDIM, KDIM, 0, 0, 0, 0);
    // 4) K projection: TERMS=2 (output rounds to single fp16 anyway)
    gemm_hmma<4,2,3><<<gp, GT, SM2T>>>(inh + 1*ISZ, inl + 1*ISZ, wh + 1*WSZ, nullptr,
                                       bk, nullptr, kh, nullptr, KDIM, KDIM, 0, 0, 0, 0);
    // 5) V projection: TERMS=2 (output rounds to single fp16 in vtrans)
    gemm_hmma<0,2,3><<<gp, GT, SM2T>>>(inh + 2*ISZ, inl + 2*ISZ, wh + 2*WSZ, nullptr,
                                       bv, v, nullptr, nullptr, KDIM, KDIM, 0, 0, 0, 0);

    // 6) scores = q_s k_s^T * scale + mask  (TERMS=2; ncu capture target)
    dim3 gs(KSEQ / TILE_N, KSEQ / TILE_M, KBATCH);
    gemm_hmma<1,2,3><<<gs, GT, SM2T>>>(qh, ql, kh, nullptr, mask, s, nullptr, nullptr,
                                       KSEQ, KDIM,
                                       (size_t)KSEQ * KDIM, (size_t)KSEQ * KDIM,
                                       (size_t)KSEQ * KSEQ, (size_t)KSEQ * KSEQ);

    // 7) v_s -> v_s^T single fp16
    vtrans<<<dim3(KDIM / 32, KSEQ / 32, KBATCH), tb>>>(v, vt);

    // 8) softmax -> single fp16 probs
    softmax_kernel<<<KROWS, 256>>>(s, ph);

    // 9) out = probs @ v_s : TERMS=1
    dim3 ga(KDIM / TILE_N, KSEQ / TILE_M, KBATCH);
    gemm_hmma<2,1,4><<<ga, GT, SM1T>>>(ph, nullptr, vt, nullptr, nullptr, out, nullptr, nullptr,
                                       KDIM, KSEQ,
                                       (size_t)KSEQ * KSEQ, (size_t)KDIM * KSEQ,
                                       (size_t)KSEQ * KDIM, 0);
}

// round 12
// speedup vs baseline: 2.2745x; 1.2032x over previous
#include <cuda_runtime.h>
#include <cuda_fp16.h>
#include <cstdint>
#include <math.h>

// ---------------- problem constants ----------------
#define KBATCH 8
#define KSEQ   2048
#define KDIM   512
#define KROWS  (KBATCH*KSEQ)   // 16384

// ---------------- scratch (device globals; no allocations) ----------------
__device__ __half  g_inh[3][(size_t)KROWS * KDIM];   // split Q,K,V inputs (hi)
__device__ __half  g_inl[3][(size_t)KROWS * KDIM];   // (lo)
__device__ __half  g_wh [3][(size_t)KDIM * KDIM];    // W^T hi [e][d] = [N,K]
__device__ __half  g_wl [3][(size_t)KDIM * KDIM];
__device__ __half  g_qh [(size_t)KROWS * KDIM];      // q_s single fp16 [M,K]
__device__ __half  g_kh [(size_t)KROWS * KDIM];      // k_s single fp16 [N,K]
__device__ float   g_v  [(size_t)KROWS * KDIM];      // v_s fp32
__device__ __half  g_vt [(size_t)KBATCH * KDIM * KSEQ]; // v_s^T single fp16 [B][D][S]
__device__ float   g_s  [(size_t)KBATCH * KSEQ * KSEQ]; // scores f32
__device__ __half  g_ph [(size_t)KBATCH * KSEQ * KSEQ]; // probs single fp16

// ---------------- helpers ----------------
__device__ __forceinline__ uint32_t smem_u32(const void* p) {
    uint32_t a;
    asm("{ .reg .u64 t; cvta.to.shared.u64 t, %1; cvt.u32.u64 %0, t; }" : "=r"(a) : "l"(p));
    return a;
}
__device__ __forceinline__ void split_h(float x, __half& h, __half& l) {
    h = __float2half(x);
    l = __float2half(x - __half2float(h));
}
__device__ __forceinline__ uint32_t pack2h(__half a, __half b) {
    return (uint32_t)__half_as_ushort(a) | ((uint32_t)__half_as_ushort(b) << 16);
}
__device__ __forceinline__ void ldmx4(uint32_t& r0, uint32_t& r1, uint32_t& r2, uint32_t& r3,
                                      uint32_t addr) {
    asm volatile("ldmatrix.sync.aligned.m8n8.x4.shared.b16 {%0,%1,%2,%3}, [%4];"
                 : "=r"(r0), "=r"(r1), "=r"(r2), "=r"(r3) : "r"(addr));
}
__device__ __forceinline__ void mma_f16(float* c, const uint32_t* a, uint32_t b0, uint32_t b1) {
    asm volatile("mma.sync.aligned.m16n8k16.row.col.f32.f16.f16.f32 "
                 "{%0,%1,%2,%3}, {%4,%5,%6,%7}, {%8,%9}, {%0,%1,%2,%3};"
                 : "+f"(c[0]), "+f"(c[1]), "+f"(c[2]), "+f"(c[3])
                 : "r"(a[0]), "r"(a[1]), "r"(a[2]), "r"(a[3]), "r"(b0), "r"(b1));
}
#define CP16(dst, src) \
    asm volatile("cp.async.cg.shared.global [%0], [%1], 16;" :: "r"(dst), "l"(src))
#define CP_COMMIT() asm volatile("cp.async.commit_group;" ::: "memory")

__device__ __forceinline__ float ssc() { return 0.044194173824159216f; } // 1/sqrt(512)

// ---------------- HMMA GEMM: 128 threads, CTA 128x128, warp tile 64x64 ----------------
// 2 CTAs per SM.  TERMS=3: AhBh+AlBh+AhBl.  TERMS=2: AhBh+AlBh.  TERMS=1: AhBh only.
// EPI 0: +bias -> f32    EPI 1: *scale + mask -> f32    EPI 2: plain -> f32
// EPI 3: +bias -> split fp16 (Ch, Cl)    EPI 4: +bias -> single fp16 (Ch)
#define TILE_M 128
#define TILE_N 128
#define TILE_K 32
#define GT 128
#define PSTR 40                     // padded smem row stride (halves) -> 80 B/row
#define T_B (128 * PSTR * 2)        // 10240 bytes per 128x32 fp16 tile

template<int EPI, int TERMS, int NST>
__global__ __launch_bounds__(GT, 2)
void gemm_hmma(const __half* __restrict__ Ah,
               const __half* __restrict__ Al,
               const __half* __restrict__ Bh,
               const __half* __restrict__ Bl,
               const float* __restrict__ aux,
               float* __restrict__ C,
               __half* __restrict__ Ch,
               __half* __restrict__ Cl,
               int N, int K,
               size_t sA, size_t sB, size_t sC, size_t sAux)
{
    constexpr bool HAS_AL = (TERMS >= 2);
    constexpr bool HAS_BL = (TERMS == 3);
    constexpr int  NTILE  = 1 + (HAS_AL ? 1 : 0) + 1 + (HAS_BL ? 1 : 0);
    constexpr int  STB    = NTILE * T_B;

    extern __shared__ char sm[];
    const uint32_t sb = smem_u32(sm);

    Ah  += sA   * (size_t)blockIdx.z;
    if (HAS_AL) Al += sA * (size_t)blockIdx.z;
    Bh  += sB   * (size_t)blockIdx.z;
    if (HAS_BL) Bl += sB * (size_t)blockIdx.z;
    C   += sC   * (size_t)blockIdx.z;
    Ch  += sC   * (size_t)blockIdx.z;
    Cl  += sC   * (size_t)blockIdx.z;
    aux += sAux * (size_t)blockIdx.z;

    const int t    = threadIdx.x;
    const int lane = t & 31;
    const int w    = t >> 5;        // 0..3
    const int wm   = w & 1;         // warp row (2) -> M offset 64*wm
    const int wn   = w >> 1;        // warp col (2) -> N offset 64*wn
    const int bm   = blockIdx.y * TILE_M;
    const int bn   = blockIdx.x * TILE_N;

    const int cr = t >> 2;          // 0..31
    const int cc = t & 3;           // 16B chunk within 64B row

    const int a_r  = wm * 64 + (lane & 15);
    const int a_c8 = (lane >> 4) * 8;
    const int b_r  = wn * 64 + (lane & 7) + ((lane >> 4) & 1) * 8;
    const int b_c8 = ((lane >> 3) & 1) * 8;

    float acc[4][8][4];
    #pragma unroll
    for (int i = 0; i < 4; ++i)
        #pragma unroll
        for (int j = 0; j < 8; ++j)
            #pragma unroll
            for (int e = 0; e < 4; ++e) acc[i][j][e] = 0.0f;

    const int nch = K / TILE_K;

    // smem tile offsets within a stage
    constexpr int OAH = 0;
    constexpr int OAL = T_B;                                 // valid if HAS_AL
    constexpr int OBH = (HAS_AL ? 2 : 1) * T_B;
    constexpr int OBL = OBH + T_B;                           // valid if HAS_BL

    auto issue = [&](int j, int s) {
        const size_t kco = (size_t)j * TILE_K + cc * 8;
        const uint32_t base = sb + (uint32_t)(s * STB);
        #pragma unroll
        for (int p = 0; p < 4; ++p) {
            const int row = cr + p * 32;
            const uint32_t doff = (uint32_t)(row * (PSTR * 2) + cc * 16);
            const size_t ga = (size_t)(bm + row) * K + kco;
            const size_t gb = (size_t)(bn + row) * K + kco;
            CP16(base + OAH + doff, Ah + ga);
            if (HAS_AL) CP16(base + OAL + doff, Al + ga);
            CP16(base + OBH + doff, Bh + gb);
            if (HAS_BL) CP16(base + OBL + doff, Bl + gb);
        }
    };

    // prologue: stages 0..NST-2 in flight
    #pragma unroll
    for (int j = 0; j < NST - 1; ++j) {
        if (j < nch) issue(j, j);
        CP_COMMIT();
    }

    // canonical multistage: ONE sync per chunk.
    for (int i = 0; i < nch; ++i) {
        asm volatile("cp.async.wait_group %0;" :: "n"(NST - 2 >= 0 ? NST - 2 : 0) : "memory");
        __syncthreads();

        const int jn = i + NST - 1;
        if (jn < nch) { issue(jn, jn % NST); }
        CP_COMMIT();

        const int s = i % NST;
        const uint32_t sAH = sb + (uint32_t)(s * STB) + OAH;
        const uint32_t sAL = sb + (uint32_t)(s * STB) + OAL;
        const uint32_t sBH = sb + (uint32_t)(s * STB) + OBH;
        const uint32_t sBL = sb + (uint32_t)(s * STB) + OBL;

        #pragma unroll
        for (int h = 0; h < 2; ++h) {
            const uint32_t bcol = (uint32_t)((h * 16 + b_c8) * 2);
            uint32_t bh[4][4], bl[4][4];
            #pragma unroll
            for (int np = 0; np < 4; ++np) {
                const uint32_t boff = (uint32_t)((b_r + np * 16) * (PSTR * 2)) + bcol;
                ldmx4(bh[np][0], bh[np][1], bh[np][2], bh[np][3], sBH + boff);
                if (HAS_BL)
                    ldmx4(bl[np][0], bl[np][1], bl[np][2], bl[np][3], sBL + boff);
            }
            const uint32_t acol = (uint32_t)((h * 16 + a_c8) * 2);
            #pragma unroll
            for (int mp = 0; mp < 2; ++mp) {
                uint32_t ahr[2][4], alr[2][4];
                #pragma unroll
                for (int m2 = 0; m2 < 2; ++m2) {
                    const uint32_t aoff =
                        (uint32_t)((a_r + (mp * 2 + m2) * 16) * (PSTR * 2)) + acol;
                    ldmx4(ahr[m2][0], ahr[m2][1], ahr[m2][2], ahr[m2][3], sAH + aoff);
                    if (HAS_AL)
                        ldmx4(alr[m2][0], alr[m2][1], alr[m2][2], alr[m2][3], sAL + aoff);
                }
                // term 1: Ah * Bh
                #pragma unroll
                for (int np = 0; np < 4; ++np)
                    #pragma unroll
                    for (int m2 = 0; m2 < 2; ++m2) {
                        mma_f16(acc[mp*2+m2][2*np],   ahr[m2], bh[np][0], bh[np][1]);
                        mma_f16(acc[mp*2+m2][2*np+1], ahr[m2], bh[np][2], bh[np][3]);
                    }
                // term 2: Al * Bh
                if (HAS_AL) {
                    #pragma unroll
                    for (int np = 0; np < 4; ++np)
                        #pragma unroll
                        for (int m2 = 0; m2 < 2; ++m2) {
                            mma_f16(acc[mp*2+m2][2*np],   alr[m2], bh[np][0], bh[np][1]);
                            mma_f16(acc[mp*2+m2][2*np+1], alr[m2], bh[np][2], bh[np][3]);
                        }
                }
                // term 3: Ah * Bl
                if (HAS_BL) {
                    #pragma unroll
                    for (int np = 0; np < 4; ++np)
                        #pragma unroll
                        for (int m2 = 0; m2 < 2; ++m2) {
                            mma_f16(acc[mp*2+m2][2*np],   ahr[m2], bl[np][0], bl[np][1]);
                            mma_f16(acc[mp*2+m2][2*np+1], ahr[m2], bl[np][2], bl[np][3]);
                        }
                }
            }
        }
    }

    // ---------------- epilogue ----------------
    const int er = (lane >> 2);
    const int ec = (lane & 3) * 2;
    #pragma unroll
    for (int mt = 0; mt < 4; ++mt) {
        #pragma unroll
        for (int nt = 0; nt < 8; ++nt) {
            const int col = bn + wn * 64 + nt * 8 + ec;
            #pragma unroll
            for (int half = 0; half < 2; ++half) {
                const int row = bm + wm * 64 + mt * 16 + er + half * 8;
                float x0 = acc[mt][nt][2*half + 0];
                float x1 = acc[mt][nt][2*half + 1];
                if (EPI == 0 || EPI == 3 || EPI == 4) {
                    x0 += aux[col];
                    x1 += aux[col + 1];
                }
                if (EPI == 1) {
                    const float2 m2 = *reinterpret_cast<const float2*>(&aux[(size_t)row * N + col]);
                    x0 = fmaf(x0, ssc(), m2.x);
                    x1 = fmaf(x1, ssc(), m2.y);
                }
                const size_t o = (size_t)row * N + col;
                if (EPI == 3) {
                    __half h0,h1,l0,l1;
                    split_h(x0, h0, l0);
                    split_h(x1, h1, l1);
                    *reinterpret_cast<uint32_t*>(&Ch[o]) = pack2h(h0, h1);
                    *reinterpret_cast<uint32_t*>(&Cl[o]) = pack2h(l0, l1);
                } else if (EPI == 4) {
                    *reinterpret_cast<uint32_t*>(&Ch[o]) =
                        pack2h(__float2half(x0), __float2half(x1));
                } else {
                    *reinterpret_cast<float2*>(&C[o]) = make_float2(x0, x1);
                }
            }
        }
    }
}

// ---------------- fused input split: 3 tensors -> fp16 hi/lo ----------------
__global__ __launch_bounds__(256)
void split_inputs(const float* __restrict__ q, const float* __restrict__ k,
                  const float* __restrict__ v,
                  __half* __restrict__ dh, __half* __restrict__ dl)
{
    const size_t ISZ = (size_t)KROWS * KDIM;
    const float* src = (blockIdx.z == 0) ? q : (blockIdx.z == 1) ? k : v;
    __half* oh = dh + blockIdx.z * ISZ;
    __half* ol = dl + blockIdx.z * ISZ;
    const size_t i = ((size_t)blockIdx.x * 256 + threadIdx.x) * 4;
    float4 x = *reinterpret_cast<const float4*>(src + i);
    __half h0,h1,h2,h3,l0,l1,l2,l3;
    split_h(x.x, h0, l0); split_h(x.y, h1, l1);
    split_h(x.z, h2, l2); split_h(x.w, h3, l3);
    *reinterpret_cast<uint2*>(oh + i) = make_uint2(pack2h(h0,h1), pack2h(h2,h3));
    *reinterpret_cast<uint2*>(ol + i) = make_uint2(pack2h(l0,l1), pack2h(l2,l3));
}

// ---------------- fused weight transpose+split ----------------
__global__ __launch_bounds__(256)
void wtrans(const float* __restrict__ wq, const float* __restrict__ wk,
            const float* __restrict__ wv,
            __half* __restrict__ dh, __half* __restrict__ dl)
{
    __shared__ float tile[32][33];
    const size_t WSZ = (size_t)KDIM * KDIM;
    const float* src = (blockIdx.z == 0) ? wq : (blockIdx.z == 1) ? wk : wv;
    __half* oh = dh + blockIdx.z * WSZ;
    __half* ol = dl + blockIdx.z * WSZ;
    const int bx = blockIdx.x * 32;
    const int by = blockIdx.y * 32;
    const int tx = threadIdx.x & 31;
    const int ty = threadIdx.x >> 5;
    #pragma unroll
    for (int i = 0; i < 32; i += 8)
        tile[ty + i][tx] = src[(size_t)(by + ty + i) * KDIM + bx + tx];
    __syncthreads();
    #pragma unroll
    for (int i = 0; i < 32; i += 8) {
        float x = tile[tx][ty + i];
        __half h, l;
        split_h(x, h, l);
        size_t o = (size_t)(bx + ty + i) * KDIM + by + tx;
        oh[o] = h; ol[o] = l;
    }
}

// ---------------- v transpose: f32 [B][S][D] -> single fp16 [B][D][S] ----------------
__global__ __launch_bounds__(256)
void vtrans(const float* __restrict__ src, __half* __restrict__ dst)
{
    __shared__ float tile[32][33];
    src += (size_t)KSEQ * KDIM * blockIdx.z;
    dst += (size_t)KDIM * KSEQ * blockIdx.z;
    const int bx = blockIdx.x * 32;   // D
    const int by = blockIdx.y * 32;   // S
    const int tx = threadIdx.x & 31;
    const int ty = threadIdx.x >> 5;
    #pragma unroll
    for (int i = 0; i < 32; i += 8)
        tile[ty + i][tx] = src[(size_t)(by + ty + i) * KDIM + bx + tx];
    __syncthreads();
    #pragma unroll
    for (int i = 0; i < 32; i += 8)
        dst[(size_t)(bx + ty + i) * KSEQ + by + tx] = __float2half(tile[tx][ty + i]);
}

// ---------------- row softmax over 2048, emits single fp16 probs ----------------
__global__ __launch_bounds__(256)
void softmax_kernel(const float* __restrict__ S, __half* __restrict__ Ph)
{
    __shared__ float buf[KSEQ];
    __shared__ float red[8];
    const float* p = S + (size_t)blockIdx.x * KSEQ;
    const int t = threadIdx.x, lane = t & 31, wid = t >> 5;

    float mx = -3.4e38f;
    #pragma unroll
    for (int i = t; i < KSEQ; i += 256) { float v = p[i]; buf[i] = v; mx = fmaxf(mx, v); }
    #pragma unroll
    for (int o = 16; o > 0; o >>= 1) mx = fmaxf(mx, __shfl_xor_sync(0xffffffffu, mx, o));
    if (lane == 0) red[wid] = mx;
    __syncthreads();
    mx = fmaxf(fmaxf(fmaxf(red[0], red[1]), fmaxf(red[2], red[3])),
               fmaxf(fmaxf(red[4], red[5]), fmaxf(red[6], red[7])));
    __syncthreads();

    float sum = 0.0f;
    #pragma unroll
    for (int i = t; i < KSEQ; i += 256) { float e = __expf(buf[i] - mx); buf[i] = e; sum += e; }
    #pragma unroll
    for (int o = 16; o > 0; o >>= 1) sum += __shfl_xor_sync(0xffffffffu, sum, o);
    if (lane == 0) red[wid] = sum;
    __syncthreads();
    sum = ((red[0] + red[1]) + (red[2] + red[3])) + ((red[4] + red[5]) + (red[6] + red[7]));
    const float inv = 1.0f / sum;

    __half* ph = Ph + (size_t)blockIdx.x * KSEQ;
    #pragma unroll
    for (int j = t; j < KSEQ / 2; j += 256) {
        float e0 = buf[2*j]     * inv;
        float e1 = buf[2*j + 1] * inv;
        *reinterpret_cast<uint32_t*>(ph + 2*j) =
            pack2h(__float2half(e0), __float2half(e1));
    }
}

// ---------------- launch ----------------
extern "C" void kernel_launch(void* const* d_in, const int* in_sizes, int n_in,
                              void* d_out, int out_size)
{
    (void)in_sizes; (void)n_in; (void)out_size;
    const float* Qin  = (const float*)d_in[0];
    const float* Kin  = (const float*)d_in[1];
    const float* Vin  = (const float*)d_in[2];
    const float* mask = (const float*)d_in[3];
    const float* Wq   = (const float*)d_in[4];
    const float* bq   = (const float*)d_in[5];
    const float* Wk   = (const float*)d_in[6];
    const float* bk   = (const float*)d_in[7];
    const float* Wv   = (const float*)d_in[8];
    const float* bv   = (const float*)d_in[9];
    float* out = (float*)d_out;

    float *v, *s;
    __half *inh, *inl, *wh, *wl, *qh, *kh, *vt, *ph;
    cudaGetSymbolAddress((void**)&inh, g_inh);
    cudaGetSymbolAddress((void**)&inl, g_inl);
    cudaGetSymbolAddress((void**)&wh,  g_wh);
    cudaGetSymbolAddress((void**)&wl,  g_wl);
    cudaGetSymbolAddress((void**)&qh,  g_qh);
    cudaGetSymbolAddress((void**)&kh,  g_kh);
    cudaGetSymbolAddress((void**)&v,   g_v);
    cudaGetSymbolAddress((void**)&vt,  g_vt);
    cudaGetSymbolAddress((void**)&s,   g_s);
    cudaGetSymbolAddress((void**)&ph,  g_ph);

    constexpr int SM2T = 3 * 3 * T_B;   // TERMS=2, 3 stages: 92160
    constexpr int SM1T = 4 * 2 * T_B;   // TERMS=1, 4 stages: 81920
    cudaFuncSetAttribute(gemm_hmma<4,2,3>, cudaFuncAttributeMaxDynamicSharedMemorySize, SM2T);
    cudaFuncSetAttribute(gemm_hmma<0,2,3>, cudaFuncAttributeMaxDynamicSharedMemorySize, SM2T);
    cudaFuncSetAttribute(gemm_hmma<1,1,4>, cudaFuncAttributeMaxDynamicSharedMemorySize, SM1T);
    cudaFuncSetAttribute(gemm_hmma<2,1,4>, cudaFuncAttributeMaxDynamicSharedMemorySize, SM1T);

    const size_t ISZ = (size_t)KROWS * KDIM;
    const size_t WSZ = (size_t)KDIM * KDIM;
    dim3 tb(256);

    // 1-2) preprocessing
    split_inputs<<<dim3((int)(ISZ / 4 / 256), 1, 3), tb>>>(Qin, Kin, Vin, inh, inl);
    wtrans<<<dim3(16, 16, 3), tb>>>(Wq, Wk, Wv, wh, wl);

    // 3) Q projection: TERMS=2 -> single fp16 qh (consumer is 1-term scores)
    dim3 gp(KDIM / TILE_N, KROWS / TILE_M, 1);
    gemm_hmma<4,2,3><<<gp, GT, SM2T>>>(inh + 0*ISZ, inl + 0*ISZ, wh + 0*WSZ, nullptr,
                                       bq, nullptr, qh, nullptr, KDIM, KDIM, 0, 0, 0, 0);
    // 4) K projection: TERMS=2 -> single fp16 kh
    gemm_hmma<4,2,3><<<gp, GT, SM2T>>>(inh + 1*ISZ, inl + 1*ISZ, wh + 1*WSZ, nullptr,
                                       bk, nullptr, kh, nullptr, KDIM, KDIM, 0, 0, 0, 0);
    // 5) V projection: TERMS=2 -> f32 (vtrans rounds to fp16)
    gemm_hmma<0,2,3><<<gp, GT, SM2T>>>(inh + 2*ISZ, inl + 2*ISZ, wh + 2*WSZ, nullptr,
                                       bv, v, nullptr, nullptr, KDIM, KDIM, 0, 0, 0, 0);

    // 6) scores = q_s k_s^T * scale + mask  (TERMS=1; ncu capture target)
    dim3 gs(KSEQ / TILE_N, KSEQ / TILE_M, KBATCH);
    gemm_hmma<1,1,4><<<gs, GT, SM1T>>>(qh, nullptr, kh, nullptr, mask, s, nullptr, nullptr,
                                       KSEQ, KDIM,
                                       (size_t)KSEQ * KDIM, (size_t)KSEQ * KDIM,
                                       (size_t)KSEQ * KSEQ, (size_t)KSEQ * KSEQ);

    // 7) v_s -> v_s^T single fp16
    vtrans<<<dim3(KDIM / 32, KSEQ / 32, KBATCH), tb>>>(v, vt);

    // 8) softmax -> single fp16 probs
    softmax_kernel<<<KROWS, 256>>>(s, ph);

    // 9) out = probs @ v_s : TERMS=1
    dim3 ga(KDIM / TILE_N, KSEQ / TILE_M, KBATCH);
    gemm_hmma<2,1,4><<<ga, GT, SM1T>>>(ph, nullptr, vt, nullptr, nullptr, out, nullptr, nullptr,
                                       KDIM, KSEQ,
                                       (size_t)KSEQ * KSEQ, (size_t)KDIM * KSEQ,
                                       (size_t)KSEQ * KDIM, 0);
}

// round 13
// speedup vs baseline: 2.6685x; 1.1732x over previous
#include <cuda_runtime.h>
#include <cuda_fp16.h>
#include <cstdint>
#include <math.h>

// ---------------- problem constants ----------------
#define KBATCH 8
#define KSEQ   2048
#define KDIM   512
#define KROWS  (KBATCH*KSEQ)   // 16384

// ---------------- scratch (device globals; no allocations) ----------------
__device__ __half  g_in [3][(size_t)KROWS * KDIM];   // Q,K,V inputs fp16
__device__ __half  g_w  [3][(size_t)KDIM * KDIM];    // W^T fp16 [e][d] = [N,K]
__device__ __half  g_qh [(size_t)KROWS * KDIM];      // q_s single fp16 [M,K]
__device__ __half  g_kh [(size_t)KROWS * KDIM];      // k_s single fp16 [N,K]
__device__ float   g_v  [(size_t)KROWS * KDIM];      // v_s fp32
__device__ __half  g_vt [(size_t)KBATCH * KDIM * KSEQ]; // v_s^T fp16 [B][D][S]
__device__ float   g_s  [(size_t)KBATCH * KSEQ * KSEQ]; // scores f32
__device__ __half  g_ph [(size_t)KBATCH * KSEQ * KSEQ]; // probs fp16

// ---------------- helpers ----------------
__device__ __forceinline__ uint32_t smem_u32(const void* p) {
    uint32_t a;
    asm("{ .reg .u64 t; cvta.to.shared.u64 t, %1; cvt.u32.u64 %0, t; }" : "=r"(a) : "l"(p));
    return a;
}
__device__ __forceinline__ void split_h(float x, __half& h, __half& l) {
    h = __float2half(x);
    l = __float2half(x - __half2float(h));
}
__device__ __forceinline__ uint32_t pack2h(__half a, __half b) {
    return (uint32_t)__half_as_ushort(a) | ((uint32_t)__half_as_ushort(b) << 16);
}
__device__ __forceinline__ void ldmx4(uint32_t& r0, uint32_t& r1, uint32_t& r2, uint32_t& r3,
                                      uint32_t addr) {
    asm volatile("ldmatrix.sync.aligned.m8n8.x4.shared.b16 {%0,%1,%2,%3}, [%4];"
                 : "=r"(r0), "=r"(r1), "=r"(r2), "=r"(r3) : "r"(addr));
}
__device__ __forceinline__ void mma_f16(float* c, const uint32_t* a, uint32_t b0, uint32_t b1) {
    asm volatile("mma.sync.aligned.m16n8k16.row.col.f32.f16.f16.f32 "
                 "{%0,%1,%2,%3}, {%4,%5,%6,%7}, {%8,%9}, {%0,%1,%2,%3};"
                 : "+f"(c[0]), "+f"(c[1]), "+f"(c[2]), "+f"(c[3])
                 : "r"(a[0]), "r"(a[1]), "r"(a[2]), "r"(a[3]), "r"(b0), "r"(b1));
}
#define CP16(dst, src) \
    asm volatile("cp.async.cg.shared.global [%0], [%1], 16;" :: "r"(dst), "l"(src))
#define CP_COMMIT() asm volatile("cp.async.commit_group;" ::: "memory")

__device__ __forceinline__ float ssc() { return 0.044194173824159216f; } // 1/sqrt(512)

// ---------------- HMMA GEMM: 128 threads, CTA 128x128, warp tile 64x64 ----------------
// 2 CTAs per SM.  TERMS=2: AhBh+AlBh.  TERMS=1: AhBh only.
// EPI 0: +bias -> f32    EPI 1: *scale + mask -> f32    EPI 2: plain -> f32
// EPI 4: +bias -> single fp16 (Ch)
#define TILE_M 128
#define TILE_N 128
#define TILE_K 32
#define GT 128
#define PSTR 40                     // padded smem row stride (halves) -> 80 B/row
#define T_B (128 * PSTR * 2)        // 10240 bytes per 128x32 fp16 tile

template<int EPI, int TERMS, int NST>
__global__ __launch_bounds__(GT, 2)
void gemm_hmma(const __half* __restrict__ Ah,
               const __half* __restrict__ Al,
               const __half* __restrict__ Bh,
               const float* __restrict__ aux,
               float* __restrict__ C,
               __half* __restrict__ Ch,
               int N, int K,
               size_t sA, size_t sB, size_t sC, size_t sAux)
{
    constexpr bool HAS_AL = (TERMS >= 2);
    constexpr int  NTILE  = (HAS_AL ? 3 : 2);      // Ah[, Al], Bh
    constexpr int  STB    = NTILE * T_B;

    extern __shared__ char sm[];
    const uint32_t sb = smem_u32(sm);

    Ah  += sA   * (size_t)blockIdx.z;
    if (HAS_AL) Al += sA * (size_t)blockIdx.z;
    Bh  += sB   * (size_t)blockIdx.z;
    C   += sC   * (size_t)blockIdx.z;
    Ch  += sC   * (size_t)blockIdx.z;
    aux += sAux * (size_t)blockIdx.z;

    const int t    = threadIdx.x;
    const int lane = t & 31;
    const int w    = t >> 5;        // 0..3
    const int wm   = w & 1;         // warp row (2) -> M offset 64*wm
    const int wn   = w >> 1;        // warp col (2) -> N offset 64*wn
    const int bm   = blockIdx.y * TILE_M;
    const int bn   = blockIdx.x * TILE_N;

    const int cr = t >> 2;          // 0..31
    const int cc = t & 3;           // 16B chunk within 64B row

    const int a_r  = wm * 64 + (lane & 15);
    const int a_c8 = (lane >> 4) * 8;
    const int b_r  = wn * 64 + (lane & 7) + ((lane >> 4) & 1) * 8;
    const int b_c8 = ((lane >> 3) & 1) * 8;

    float acc[4][8][4];
    #pragma unroll
    for (int i = 0; i < 4; ++i)
        #pragma unroll
        for (int j = 0; j < 8; ++j)
            #pragma unroll
            for (int e = 0; e < 4; ++e) acc[i][j][e] = 0.0f;

    const int nch = K / TILE_K;

    // smem tile offsets within a stage
    constexpr int OAH = 0;
    constexpr int OAL = T_B;                         // valid if HAS_AL
    constexpr int OBH = (HAS_AL ? 2 : 1) * T_B;

    auto issue = [&](int j, int s) {
        const size_t kco = (size_t)j * TILE_K + cc * 8;
        const uint32_t base = sb + (uint32_t)(s * STB);
        #pragma unroll
        for (int p = 0; p < 4; ++p) {
            const int row = cr + p * 32;
            const uint32_t doff = (uint32_t)(row * (PSTR * 2) + cc * 16);
            const size_t ga = (size_t)(bm + row) * K + kco;
            const size_t gb = (size_t)(bn + row) * K + kco;
            CP16(base + OAH + doff, Ah + ga);
            if (HAS_AL) CP16(base + OAL + doff, Al + ga);
            CP16(base + OBH + doff, Bh + gb);
        }
    };

    // prologue: stages 0..NST-2 in flight
    #pragma unroll
    for (int j = 0; j < NST - 1; ++j) {
        if (j < nch) issue(j, j);
        CP_COMMIT();
    }

    // canonical multistage: ONE sync per chunk.
    for (int i = 0; i < nch; ++i) {
        asm volatile("cp.async.wait_group %0;" :: "n"(NST - 2 >= 0 ? NST - 2 : 0) : "memory");
        __syncthreads();

        const int jn = i + NST - 1;
        if (jn < nch) { issue(jn, jn % NST); }
        CP_COMMIT();

        const int s = i % NST;
        const uint32_t sAH = sb + (uint32_t)(s * STB) + OAH;
        const uint32_t sAL = sb + (uint32_t)(s * STB) + OAL;
        const uint32_t sBH = sb + (uint32_t)(s * STB) + OBH;

        #pragma unroll
        for (int h = 0; h < 2; ++h) {
            const uint32_t bcol = (uint32_t)((h * 16 + b_c8) * 2);
            uint32_t bh[4][4];
            #pragma unroll
            for (int np = 0; np < 4; ++np) {
                const uint32_t boff = (uint32_t)((b_r + np * 16) * (PSTR * 2)) + bcol;
                ldmx4(bh[np][0], bh[np][1], bh[np][2], bh[np][3], sBH + boff);
            }
            const uint32_t acol = (uint32_t)((h * 16 + a_c8) * 2);
            #pragma unroll
            for (int mp = 0; mp < 2; ++mp) {
                uint32_t ahr[2][4], alr[2][4];
                #pragma unroll
                for (int m2 = 0; m2 < 2; ++m2) {
                    const uint32_t aoff =
                        (uint32_t)((a_r + (mp * 2 + m2) * 16) * (PSTR * 2)) + acol;
                    ldmx4(ahr[m2][0], ahr[m2][1], ahr[m2][2], ahr[m2][3], sAH + aoff);
                    if (HAS_AL)
                        ldmx4(alr[m2][0], alr[m2][1], alr[m2][2], alr[m2][3], sAL + aoff);
                }
                // term 1: Ah * Bh
                #pragma unroll
                for (int np = 0; np < 4; ++np)
                    #pragma unroll
                    for (int m2 = 0; m2 < 2; ++m2) {
                        mma_f16(acc[mp*2+m2][2*np],   ahr[m2], bh[np][0], bh[np][1]);
                        mma_f16(acc[mp*2+m2][2*np+1], ahr[m2], bh[np][2], bh[np][3]);
                    }
                // term 2: Al * Bh
                if (HAS_AL) {
                    #pragma unroll
                    for (int np = 0; np < 4; ++np)
                        #pragma unroll
                        for (int m2 = 0; m2 < 2; ++m2) {
                            mma_f16(acc[mp*2+m2][2*np],   alr[m2], bh[np][0], bh[np][1]);
                            mma_f16(acc[mp*2+m2][2*np+1], alr[m2], bh[np][2], bh[np][3]);
                        }
                }
            }
        }
    }

    // ---------------- epilogue ----------------
    const int er = (lane >> 2);
    const int ec = (lane & 3) * 2;
    #pragma unroll
    for (int mt = 0; mt < 4; ++mt) {
        #pragma unroll
        for (int nt = 0; nt < 8; ++nt) {
            const int col = bn + wn * 64 + nt * 8 + ec;
            #pragma unroll
            for (int half = 0; half < 2; ++half) {
                const int row = bm + wm * 64 + mt * 16 + er + half * 8;
                float x0 = acc[mt][nt][2*half + 0];
                float x1 = acc[mt][nt][2*half + 1];
                if (EPI == 0 || EPI == 4) {
                    x0 += aux[col];
                    x1 += aux[col + 1];
                }
                if (EPI == 1) {
                    const float2 m2 = *reinterpret_cast<const float2*>(&aux[(size_t)row * N + col]);
                    x0 = fmaf(x0, ssc(), m2.x);
                    x1 = fmaf(x1, ssc(), m2.y);
                }
                const size_t o = (size_t)row * N + col;
                if (EPI == 4) {
                    *reinterpret_cast<uint32_t*>(&Ch[o]) =
                        pack2h(__float2half(x0), __float2half(x1));
                } else {
                    *reinterpret_cast<float2*>(&C[o]) = make_float2(x0, x1);
                }
            }
        }
    }
}

// ---------------- fused input convert: 3 tensors -> single fp16 ----------------
__global__ __launch_bounds__(256)
void convert_inputs(const float* __restrict__ q, const float* __restrict__ k,
                    const float* __restrict__ v, __half* __restrict__ dh)
{
    const size_t ISZ = (size_t)KROWS * KDIM;
    const float* src = (blockIdx.z == 0) ? q : (blockIdx.z == 1) ? k : v;
    __half* oh = dh + blockIdx.z * ISZ;
    const size_t i = ((size_t)blockIdx.x * 256 + threadIdx.x) * 4;
    float4 x = *reinterpret_cast<const float4*>(src + i);
    *reinterpret_cast<uint2*>(oh + i) =
        make_uint2(pack2h(__float2half(x.x), __float2half(x.y)),
                   pack2h(__float2half(x.z), __float2half(x.w)));
}

// ---------------- fused weight transpose -> single fp16 [e][d] ----------------
__global__ __launch_bounds__(256)
void wtrans(const float* __restrict__ wq, const float* __restrict__ wk,
            const float* __restrict__ wv, __half* __restrict__ dh)
{
    __shared__ float tile[32][33];
    const size_t WSZ = (size_t)KDIM * KDIM;
    const float* src = (blockIdx.z == 0) ? wq : (blockIdx.z == 1) ? wk : wv;
    __half* oh = dh + blockIdx.z * WSZ;
    const int bx = blockIdx.x * 32;
    const int by = blockIdx.y * 32;
    const int tx = threadIdx.x & 31;
    const int ty = threadIdx.x >> 5;
    #pragma unroll
    for (int i = 0; i < 32; i += 8)
        tile[ty + i][tx] = src[(size_t)(by + ty + i) * KDIM + bx + tx];
    __syncthreads();
    #pragma unroll
    for (int i = 0; i < 32; i += 8)
        oh[(size_t)(bx + ty + i) * KDIM + by + tx] = __float2half(tile[tx][ty + i]);
}

// ---------------- v transpose: f32 [B][S][D] -> single fp16 [B][D][S] ----------------
__global__ __launch_bounds__(256)
void vtrans(const float* __restrict__ src, __half* __restrict__ dst)
{
    __shared__ float tile[32][33];
    src += (size_t)KSEQ * KDIM * blockIdx.z;
    dst += (size_t)KDIM * KSEQ * blockIdx.z;
    const int bx = blockIdx.x * 32;   // D
    const int by = blockIdx.y * 32;   // S
    const int tx = threadIdx.x & 31;
    const int ty = threadIdx.x >> 5;
    #pragma unroll
    for (int i = 0; i < 32; i += 8)
        tile[ty + i][tx] = src[(size_t)(by + ty + i) * KDIM + bx + tx];
    __syncthreads();
    #pragma unroll
    for (int i = 0; i < 32; i += 8)
        dst[(size_t)(bx + ty + i) * KSEQ + by + tx] = __float2half(tile[tx][ty + i]);
}

// ---------------- row softmax over 2048, emits single fp16 probs ----------------
__global__ __launch_bounds__(256)
void softmax_kernel(const float* __restrict__ S, __half* __restrict__ Ph)
{
    __shared__ float buf[KSEQ];
    __shared__ float red[8];
    const float* p = S + (size_t)blockIdx.x * KSEQ;
    const int t = threadIdx.x, lane = t & 31, wid = t >> 5;

    float mx = -3.4e38f;
    #pragma unroll
    for (int i = t; i < KSEQ; i += 256) { float v = p[i]; buf[i] = v; mx = fmaxf(mx, v); }
    #pragma unroll
    for (int o = 16; o > 0; o >>= 1) mx = fmaxf(mx, __shfl_xor_sync(0xffffffffu, mx, o));
    if (lane == 0) red[wid] = mx;
    __syncthreads();
    mx = fmaxf(fmaxf(fmaxf(red[0], red[1]), fmaxf(red[2], red[3])),
               fmaxf(fmaxf(red[4], red[5]), fmaxf(red[6], red[7])));
    __syncthreads();

    float sum = 0.0f;
    #pragma unroll
    for (int i = t; i < KSEQ; i += 256) { float e = __expf(buf[i] - mx); buf[i] = e; sum += e; }
    #pragma unroll
    for (int o = 16; o > 0; o >>= 1) sum += __shfl_xor_sync(0xffffffffu, sum, o);
    if (lane == 0) red[wid] = sum;
    __syncthreads();
    sum = ((red[0] + red[1]) + (red[2] + red[3])) + ((red[4] + red[5]) + (red[6] + red[7]));
    const float inv = 1.0f / sum;

    __half* ph = Ph + (size_t)blockIdx.x * KSEQ;
    #pragma unroll
    for (int j = t; j < KSEQ / 2; j += 256) {
        float e0 = buf[2*j]     * inv;
        float e1 = buf[2*j + 1] * inv;
        *reinterpret_cast<uint32_t*>(ph + 2*j) =
            pack2h(__float2half(e0), __float2half(e1));
    }
}

// ---------------- launch ----------------
extern "C" void kernel_launch(void* const* d_in, const int* in_sizes, int n_in,
                              void* d_out, int out_size)
{
    (void)in_sizes; (void)n_in; (void)out_size;
    const float* Qin  = (const float*)d_in[0];
    const float* Kin  = (const float*)d_in[1];
    const float* Vin  = (const float*)d_in[2];
    const float* mask = (const float*)d_in[3];
    const float* Wq   = (const float*)d_in[4];
    const float* bq   = (const float*)d_in[5];
    const float* Wk   = (const float*)d_in[6];
    const float* bk   = (const float*)d_in[7];
    const float* Wv   = (const float*)d_in[8];
    const float* bv   = (const float*)d_in[9];
    float* out = (float*)d_out;

    float *v, *s;
    __half *in16, *w16, *qh, *kh, *vt, *ph;
    cudaGetSymbolAddress((void**)&in16, g_in);
    cudaGetSymbolAddress((void**)&w16,  g_w);
    cudaGetSymbolAddress((void**)&qh,   g_qh);
    cudaGetSymbolAddress((void**)&kh,   g_kh);
    cudaGetSymbolAddress((void**)&v,    g_v);
    cudaGetSymbolAddress((void**)&vt,   g_vt);
    cudaGetSymbolAddress((void**)&s,    g_s);
    cudaGetSymbolAddress((void**)&ph,   g_ph);

    constexpr int SM1T = 4 * 2 * T_B;   // TERMS=1, 4 stages: 81920
    cudaFuncSetAttribute(gemm_hmma<4,1,4>, cudaFuncAttributeMaxDynamicSharedMemorySize, SM1T);
    cudaFuncSetAttribute(gemm_hmma<0,1,4>, cudaFuncAttributeMaxDynamicSharedMemorySize, SM1T);
    cudaFuncSetAttribute(gemm_hmma<1,1,4>, cudaFuncAttributeMaxDynamicSharedMemorySize, SM1T);
    cudaFuncSetAttribute(gemm_hmma<2,1,4>, cudaFuncAttributeMaxDynamicSharedMemorySize, SM1T);

    const size_t ISZ = (size_t)KROWS * KDIM;
    const size_t WSZ = (size_t)KDIM * KDIM;
    dim3 tb(256);

    // 1-2) preprocessing: inputs + weights -> single fp16
    convert_inputs<<<dim3((int)(ISZ / 4 / 256), 1, 3), tb>>>(Qin, Kin, Vin, in16);
    wtrans<<<dim3(16, 16, 3), tb>>>(Wq, Wk, Wv, w16);

    // 3) Q projection: TERMS=1 -> single fp16 qh
    dim3 gp(KDIM / TILE_N, KROWS / TILE_M, 1);
    gemm_hmma<4,1,4><<<gp, GT, SM1T>>>(in16 + 0*ISZ, nullptr, w16 + 0*WSZ,
                                       bq, nullptr, qh, KDIM, KDIM, 0, 0, 0, 0);
    // 4) K projection: TERMS=1 -> single fp16 kh  (ncu capture slot 4)
    gemm_hmma<4,1,4><<<gp, GT, SM1T>>>(in16 + 1*ISZ, nullptr, w16 + 1*WSZ,
                                       bk, nullptr, kh, KDIM, KDIM, 0, 0, 0, 0);
    // 5) V projection: TERMS=1 -> f32 (vtrans rounds to fp16)
    gemm_hmma<0,1,4><<<gp, GT, SM1T>>>(in16 + 2*ISZ, nullptr, w16 + 2*WSZ,
                                       bv, v, nullptr, KDIM, KDIM, 0, 0, 0, 0);

    // 6) scores = q_s k_s^T * scale + mask  (TERMS=1)
    dim3 gs(KSEQ / TILE_N, KSEQ / TILE_M, KBATCH);
    gemm_hmma<1,1,4><<<gs, GT, SM1T>>>(qh, nullptr, kh, mask, s, nullptr,
                                       KSEQ, KDIM,
                                       (size_t)KSEQ * KDIM, (size_t)KSEQ * KDIM,
                                       (size_t)KSEQ * KSEQ, (size_t)KSEQ * KSEQ);

    // 7) v_s -> v_s^T single fp16
    vtrans<<<dim3(KDIM / 32, KSEQ / 32, KBATCH), tb>>>(v, vt);

    // 8) softmax -> single fp16 probs
    softmax_kernel<<<KROWS, 256>>>(s, ph);

    // 9) out = probs @ v_s : TERMS=1
    dim3 ga(KDIM / TILE_N, KSEQ / TILE_M, KBATCH);
    gemm_hmma<2,1,4><<<ga, GT, SM1T>>>(ph, nullptr, vt, nullptr, out, nullptr,
                                       KDIM, KSEQ,
                                       (size_t)KSEQ * KSEQ, (size_t)KDIM * KSEQ,
                                       (size_t)KSEQ * KDIM, 0);
}